// round 7
// baseline (speedup 1.0000x reference)
#include <cuda_runtime.h>
#include <math.h>
#include <stdint.h>

#define Bb   16
#define Ss   512
#define Hh   768
#define NHh  12
#define DHh  64
#define Ll   2
#define FFf  3072
#define Tt   (Bb*Ss)          // 8192 tokens
#define H3   (3*Hh)           // 2304

// ---------------- scratch (no allocations allowed) ----------------
__device__ float g_x[Tt*Hh];                    // hidden state      25 MB
__device__ float g_tmp[Tt*FFf];                 // qkv / wo / ff1   100 MB
__device__ float g_ctx[Tt*Hh];                  // attn ctx / ff2    25 MB
// RNA-pre-rounded weights, per layer: qkv | wo | ff1 | ff2 (same [K,N] layout)
#define WT_LAYER 7077888
#define WT_QKV   0
#define WT_WO    1769472
#define WT_FF1   2359296
#define WT_FF2   4718592
__device__ float g_wt[2*WT_LAYER];              // 56.6 MB
__device__ int   g_seg_first[Bb*Ss];
__device__ int   g_seg_cnt[Bb*Ss];
__device__ int   g_nseg[Bb];

// ---------------- helpers ----------------
__device__ __forceinline__ float block_reduce_sum_256(float v, float* red) {
    int t = threadIdx.x;
    red[t] = v; __syncthreads();
#pragma unroll
    for (int o = 128; o > 0; o >>= 1) {
        if (t < o) red[t] += red[t + o];
        __syncthreads();
    }
    float r = red[0];
    __syncthreads();
    return r;
}

__device__ __forceinline__ uint32_t f2tf32(float x) {
    uint32_t r;
    asm("cvt.rna.tf32.f32 %0, %1;" : "=r"(r) : "f"(x));
    return r;
}

__device__ __forceinline__ void mma_tf32(float* c, const uint32_t* a, const uint32_t* b) {
    asm volatile(
        "mma.sync.aligned.m16n8k8.row.col.f32.tf32.tf32.f32 "
        "{%0,%1,%2,%3}, {%4,%5,%6,%7}, {%8,%9}, {%0,%1,%2,%3};"
        : "+f"(c[0]), "+f"(c[1]), "+f"(c[2]), "+f"(c[3])
        : "r"(a[0]), "r"(a[1]), "r"(a[2]), "r"(a[3]), "r"(b[0]), "r"(b[1]));
}

__device__ __forceinline__ void cp_async16(void* smem_ptr, const void* gptr) {
    uint32_t s = (uint32_t)__cvta_generic_to_shared(smem_ptr);
    asm volatile("cp.async.cg.shared.global [%0], [%1], 16;" :: "r"(s), "l"(gptr));
}

// raw fp32 bits + half tf32 ulp; HW mma truncates low 13 bits => effective RNA
#define RND_TF32(x) ((x) + 0x1000u)

// ---------------- weight pre-round (RNA to tf32 grid, same layout) ----------
__global__ void round_tf32_kernel(const float* __restrict__ src,
                                  float* __restrict__ dst, int n4) {
    int i = blockIdx.x * 256 + threadIdx.x;
    if (i < n4) {
        uint4 v = reinterpret_cast<const uint4*>(src)[i];
        v.x += 0x1000u; v.y += 0x1000u; v.z += 0x1000u; v.w += 0x1000u;
        reinterpret_cast<uint4*>(dst)[i] = v;
    }
}

// ---------------- embedding + LN ----------------
__global__ void embed_ln_kernel(const int* __restrict__ tok,
                                const float* __restrict__ emb,
                                const float* __restrict__ pos,
                                const float* __restrict__ g,
                                const float* __restrict__ bt) {
    int row = blockIdx.x;
    int s   = row & (Ss - 1);
    int id  = tok[row * 2 + 1];
    __shared__ float y[Hh];
    __shared__ float red[256];
    int t = threadIdx.x;
    float part = 0.f;
    for (int j = t; j < Hh; j += 256) {
        float v = emb[(size_t)id * Hh + j] + pos[s * Hh + j];
        y[j] = v; part += v;
    }
    float mean = block_reduce_sum_256(part, red) * (1.f / Hh);
    part = 0.f;
    for (int j = t; j < Hh; j += 256) { float d = y[j] - mean; part += d * d; }
    float var = block_reduce_sum_256(part, red) * (1.f / Hh);
    float inv = rsqrtf(var + 1e-12f);
    for (int j = t; j < Hh; j += 256)
        g_x[(size_t)row * Hh + j] = (y[j] - mean) * inv * g[j] + bt[j];
}

// ---------------- residual add + LN ----------------
__global__ void add_ln_kernel(const float* __restrict__ x,
                              const float* __restrict__ tadd,
                              const float* __restrict__ g,
                              const float* __restrict__ bt,
                              float* __restrict__ out) {
    int row = blockIdx.x;
    size_t base = (size_t)row * Hh;
    __shared__ float y[Hh];
    __shared__ float red[256];
    int t = threadIdx.x;
    float part = 0.f;
    for (int j = t; j < Hh; j += 256) {
        float v = x[base + j] + tadd[base + j];
        y[j] = v; part += v;
    }
    float mean = block_reduce_sum_256(part, red) * (1.f / Hh);
    part = 0.f;
    for (int j = t; j < Hh; j += 256) { float d = y[j] - mean; part += d * d; }
    float var = block_reduce_sum_256(part, red) * (1.f / Hh);
    float inv = rsqrtf(var + 1e-12f);
    for (int j = t; j < Hh; j += 256)
        out[base + j] = (y[j] - mean) * inv * g[j] + bt[j];
}

// ---------------- TF32 tensor-core GEMM with 3-stage cp.async pipeline --------
// C = A[M,K] @ W[K,N] + bias, optional GELU. BM=128, BN template (128 or 96).
// 8 warps in 2x4 grid: warp tile 64 x (BN/4); NI = BN/32 n-subtiles of 8.
// B (W) is pre-rounded to the tf32 grid; A is rounded at fragment-read time.
#define AS_STRIDE 36
#define AS_SZ     (128 * AS_STRIDE)          // 4608 u32

template<int BN>
__global__ __launch_bounds__(256) void gemm_tf32_kernel(const float* __restrict__ A,
                                                        const float* __restrict__ W,
                                                        const float* __restrict__ bias,
                                                        float* __restrict__ C,
                                                        int M, int N, int K, int act) {
    constexpr int NI      = BN / 32;         // 4 (BN=128) or 3 (BN=96)
    constexpr int BS_STR  = BN + 4;          // 132 or 100 (both == 4 mod 32)
    constexpr int BS_SZ   = 32 * BS_STR;
    constexpr int STAGE   = AS_SZ + BS_SZ;
    constexpr int BCH     = BN / 4;          // float4 chunks per B row

    extern __shared__ uint32_t sm[];
    int tid  = threadIdx.x;
    int lane = tid & 31;
    int warp = tid >> 5;
    int g    = lane >> 2, tig = lane & 3;
    int wm   = warp >> 2, wn = warp & 3;
    int mBase = blockIdx.y * 128, nBase = blockIdx.x * BN;

    float acc[4][NI][4];
#pragma unroll
    for (int i = 0; i < 4; i++)
#pragma unroll
        for (int j = 0; j < NI; j++)
#pragma unroll
            for (int r = 0; r < 4; r++) acc[i][j][r] = 0.f;

    int nK = K >> 5;

    // stage loader
    auto load_stage = [&](int stage, int k0) {
        uint32_t* st = sm + stage * STAGE;
#pragma unroll
        for (int i = 0; i < 4; i++) {
            int idx = tid + i * 256;
            int r = idx >> 3, c4 = (idx & 7) << 2;
            cp_async16(&st[r * AS_STRIDE + c4],
                       &A[(size_t)(mBase + r) * K + k0 + c4]);
        }
        uint32_t* bs = st + AS_SZ;
#pragma unroll
        for (int i = 0; i < NI; i++) {
            int idx = tid + i * 256;
            int r = idx / BCH, c4 = (idx % BCH) << 2;
            cp_async16(&bs[r * BS_STR + c4],
                       &W[(size_t)(k0 + r) * N + nBase + c4]);
        }
        asm volatile("cp.async.commit_group;" ::: "memory");
    };

    load_stage(0, 0);
    load_stage(1, 32);

    int s_cur = 0, s_next = 2;
    for (int i = 0; i < nK; i++) {
        if (i + 2 < nK) {
            load_stage(s_next, (i + 2) << 5);
            asm volatile("cp.async.wait_group 2;" ::: "memory");
        } else if (i + 1 < nK) {
            asm volatile("cp.async.wait_group 1;" ::: "memory");
        } else {
            asm volatile("cp.async.wait_group 0;" ::: "memory");
        }
        __syncthreads();

        const uint32_t* As = sm + s_cur * STAGE;
        const uint32_t* Bs = As + AS_SZ;
#pragma unroll
        for (int kk = 0; kk < 32; kk += 8) {
            uint32_t a[4][4], b[NI][2];
#pragma unroll
            for (int mi = 0; mi < 4; mi++) {
                int rm = wm * 64 + mi * 16 + g;
                a[mi][0] = RND_TF32(As[rm * AS_STRIDE + kk + tig]);
                a[mi][1] = RND_TF32(As[(rm + 8) * AS_STRIDE + kk + tig]);
                a[mi][2] = RND_TF32(As[rm * AS_STRIDE + kk + tig + 4]);
                a[mi][3] = RND_TF32(As[(rm + 8) * AS_STRIDE + kk + tig + 4]);
            }
#pragma unroll
            for (int ni = 0; ni < NI; ni++) {
                int cn = wn * BCH + ni * 8 + g;
                b[ni][0] = Bs[(kk + tig) * BS_STR + cn];
                b[ni][1] = Bs[(kk + tig + 4) * BS_STR + cn];
            }
#pragma unroll
            for (int mi = 0; mi < 4; mi++)
#pragma unroll
                for (int ni = 0; ni < NI; ni++)
                    mma_tf32(acc[mi][ni], a[mi], b[ni]);
        }
        __syncthreads();
        s_cur = (s_cur == 2) ? 0 : s_cur + 1;
        s_next = (s_next == 2) ? 0 : s_next + 1;
    }

    // epilogue: bias + optional exact GELU, float2 stores
#pragma unroll
    for (int mi = 0; mi < 4; mi++) {
        int rm0 = mBase + wm * 64 + mi * 16 + g;
#pragma unroll
        for (int ni = 0; ni < NI; ni++) {
            int cn = nBase + wn * BCH + ni * 8 + 2 * tig;
            float b0 = bias[cn], b1 = bias[cn + 1];
            float v0 = acc[mi][ni][0] + b0;
            float v1 = acc[mi][ni][1] + b1;
            float v2 = acc[mi][ni][2] + b0;
            float v3 = acc[mi][ni][3] + b1;
            if (act) {
                v0 = 0.5f * v0 * (1.0f + erff(v0 * 0.70710678118654752f));
                v1 = 0.5f * v1 * (1.0f + erff(v1 * 0.70710678118654752f));
                v2 = 0.5f * v2 * (1.0f + erff(v2 * 0.70710678118654752f));
                v3 = 0.5f * v3 * (1.0f + erff(v3 * 0.70710678118654752f));
            }
            *reinterpret_cast<float2*>(&C[(size_t)rm0 * N + cn])       = make_float2(v0, v1);
            *reinterpret_cast<float2*>(&C[(size_t)(rm0 + 8) * N + cn]) = make_float2(v2, v3);
        }
    }
}

#define GEMM_SMEM_128 (3 * (AS_SZ + 32 * 132) * 4)
#define GEMM_SMEM_96  (3 * (AS_SZ + 32 * 100) * 4)

// ---------------- fused attention: per (q-tile 64, b*h) block -----------------
#define SSS   516
#define KST   68
#define VST   72
#define ATTN_SMEM_BYTES ((64*SSS + 64*VST) * 4)

__global__ __launch_bounds__(256) void fused_attn_kernel(const float* __restrict__ qkv) {
    extern __shared__ float smem[];
    float*    Ssm = smem;                                        // 64 x 516
    uint32_t* KV  = reinterpret_cast<uint32_t*>(smem + 64 * SSS);// 64 x 72

    int bh = blockIdx.y; int b = bh / NHh, h = bh - b * NHh;
    int qt = blockIdx.x * 64;
    int tid = threadIdx.x, lane = tid & 31, warp = tid >> 5;
    int g = lane >> 2, tig = lane & 3;
    int wq = warp >> 1, wh = warp & 1;

#pragma unroll
    for (int i = 0; i < 4; i++) {
        int idx = tid + i * 256;
        int r = idx >> 4, c4 = (idx & 15) << 2;
        float4 v = *reinterpret_cast<const float4*>(
            &qkv[(size_t)(b * Ss + qt + r) * H3 + h * DHh + c4]);
        uint32_t* p = &KV[r * KST + c4];
        p[0] = f2tf32(v.x); p[1] = f2tf32(v.y);
        p[2] = f2tf32(v.z); p[3] = f2tf32(v.w);
    }
    __syncthreads();

    uint32_t qa[8][4];
#pragma unroll
    for (int ks = 0; ks < 8; ks++) {
        int rm = wq * 16 + g;
        qa[ks][0] = KV[rm * KST + ks * 8 + tig];
        qa[ks][1] = KV[(rm + 8) * KST + ks * 8 + tig];
        qa[ks][2] = KV[rm * KST + ks * 8 + tig + 4];
        qa[ks][3] = KV[(rm + 8) * KST + ks * 8 + tig + 4];
    }
    __syncthreads();

    for (int kt = 0; kt < 8; kt++) {
#pragma unroll
        for (int i = 0; i < 4; i++) {
            int idx = tid + i * 256;
            int r = idx >> 4, c4 = (idx & 15) << 2;
            float4 v = *reinterpret_cast<const float4*>(
                &qkv[(size_t)(b * Ss + kt * 64 + r) * H3 + Hh + h * DHh + c4]);
            uint32_t* p = &KV[r * KST + c4];
            p[0] = f2tf32(v.x); p[1] = f2tf32(v.y);
            p[2] = f2tf32(v.z); p[3] = f2tf32(v.w);
        }
        __syncthreads();
        float acc[4][4];
#pragma unroll
        for (int nt = 0; nt < 4; nt++)
#pragma unroll
            for (int r = 0; r < 4; r++) acc[nt][r] = 0.f;
#pragma unroll
        for (int ks = 0; ks < 8; ks++) {
            uint32_t bf[4][2];
#pragma unroll
            for (int nt = 0; nt < 4; nt++) {
                int n = wh * 32 + nt * 8 + g;
                bf[nt][0] = KV[n * KST + ks * 8 + tig];
                bf[nt][1] = KV[n * KST + ks * 8 + tig + 4];
            }
#pragma unroll
            for (int nt = 0; nt < 4; nt++)
                mma_tf32(acc[nt], qa[ks], bf[nt]);
        }
#pragma unroll
        for (int nt = 0; nt < 4; nt++) {
            int col = kt * 64 + wh * 32 + nt * 8 + 2 * tig;
            int row = wq * 16 + g;
            Ssm[row * SSS + col]           = acc[nt][0] * 0.125f;
            Ssm[row * SSS + col + 1]       = acc[nt][1] * 0.125f;
            Ssm[(row + 8) * SSS + col]     = acc[nt][2] * 0.125f;
            Ssm[(row + 8) * SSS + col + 1] = acc[nt][3] * 0.125f;
        }
        __syncthreads();
    }

    for (int r = warp * 8; r < warp * 8 + 8; r++) {
        float* row = &Ssm[r * SSS];
        float v[16];
        float m = -1e30f;
#pragma unroll
        for (int i = 0; i < 16; i++) { v[i] = row[lane + 32 * i]; m = fmaxf(m, v[i]); }
#pragma unroll
        for (int o = 16; o > 0; o >>= 1) m = fmaxf(m, __shfl_xor_sync(0xffffffffu, m, o));
        float s = 0.f;
#pragma unroll
        for (int i = 0; i < 16; i++) { v[i] = __expf(v[i] - m); s += v[i]; }
#pragma unroll
        for (int o = 16; o > 0; o >>= 1) s += __shfl_xor_sync(0xffffffffu, s, o);
        float inv = 1.0f / s;
#pragma unroll
        for (int i = 0; i < 16; i++) row[lane + 32 * i] = v[i] * inv;
    }
    __syncthreads();

    float oacc[4][4];
#pragma unroll
    for (int nt = 0; nt < 4; nt++)
#pragma unroll
        for (int r = 0; r < 4; r++) oacc[nt][r] = 0.f;

    for (int kt = 0; kt < 8; kt++) {
#pragma unroll
        for (int i = 0; i < 4; i++) {
            int idx = tid + i * 256;
            int r = idx >> 4, c4 = (idx & 15) << 2;
            float4 v = *reinterpret_cast<const float4*>(
                &qkv[(size_t)(b * Ss + kt * 64 + r) * H3 + 2 * Hh + h * DHh + c4]);
            uint32_t* p = &KV[r * VST + c4];
            p[0] = f2tf32(v.x); p[1] = f2tf32(v.y);
            p[2] = f2tf32(v.z); p[3] = f2tf32(v.w);
        }
        __syncthreads();
#pragma unroll
        for (int ks = 0; ks < 8; ks++) {
            uint32_t pa[4];
            int rm = wq * 16 + g;
            int kc = kt * 64 + ks * 8;
            pa[0] = f2tf32(Ssm[rm * SSS + kc + tig]);
            pa[1] = f2tf32(Ssm[(rm + 8) * SSS + kc + tig]);
            pa[2] = f2tf32(Ssm[rm * SSS + kc + tig + 4]);
            pa[3] = f2tf32(Ssm[(rm + 8) * SSS + kc + tig + 4]);
#pragma unroll
            for (int nt = 0; nt < 4; nt++) {
                uint32_t bf[2];
                int n = wh * 32 + nt * 8 + g;
                bf[0] = KV[(ks * 8 + tig) * VST + n];
                bf[1] = KV[(ks * 8 + tig + 4) * VST + n];
                mma_tf32(oacc[nt], pa, bf);
            }
        }
        __syncthreads();
    }

#pragma unroll
    for (int nt = 0; nt < 4; nt++) {
        int col = h * DHh + wh * 32 + nt * 8 + 2 * tig;
        size_t row = (size_t)(b * Ss + qt + wq * 16 + g);
        *reinterpret_cast<float2*>(&g_ctx[row * Hh + col]) =
            make_float2(oacc[nt][0], oacc[nt][1]);
        *reinterpret_cast<float2*>(&g_ctx[(row + 8) * Hh + col]) =
            make_float2(oacc[nt][2], oacc[nt][3]);
    }
}

// ---------------- segment bookkeeping (deterministic) ----------------
__global__ void seg_prep_kernel(const int* __restrict__ tok) {
    int b = blockIdx.x, s = threadIdx.x;
    __shared__ int sc[Ss];
    __shared__ int cnt[Ss];
    int wid = tok[(b * Ss + s) * 2];
    int isnew = (s == 0) ? 1 : (wid != tok[(b * Ss + s - 1) * 2] ? 1 : 0);
    sc[s] = isnew; cnt[s] = 0; __syncthreads();
    for (int off = 1; off < Ss; off <<= 1) {
        int v = (s >= off) ? sc[s - off] : 0;
        __syncthreads();
        sc[s] += v;
        __syncthreads();
    }
    int gid = sc[s] - 1;
    if (tok[(b * Ss + s) * 2 + 1] != 0) atomicAdd(&cnt[gid], 1);
    if (isnew) g_seg_first[b * Ss + gid] = s;
    __syncthreads();
    g_seg_cnt[b * Ss + s] = cnt[s];
    if (s == Ss - 1) g_nseg[b] = gid + 1;
}

__global__ void seg_mean_kernel(const int* __restrict__ tok, float* __restrict__ out) {
    int g = blockIdx.x, b = blockIdx.y;
    int n = g_nseg[b];
    if (g >= n) return;
    int c = g_seg_cnt[b * Ss + g];
    if (c == 0) return;
    int start = g_seg_first[b * Ss + g];
    int end = (g + 1 < n) ? g_seg_first[b * Ss + g + 1] : Ss;
    __shared__ unsigned char mf[Ss];
    for (int s = threadIdx.x; s < Ss; s += 128)
        mf[s] = (tok[(b * Ss + s) * 2 + 1] != 0);
    __syncthreads();
    float inv = 1.0f / (float)c;
    for (int j = threadIdx.x; j < Hh; j += 128) {
        float sum = 0.f;
        for (int s = start; s < end; s++)
            if (mf[s]) sum += g_x[(size_t)(b * Ss + s) * Hh + j];
        out[(size_t)(b * Ss + g) * Hh + j] = sum * inv;
    }
}

// ---------------- launch ----------------
extern "C" void kernel_launch(void* const* d_in, const int* in_sizes, int n_in,
                              void* d_out, int out_size) {
    const int*   tok  = (const int*)  d_in[0];
    const float* emb  = (const float*)d_in[1];
    const float* pos  = (const float*)d_in[2];
    const float* lng  = (const float*)d_in[3];
    const float* lnb  = (const float*)d_in[4];
    const float* Wqkv = (const float*)d_in[5];
    const float* bqkv = (const float*)d_in[6];
    const float* Wo   = (const float*)d_in[7];
    const float* bo   = (const float*)d_in[8];
    const float* ln1g = (const float*)d_in[9];
    const float* ln1b = (const float*)d_in[10];
    const float* Wff1 = (const float*)d_in[11];
    const float* bff1 = (const float*)d_in[12];
    const float* Wff2 = (const float*)d_in[13];
    const float* bff2 = (const float*)d_in[14];
    const float* ln2g = (const float*)d_in[15];
    const float* ln2b = (const float*)d_in[16];
    float* out = (float*)d_out;

    void* p;
    cudaGetSymbolAddress(&p, g_x);   float* x   = (float*)p;
    cudaGetSymbolAddress(&p, g_tmp); float* tmp = (float*)p;
    cudaGetSymbolAddress(&p, g_ctx); float* ctx = (float*)p;
    cudaGetSymbolAddress(&p, g_wt);  float* wt  = (float*)p;

    cudaFuncSetAttribute(fused_attn_kernel,
                         cudaFuncAttributeMaxDynamicSharedMemorySize, ATTN_SMEM_BYTES);
    cudaFuncSetAttribute(gemm_tf32_kernel<128>,
                         cudaFuncAttributeMaxDynamicSharedMemorySize, GEMM_SMEM_128);
    cudaFuncSetAttribute(gemm_tf32_kernel<96>,
                         cudaFuncAttributeMaxDynamicSharedMemorySize, GEMM_SMEM_96);

    cudaMemsetAsync(d_out, 0, (size_t)out_size * sizeof(float), 0);

    // pre-round all weights onto tf32 grid (same layout), ~20us
    for (int l = 0; l < Ll; l++) {
        float* wl = wt + (size_t)l * WT_LAYER;
        round_tf32_kernel<<<(Hh*H3/4 + 255)/256, 256>>>(Wqkv + (size_t)l*Hh*H3, wl + WT_QKV, Hh*H3/4);
        round_tf32_kernel<<<(Hh*Hh/4 + 255)/256, 256>>>(Wo   + (size_t)l*Hh*Hh, wl + WT_WO,  Hh*Hh/4);
        round_tf32_kernel<<<(Hh*FFf/4 + 255)/256, 256>>>(Wff1 + (size_t)l*Hh*FFf, wl + WT_FF1, Hh*FFf/4);
        round_tf32_kernel<<<(FFf*Hh/4 + 255)/256, 256>>>(Wff2 + (size_t)l*FFf*Hh, wl + WT_FF2, FFf*Hh/4);
    }

    embed_ln_kernel<<<Tt, 256>>>(tok, emb, pos, lng, lnb);

    for (int l = 0; l < Ll; l++) {
        const float* wl = wt + (size_t)l * WT_LAYER;
        // QKV: [8192,768] @ [768,2304]   (18x64 tiles, ~4 full waves)
        gemm_tf32_kernel<128><<<dim3(H3 / 128, Tt / 128), 256, GEMM_SMEM_128>>>(
            x, wl + WT_QKV, bqkv + l * H3, tmp, Tt, H3, Hh, 0);
        // fused attention
        fused_attn_kernel<<<dim3(8, Bb * NHh), 256, ATTN_SMEM_BYTES>>>(tmp);
        // Wo: [8192,768] @ [768,768]     (8x64 tiles of BN=96)
        gemm_tf32_kernel<96><<<dim3(Hh / 96, Tt / 128), 256, GEMM_SMEM_96>>>(
            ctx, wl + WT_WO, bo + l * Hh, tmp, Tt, Hh, Hh, 0);
        add_ln_kernel<<<Tt, 256>>>(x, tmp, ln1g + l * Hh, ln1b + l * Hh, x);
        // FF1: [8192,768] @ [768,3072] + GELU  (32x64 tiles of BN=96, ~7 waves)
        gemm_tf32_kernel<96><<<dim3(FFf / 96, Tt / 128), 256, GEMM_SMEM_96>>>(
            x, wl + WT_FF1, bff1 + l * FFf, tmp, Tt, FFf, Hh, 1);
        // FF2: [8192,3072] @ [3072,768]  (8x64 tiles of BN=96)
        gemm_tf32_kernel<96><<<dim3(Hh / 96, Tt / 128), 256, GEMM_SMEM_96>>>(
            tmp, wl + WT_FF2, bff2 + l * Hh, ctx, Tt, Hh, FFf, 0);
        add_ln_kernel<<<Tt, 256>>>(x, ctx, ln2g + l * Hh, ln2b + l * Hh, x);
    }

    seg_prep_kernel<<<Bb, Ss>>>(tok);
    seg_mean_kernel<<<dim3(Ss, Bb), 128>>>(tok, out);
}

// round 8
// speedup vs baseline: 1.0858x; 1.0858x over previous
#include <cuda_runtime.h>
#include <math.h>
#include <stdint.h>

#define Bb   16
#define Ss   512
#define Hh   768
#define NHh  12
#define DHh  64
#define Ll   2
#define FFf  3072
#define Tt   (Bb*Ss)          // 8192 tokens
#define H3   (3*Hh)           // 2304

#define NSM       148
#define PERSIST   (2*NSM)     // 2 CTAs/SM

// ---------------- scratch (no allocations allowed) ----------------
__device__ float g_x[Tt*Hh];                    // hidden state      25 MB
__device__ float g_tmp[Tt*FFf];                 // qkv / wo / ff1   100 MB
__device__ float g_ctx[Tt*Hh];                  // attn ctx / ff2    25 MB
__device__ int   g_seg_first[Bb*Ss];
__device__ int   g_seg_cnt[Bb*Ss];
__device__ int   g_nseg[Bb];

// ---------------- helpers ----------------
__device__ __forceinline__ float block_reduce_sum_256(float v, float* red) {
    int t = threadIdx.x;
    red[t] = v; __syncthreads();
#pragma unroll
    for (int o = 128; o > 0; o >>= 1) {
        if (t < o) red[t] += red[t + o];
        __syncthreads();
    }
    float r = red[0];
    __syncthreads();
    return r;
}

__device__ __forceinline__ uint32_t f2tf32(float x) {
    uint32_t r;
    asm("cvt.rna.tf32.f32 %0, %1;" : "=r"(r) : "f"(x));
    return r;
}

__device__ __forceinline__ void mma_tf32(float* c, const uint32_t* a, const uint32_t* b) {
    asm volatile(
        "mma.sync.aligned.m16n8k8.row.col.f32.tf32.tf32.f32 "
        "{%0,%1,%2,%3}, {%4,%5,%6,%7}, {%8,%9}, {%0,%1,%2,%3};"
        : "+f"(c[0]), "+f"(c[1]), "+f"(c[2]), "+f"(c[3])
        : "r"(a[0]), "r"(a[1]), "r"(a[2]), "r"(a[3]), "r"(b[0]), "r"(b[1]));
}

__device__ __forceinline__ void cp_async16(void* smem_ptr, const void* gptr) {
    uint32_t s = (uint32_t)__cvta_generic_to_shared(smem_ptr);
    asm volatile("cp.async.cg.shared.global [%0], [%1], 16;" :: "r"(s), "l"(gptr));
}

// raw fp32 bits + half tf32 ulp; HW mma truncates low 13 bits => effective RNA
#define RND_TF32(x) ((x) + 0x1000u)

// ---------------- embedding + LN ----------------
__global__ void embed_ln_kernel(const int* __restrict__ tok,
                                const float* __restrict__ emb,
                                const float* __restrict__ pos,
                                const float* __restrict__ g,
                                const float* __restrict__ bt) {
    int row = blockIdx.x;
    int s   = row & (Ss - 1);
    int id  = tok[row * 2 + 1];
    __shared__ float y[Hh];
    __shared__ float red[256];
    int t = threadIdx.x;
    float part = 0.f;
    for (int j = t; j < Hh; j += 256) {
        float v = emb[(size_t)id * Hh + j] + pos[s * Hh + j];
        y[j] = v; part += v;
    }
    float mean = block_reduce_sum_256(part, red) * (1.f / Hh);
    part = 0.f;
    for (int j = t; j < Hh; j += 256) { float d = y[j] - mean; part += d * d; }
    float var = block_reduce_sum_256(part, red) * (1.f / Hh);
    float inv = rsqrtf(var + 1e-12f);
    for (int j = t; j < Hh; j += 256)
        g_x[(size_t)row * Hh + j] = (y[j] - mean) * inv * g[j] + bt[j];
}

// ---------------- residual add + LN ----------------
__global__ void add_ln_kernel(const float* __restrict__ x,
                              const float* __restrict__ tadd,
                              const float* __restrict__ g,
                              const float* __restrict__ bt,
                              float* __restrict__ out) {
    int row = blockIdx.x;
    size_t base = (size_t)row * Hh;
    __shared__ float y[Hh];
    __shared__ float red[256];
    int t = threadIdx.x;
    float part = 0.f;
    for (int j = t; j < Hh; j += 256) {
        float v = x[base + j] + tadd[base + j];
        y[j] = v; part += v;
    }
    float mean = block_reduce_sum_256(part, red) * (1.f / Hh);
    part = 0.f;
    for (int j = t; j < Hh; j += 256) { float d = y[j] - mean; part += d * d; }
    float var = block_reduce_sum_256(part, red) * (1.f / Hh);
    float inv = rsqrtf(var + 1e-12f);
    for (int j = t; j < Hh; j += 256)
        out[base + j] = (y[j] - mean) * inv * g[j] + bt[j];
}

// ------- persistent TF32 tensor-core GEMM, 3-stage cp.async pipeline ---------
// C = A[M,K] @ W[K,N] + bias, optional GELU. BM=BN=128, BK=32, 8 warps (2x4).
// Grid = min(tiles, PERSIST); each CTA strides over tiles (n fastest for L2 reuse of A).
#define AS_STRIDE 36
#define BS_STRIDE 132
#define AS_SZ     (128 * AS_STRIDE)          // 4608 u32
#define BS_SZ     (32 * BS_STRIDE)           // 4224 u32
#define STAGE_SZ  (AS_SZ + BS_SZ)            // 8832 u32
#define NSTAGE    3
#define GEMM_SMEM_BYTES (NSTAGE * STAGE_SZ * 4)   // 105984 B

__global__ __launch_bounds__(256) void gemm_tf32_kernel(const float* __restrict__ A,
                                                        const float* __restrict__ W,
                                                        const float* __restrict__ bias,
                                                        float* __restrict__ C,
                                                        int M, int N, int K, int act,
                                                        int numTiles, int nTN) {
    extern __shared__ uint32_t sm[];
    int tid  = threadIdx.x;
    int lane = tid & 31;
    int warp = tid >> 5;
    int g    = lane >> 2, tig = lane & 3;
    int wm   = warp >> 2, wn = warp & 3;
    int nK   = K >> 5;

    for (int t = blockIdx.x; t < numTiles; t += gridDim.x) {
        int mBase = (t / nTN) * 128;
        int nBase = (t % nTN) * 128;

        float acc[4][4][4];
#pragma unroll
        for (int i = 0; i < 4; i++)
#pragma unroll
            for (int j = 0; j < 4; j++)
#pragma unroll
                for (int r = 0; r < 4; r++) acc[i][j][r] = 0.f;

        auto load_stage = [&](int stage, int k0) {
            uint32_t* st = sm + stage * STAGE_SZ;
#pragma unroll
            for (int i = 0; i < 4; i++) {
                int idx = tid + i * 256;
                int r = idx >> 3, c4 = (idx & 7) << 2;
                cp_async16(&st[r * AS_STRIDE + c4],
                           &A[(size_t)(mBase + r) * K + k0 + c4]);
            }
            uint32_t* bs = st + AS_SZ;
#pragma unroll
            for (int i = 0; i < 4; i++) {
                int idx = tid + i * 256;
                int r = idx >> 5, c4 = (idx & 31) << 2;
                cp_async16(&bs[r * BS_STRIDE + c4],
                           &W[(size_t)(k0 + r) * N + nBase + c4]);
            }
            asm volatile("cp.async.commit_group;" ::: "memory");
        };

        load_stage(0, 0);
        load_stage(1, 32);

        int s_cur = 0, s_next = 2;
        for (int i = 0; i < nK; i++) {
            if (i + 2 < nK) {
                load_stage(s_next, (i + 2) << 5);
                asm volatile("cp.async.wait_group 2;" ::: "memory");
            } else if (i + 1 < nK) {
                asm volatile("cp.async.wait_group 1;" ::: "memory");
            } else {
                asm volatile("cp.async.wait_group 0;" ::: "memory");
            }
            __syncthreads();

            const uint32_t* As = sm + s_cur * STAGE_SZ;
            const uint32_t* Bs = As + AS_SZ;
#pragma unroll
            for (int kk = 0; kk < 32; kk += 8) {
                uint32_t a[4][4], b[4][2];
#pragma unroll
                for (int mi = 0; mi < 4; mi++) {
                    int rm = wm * 64 + mi * 16 + g;
                    a[mi][0] = RND_TF32(As[rm * AS_STRIDE + kk + tig]);
                    a[mi][1] = RND_TF32(As[(rm + 8) * AS_STRIDE + kk + tig]);
                    a[mi][2] = RND_TF32(As[rm * AS_STRIDE + kk + tig + 4]);
                    a[mi][3] = RND_TF32(As[(rm + 8) * AS_STRIDE + kk + tig + 4]);
                }
#pragma unroll
                for (int ni = 0; ni < 4; ni++) {
                    int cn = wn * 32 + ni * 8 + g;
                    b[ni][0] = RND_TF32(Bs[(kk + tig) * BS_STRIDE + cn]);
                    b[ni][1] = RND_TF32(Bs[(kk + tig + 4) * BS_STRIDE + cn]);
                }
#pragma unroll
                for (int mi = 0; mi < 4; mi++)
#pragma unroll
                    for (int ni = 0; ni < 4; ni++)
                        mma_tf32(acc[mi][ni], a[mi], b[ni]);
            }
            __syncthreads();
            s_cur = (s_cur == 2) ? 0 : s_cur + 1;
            s_next = (s_next == 2) ? 0 : s_next + 1;
        }

        // epilogue: bias + optional exact GELU, float2 stores (regs only; smem free)
#pragma unroll
        for (int mi = 0; mi < 4; mi++) {
            int rm0 = mBase + wm * 64 + mi * 16 + g;
#pragma unroll
            for (int ni = 0; ni < 4; ni++) {
                int cn = nBase + wn * 32 + ni * 8 + 2 * tig;
                float b0 = bias[cn], b1 = bias[cn + 1];
                float v0 = acc[mi][ni][0] + b0;
                float v1 = acc[mi][ni][1] + b1;
                float v2 = acc[mi][ni][2] + b0;
                float v3 = acc[mi][ni][3] + b1;
                if (act) {
                    v0 = 0.5f * v0 * (1.0f + erff(v0 * 0.70710678118654752f));
                    v1 = 0.5f * v1 * (1.0f + erff(v1 * 0.70710678118654752f));
                    v2 = 0.5f * v2 * (1.0f + erff(v2 * 0.70710678118654752f));
                    v3 = 0.5f * v3 * (1.0f + erff(v3 * 0.70710678118654752f));
                }
                *reinterpret_cast<float2*>(&C[(size_t)rm0 * N + cn])       = make_float2(v0, v1);
                *reinterpret_cast<float2*>(&C[(size_t)(rm0 + 8) * N + cn]) = make_float2(v2, v3);
            }
        }
    }
}

static inline void launch_gemm(const float* A, const float* W, const float* bias,
                               float* C, int M, int N, int K, int act) {
    int nTM = M / 128, nTN = N / 128;
    int tiles = nTM * nTN;
    int grid = tiles < PERSIST ? tiles : PERSIST;
    gemm_tf32_kernel<<<grid, 256, GEMM_SMEM_BYTES>>>(A, W, bias, C, M, N, K, act,
                                                     tiles, nTN);
}

// ---------------- fused attention: per (q-tile 64, b*h) block -----------------
#define SSS   516
#define KST   68
#define VST   72
#define ATTN_SMEM_BYTES ((64*SSS + 64*VST) * 4)

__global__ __launch_bounds__(256) void fused_attn_kernel(const float* __restrict__ qkv) {
    extern __shared__ float smem[];
    float*    Ssm = smem;                                        // 64 x 516
    uint32_t* KV  = reinterpret_cast<uint32_t*>(smem + 64 * SSS);// 64 x 72

    int bh = blockIdx.y; int b = bh / NHh, h = bh - b * NHh;
    int qt = blockIdx.x * 64;
    int tid = threadIdx.x, lane = tid & 31, warp = tid >> 5;
    int g = lane >> 2, tig = lane & 3;
    int wq = warp >> 1, wh = warp & 1;

#pragma unroll
    for (int i = 0; i < 4; i++) {
        int idx = tid + i * 256;
        int r = idx >> 4, c4 = (idx & 15) << 2;
        float4 v = *reinterpret_cast<const float4*>(
            &qkv[(size_t)(b * Ss + qt + r) * H3 + h * DHh + c4]);
        uint32_t* p = &KV[r * KST + c4];
        p[0] = f2tf32(v.x); p[1] = f2tf32(v.y);
        p[2] = f2tf32(v.z); p[3] = f2tf32(v.w);
    }
    __syncthreads();

    uint32_t qa[8][4];
#pragma unroll
    for (int ks = 0; ks < 8; ks++) {
        int rm = wq * 16 + g;
        qa[ks][0] = KV[rm * KST + ks * 8 + tig];
        qa[ks][1] = KV[(rm + 8) * KST + ks * 8 + tig];
        qa[ks][2] = KV[rm * KST + ks * 8 + tig + 4];
        qa[ks][3] = KV[(rm + 8) * KST + ks * 8 + tig + 4];
    }
    __syncthreads();

    for (int kt = 0; kt < 8; kt++) {
#pragma unroll
        for (int i = 0; i < 4; i++) {
            int idx = tid + i * 256;
            int r = idx >> 4, c4 = (idx & 15) << 2;
            float4 v = *reinterpret_cast<const float4*>(
                &qkv[(size_t)(b * Ss + kt * 64 + r) * H3 + Hh + h * DHh + c4]);
            uint32_t* p = &KV[r * KST + c4];
            p[0] = f2tf32(v.x); p[1] = f2tf32(v.y);
            p[2] = f2tf32(v.z); p[3] = f2tf32(v.w);
        }
        __syncthreads();
        float acc[4][4];
#pragma unroll
        for (int nt = 0; nt < 4; nt++)
#pragma unroll
            for (int r = 0; r < 4; r++) acc[nt][r] = 0.f;
#pragma unroll
        for (int ks = 0; ks < 8; ks++) {
            uint32_t bf[4][2];
#pragma unroll
            for (int nt = 0; nt < 4; nt++) {
                int n = wh * 32 + nt * 8 + g;
                bf[nt][0] = KV[n * KST + ks * 8 + tig];
                bf[nt][1] = KV[n * KST + ks * 8 + tig + 4];
            }
#pragma unroll
            for (int nt = 0; nt < 4; nt++)
                mma_tf32(acc[nt], qa[ks], bf[nt]);
        }
#pragma unroll
        for (int nt = 0; nt < 4; nt++) {
            int col = kt * 64 + wh * 32 + nt * 8 + 2 * tig;
            int row = wq * 16 + g;
            Ssm[row * SSS + col]           = acc[nt][0] * 0.125f;
            Ssm[row * SSS + col + 1]       = acc[nt][1] * 0.125f;
            Ssm[(row + 8) * SSS + col]     = acc[nt][2] * 0.125f;
            Ssm[(row + 8) * SSS + col + 1] = acc[nt][3] * 0.125f;
        }
        __syncthreads();
    }

    for (int r = warp * 8; r < warp * 8 + 8; r++) {
        float* row = &Ssm[r * SSS];
        float v[16];
        float m = -1e30f;
#pragma unroll
        for (int i = 0; i < 16; i++) { v[i] = row[lane + 32 * i]; m = fmaxf(m, v[i]); }
#pragma unroll
        for (int o = 16; o > 0; o >>= 1) m = fmaxf(m, __shfl_xor_sync(0xffffffffu, m, o));
        float s = 0.f;
#pragma unroll
        for (int i = 0; i < 16; i++) { v[i] = __expf(v[i] - m); s += v[i]; }
#pragma unroll
        for (int o = 16; o > 0; o >>= 1) s += __shfl_xor_sync(0xffffffffu, s, o);
        float inv = 1.0f / s;
#pragma unroll
        for (int i = 0; i < 16; i++) row[lane + 32 * i] = v[i] * inv;
    }
    __syncthreads();

    float oacc[4][4];
#pragma unroll
    for (int nt = 0; nt < 4; nt++)
#pragma unroll
        for (int r = 0; r < 4; r++) oacc[nt][r] = 0.f;

    for (int kt = 0; kt < 8; kt++) {
#pragma unroll
        for (int i = 0; i < 4; i++) {
            int idx = tid + i * 256;
            int r = idx >> 4, c4 = (idx & 15) << 2;
            float4 v = *reinterpret_cast<const float4*>(
                &qkv[(size_t)(b * Ss + kt * 64 + r) * H3 + 2 * Hh + h * DHh + c4]);
            uint32_t* p = &KV[r * VST + c4];
            p[0] = f2tf32(v.x); p[1] = f2tf32(v.y);
            p[2] = f2tf32(v.z); p[3] = f2tf32(v.w);
        }
        __syncthreads();
#pragma unroll
        for (int ks = 0; ks < 8; ks++) {
            uint32_t pa[4];
            int rm = wq * 16 + g;
            int kc = kt * 64 + ks * 8;
            pa[0] = f2tf32(Ssm[rm * SSS + kc + tig]);
            pa[1] = f2tf32(Ssm[(rm + 8) * SSS + kc + tig]);
            pa[2] = f2tf32(Ssm[rm * SSS + kc + tig + 4]);
            pa[3] = f2tf32(Ssm[(rm + 8) * SSS + kc + tig + 4]);
#pragma unroll
            for (int nt = 0; nt < 4; nt++) {
                uint32_t bf[2];
                int n = wh * 32 + nt * 8 + g;
                bf[0] = KV[(ks * 8 + tig) * VST + n];
                bf[1] = KV[(ks * 8 + tig + 4) * VST + n];
                mma_tf32(oacc[nt], pa, bf);
            }
        }
        __syncthreads();
    }

#pragma unroll
    for (int nt = 0; nt < 4; nt++) {
        int col = h * DHh + wh * 32 + nt * 8 + 2 * tig;
        size_t row = (size_t)(b * Ss + qt + wq * 16 + g);
        *reinterpret_cast<float2*>(&g_ctx[row * Hh + col]) =
            make_float2(oacc[nt][0], oacc[nt][1]);
        *reinterpret_cast<float2*>(&g_ctx[(row + 8) * Hh + col]) =
            make_float2(oacc[nt][2], oacc[nt][3]);
    }
}

// ---------------- segment bookkeeping (deterministic) ----------------
__global__ void seg_prep_kernel(const int* __restrict__ tok) {
    int b = blockIdx.x, s = threadIdx.x;
    __shared__ int sc[Ss];
    __shared__ int cnt[Ss];
    int wid = tok[(b * Ss + s) * 2];
    int isnew = (s == 0) ? 1 : (wid != tok[(b * Ss + s - 1) * 2] ? 1 : 0);
    sc[s] = isnew; cnt[s] = 0; __syncthreads();
    for (int off = 1; off < Ss; off <<= 1) {
        int v = (s >= off) ? sc[s - off] : 0;
        __syncthreads();
        sc[s] += v;
        __syncthreads();
    }
    int gid = sc[s] - 1;
    if (tok[(b * Ss + s) * 2 + 1] != 0) atomicAdd(&cnt[gid], 1);
    if (isnew) g_seg_first[b * Ss + gid] = s;
    __syncthreads();
    g_seg_cnt[b * Ss + s] = cnt[s];
    if (s == Ss - 1) g_nseg[b] = gid + 1;
}

__global__ void seg_mean_kernel(const int* __restrict__ tok, float* __restrict__ out) {
    int g = blockIdx.x, b = blockIdx.y;
    int n = g_nseg[b];
    if (g >= n) return;
    int c = g_seg_cnt[b * Ss + g];
    if (c == 0) return;
    int start = g_seg_first[b * Ss + g];
    int end = (g + 1 < n) ? g_seg_first[b * Ss + g + 1] : Ss;
    __shared__ unsigned char mf[Ss];
    for (int s = threadIdx.x; s < Ss; s += 128)
        mf[s] = (tok[(b * Ss + s) * 2 + 1] != 0);
    __syncthreads();
    float inv = 1.0f / (float)c;
    for (int j = threadIdx.x; j < Hh; j += 128) {
        float sum = 0.f;
        for (int s = start; s < end; s++)
            if (mf[s]) sum += g_x[(size_t)(b * Ss + s) * Hh + j];
        out[(size_t)(b * Ss + g) * Hh + j] = sum * inv;
    }
}

// ---------------- launch ----------------
extern "C" void kernel_launch(void* const* d_in, const int* in_sizes, int n_in,
                              void* d_out, int out_size) {
    const int*   tok  = (const int*)  d_in[0];
    const float* emb  = (const float*)d_in[1];
    const float* pos  = (const float*)d_in[2];
    const float* lng  = (const float*)d_in[3];
    const float* lnb  = (const float*)d_in[4];
    const float* Wqkv = (const float*)d_in[5];
    const float* bqkv = (const float*)d_in[6];
    const float* Wo   = (const float*)d_in[7];
    const float* bo   = (const float*)d_in[8];
    const float* ln1g = (const float*)d_in[9];
    const float* ln1b = (const float*)d_in[10];
    const float* Wff1 = (const float*)d_in[11];
    const float* bff1 = (const float*)d_in[12];
    const float* Wff2 = (const float*)d_in[13];
    const float* bff2 = (const float*)d_in[14];
    const float* ln2g = (const float*)d_in[15];
    const float* ln2b = (const float*)d_in[16];
    float* out = (float*)d_out;

    void* p;
    cudaGetSymbolAddress(&p, g_x);   float* x   = (float*)p;
    cudaGetSymbolAddress(&p, g_tmp); float* tmp = (float*)p;
    cudaGetSymbolAddress(&p, g_ctx); float* ctx = (float*)p;

    cudaFuncSetAttribute(fused_attn_kernel,
                         cudaFuncAttributeMaxDynamicSharedMemorySize, ATTN_SMEM_BYTES);
    cudaFuncSetAttribute(gemm_tf32_kernel,
                         cudaFuncAttributeMaxDynamicSharedMemorySize, GEMM_SMEM_BYTES);

    cudaMemsetAsync(d_out, 0, (size_t)out_size * sizeof(float), 0);

    embed_ln_kernel<<<Tt, 256>>>(tok, emb, pos, lng, lnb);

    for (int l = 0; l < Ll; l++) {
        // QKV: [8192,768] @ [768,2304]
        launch_gemm(x, Wqkv + (size_t)l * Hh * H3, bqkv + l * H3, tmp, Tt, H3, Hh, 0);
        // fused attention
        fused_attn_kernel<<<dim3(8, Bb * NHh), 256, ATTN_SMEM_BYTES>>>(tmp);
        // Wo: [8192,768] @ [768,768]
        launch_gemm(ctx, Wo + (size_t)l * Hh * Hh, bo + l * Hh, tmp, Tt, Hh, Hh, 0);
        add_ln_kernel<<<Tt, 256>>>(x, tmp, ln1g + l * Hh, ln1b + l * Hh, x);
        // FF1: [8192,768] @ [768,3072] + GELU
        launch_gemm(x, Wff1 + (size_t)l * Hh * FFf, bff1 + l * FFf, tmp, Tt, FFf, Hh, 1);
        // FF2: [8192,3072] @ [3072,768]
        launch_gemm(tmp, Wff2 + (size_t)l * FFf * Hh, bff2 + l * Hh, ctx, Tt, Hh, FFf, 0);
        add_ln_kernel<<<Tt, 256>>>(x, ctx, ln2g + l * Hh, ln2b + l * Hh, x);
    }

    seg_prep_kernel<<<Bb, Ss>>>(tok);
    seg_mean_kernel<<<dim3(Ss, Bb), 128>>>(tok, out);
}

// round 9
// speedup vs baseline: 1.1623x; 1.0705x over previous
#include <cuda_runtime.h>
#include <math.h>
#include <stdint.h>

#define Bb   16
#define Ss   512
#define Hh   768
#define NHh  12
#define DHh  64
#define Ll   2
#define FFf  3072
#define Tt   (Bb*Ss)          // 8192 tokens
#define H3   (3*Hh)           // 2304

#define NSM       148
#define PERSIST   (2*NSM)     // 2 CTAs/SM

// ---------------- scratch (no allocations allowed) ----------------
__device__ float g_x[Tt*Hh];                    // hidden state      25 MB
__device__ float g_tmp[Tt*FFf];                 // qkv / wo / ff1   100 MB
__device__ float g_ctx[Tt*Hh];                  // attn ctx / ff2    25 MB
__device__ int   g_seg_first[Bb*Ss];
__device__ int   g_seg_cnt[Bb*Ss];
__device__ int   g_nseg[Bb];

// ---------------- helpers ----------------
__device__ __forceinline__ float block_reduce_sum_256(float v, float* red) {
    int t = threadIdx.x;
    red[t] = v; __syncthreads();
#pragma unroll
    for (int o = 128; o > 0; o >>= 1) {
        if (t < o) red[t] += red[t + o];
        __syncthreads();
    }
    float r = red[0];
    __syncthreads();
    return r;
}

__device__ __forceinline__ void mma_tf32(float* c, const uint32_t* a, const uint32_t* b) {
    asm volatile(
        "mma.sync.aligned.m16n8k8.row.col.f32.tf32.tf32.f32 "
        "{%0,%1,%2,%3}, {%4,%5,%6,%7}, {%8,%9}, {%0,%1,%2,%3};"
        : "+f"(c[0]), "+f"(c[1]), "+f"(c[2]), "+f"(c[3])
        : "r"(a[0]), "r"(a[1]), "r"(a[2]), "r"(a[3]), "r"(b[0]), "r"(b[1]));
}

__device__ __forceinline__ void cp_async16(void* smem_ptr, const void* gptr) {
    uint32_t s = (uint32_t)__cvta_generic_to_shared(smem_ptr);
    asm volatile("cp.async.cg.shared.global [%0], [%1], 16;" :: "r"(s), "l"(gptr));
}

// raw fp32 bits + half tf32 ulp; HW mma truncates low 13 bits => effective RNA
#define RND_TF32(x) ((x) + 0x1000u)

// ---------------- embedding + LN ----------------
__global__ void embed_ln_kernel(const int* __restrict__ tok,
                                const float* __restrict__ emb,
                                const float* __restrict__ pos,
                                const float* __restrict__ g,
                                const float* __restrict__ bt) {
    int row = blockIdx.x;
    int s   = row & (Ss - 1);
    int id  = tok[row * 2 + 1];
    __shared__ float y[Hh];
    __shared__ float red[256];
    int t = threadIdx.x;
    float part = 0.f;
    for (int j = t; j < Hh; j += 256) {
        float v = emb[(size_t)id * Hh + j] + pos[s * Hh + j];
        y[j] = v; part += v;
    }
    float mean = block_reduce_sum_256(part, red) * (1.f / Hh);
    part = 0.f;
    for (int j = t; j < Hh; j += 256) { float d = y[j] - mean; part += d * d; }
    float var = block_reduce_sum_256(part, red) * (1.f / Hh);
    float inv = rsqrtf(var + 1e-12f);
    for (int j = t; j < Hh; j += 256)
        g_x[(size_t)row * Hh + j] = (y[j] - mean) * inv * g[j] + bt[j];
}

// ---------------- residual add + LN ----------------
__global__ void add_ln_kernel(const float* __restrict__ x,
                              const float* __restrict__ tadd,
                              const float* __restrict__ g,
                              const float* __restrict__ bt,
                              float* __restrict__ out) {
    int row = blockIdx.x;
    size_t base = (size_t)row * Hh;
    __shared__ float y[Hh];
    __shared__ float red[256];
    int t = threadIdx.x;
    float part = 0.f;
    for (int j = t; j < Hh; j += 256) {
        float v = x[base + j] + tadd[base + j];
        y[j] = v; part += v;
    }
    float mean = block_reduce_sum_256(part, red) * (1.f / Hh);
    part = 0.f;
    for (int j = t; j < Hh; j += 256) { float d = y[j] - mean; part += d * d; }
    float var = block_reduce_sum_256(part, red) * (1.f / Hh);
    float inv = rsqrtf(var + 1e-12f);
    for (int j = t; j < Hh; j += 256)
        out[base + j] = (y[j] - mean) * inv * g[j] + bt[j];
}

// ------- persistent TF32 tensor-core GEMM, 3-stage cp.async pipeline ---------
#define AS_STRIDE 36
#define BS_STRIDE 132
#define AS_SZ     (128 * AS_STRIDE)
#define BS_SZ     (32 * BS_STRIDE)
#define STAGE_SZ  (AS_SZ + BS_SZ)
#define NSTAGE    3
#define GEMM_SMEM_BYTES (NSTAGE * STAGE_SZ * 4)

__global__ __launch_bounds__(256) void gemm_tf32_kernel(const float* __restrict__ A,
                                                        const float* __restrict__ W,
                                                        const float* __restrict__ bias,
                                                        float* __restrict__ C,
                                                        int M, int N, int K, int act,
                                                        int numTiles, int nTN) {
    extern __shared__ uint32_t sm[];
    int tid  = threadIdx.x;
    int lane = tid & 31;
    int warp = tid >> 5;
    int g    = lane >> 2, tig = lane & 3;
    int wm   = warp >> 2, wn = warp & 3;
    int nK   = K >> 5;

    for (int t = blockIdx.x; t < numTiles; t += gridDim.x) {
        int mBase = (t / nTN) * 128;
        int nBase = (t % nTN) * 128;

        float acc[4][4][4];
#pragma unroll
        for (int i = 0; i < 4; i++)
#pragma unroll
            for (int j = 0; j < 4; j++)
#pragma unroll
                for (int r = 0; r < 4; r++) acc[i][j][r] = 0.f;

        auto load_stage = [&](int stage, int k0) {
            uint32_t* st = sm + stage * STAGE_SZ;
#pragma unroll
            for (int i = 0; i < 4; i++) {
                int idx = tid + i * 256;
                int r = idx >> 3, c4 = (idx & 7) << 2;
                cp_async16(&st[r * AS_STRIDE + c4],
                           &A[(size_t)(mBase + r) * K + k0 + c4]);
            }
            uint32_t* bs = st + AS_SZ;
#pragma unroll
            for (int i = 0; i < 4; i++) {
                int idx = tid + i * 256;
                int r = idx >> 5, c4 = (idx & 31) << 2;
                cp_async16(&bs[r * BS_STRIDE + c4],
                           &W[(size_t)(k0 + r) * N + nBase + c4]);
            }
            asm volatile("cp.async.commit_group;" ::: "memory");
        };

        load_stage(0, 0);
        load_stage(1, 32);

        int s_cur = 0, s_next = 2;
        for (int i = 0; i < nK; i++) {
            if (i + 2 < nK) {
                load_stage(s_next, (i + 2) << 5);
                asm volatile("cp.async.wait_group 2;" ::: "memory");
            } else if (i + 1 < nK) {
                asm volatile("cp.async.wait_group 1;" ::: "memory");
            } else {
                asm volatile("cp.async.wait_group 0;" ::: "memory");
            }
            __syncthreads();

            const uint32_t* As = sm + s_cur * STAGE_SZ;
            const uint32_t* Bs = As + AS_SZ;
#pragma unroll
            for (int kk = 0; kk < 32; kk += 8) {
                uint32_t a[4][4], b[4][2];
#pragma unroll
                for (int mi = 0; mi < 4; mi++) {
                    int rm = wm * 64 + mi * 16 + g;
                    a[mi][0] = RND_TF32(As[rm * AS_STRIDE + kk + tig]);
                    a[mi][1] = RND_TF32(As[(rm + 8) * AS_STRIDE + kk + tig]);
                    a[mi][2] = RND_TF32(As[rm * AS_STRIDE + kk + tig + 4]);
                    a[mi][3] = RND_TF32(As[(rm + 8) * AS_STRIDE + kk + tig + 4]);
                }
#pragma unroll
                for (int ni = 0; ni < 4; ni++) {
                    int cn = wn * 32 + ni * 8 + g;
                    b[ni][0] = RND_TF32(Bs[(kk + tig) * BS_STRIDE + cn]);
                    b[ni][1] = RND_TF32(Bs[(kk + tig + 4) * BS_STRIDE + cn]);
                }
#pragma unroll
                for (int mi = 0; mi < 4; mi++)
#pragma unroll
                    for (int ni = 0; ni < 4; ni++)
                        mma_tf32(acc[mi][ni], a[mi], b[ni]);
            }
            __syncthreads();
            s_cur = (s_cur == 2) ? 0 : s_cur + 1;
            s_next = (s_next == 2) ? 0 : s_next + 1;
        }

#pragma unroll
        for (int mi = 0; mi < 4; mi++) {
            int rm0 = mBase + wm * 64 + mi * 16 + g;
#pragma unroll
            for (int ni = 0; ni < 4; ni++) {
                int cn = nBase + wn * 32 + ni * 8 + 2 * tig;
                float b0 = bias[cn], b1 = bias[cn + 1];
                float v0 = acc[mi][ni][0] + b0;
                float v1 = acc[mi][ni][1] + b1;
                float v2 = acc[mi][ni][2] + b0;
                float v3 = acc[mi][ni][3] + b1;
                if (act) {
                    v0 = 0.5f * v0 * (1.0f + erff(v0 * 0.70710678118654752f));
                    v1 = 0.5f * v1 * (1.0f + erff(v1 * 0.70710678118654752f));
                    v2 = 0.5f * v2 * (1.0f + erff(v2 * 0.70710678118654752f));
                    v3 = 0.5f * v3 * (1.0f + erff(v3 * 0.70710678118654752f));
                }
                *reinterpret_cast<float2*>(&C[(size_t)rm0 * N + cn])       = make_float2(v0, v1);
                *reinterpret_cast<float2*>(&C[(size_t)(rm0 + 8) * N + cn]) = make_float2(v2, v3);
            }
        }
    }
}

static inline void launch_gemm(const float* A, const float* W, const float* bias,
                               float* C, int M, int N, int K, int act) {
    int nTM = M / 128, nTN = N / 128;
    int tiles = nTM * nTN;
    int grid = tiles < PERSIST ? tiles : PERSIST;
    gemm_tf32_kernel<<<grid, 256, GEMM_SMEM_BYTES>>>(A, W, bias, C, M, N, K, act,
                                                     tiles, nTN);
}

// -------- fused attention with cp.async double-buffered tiles -----------------
// S buffer raw fp32 in smem; K/V tiles raw fp32 via cp.async; TF32 RNA at frag read.
#define SSS   516
#define KST   68
#define VST   72
#define ATTN_SMEM_BYTES ((64*SSS + 2*64*VST) * 4)   // 168960 B

__global__ __launch_bounds__(256) void fused_attn_kernel(const float* __restrict__ qkv) {
    extern __shared__ float smem[];
    float* Ssm = smem;                        // 64 x 516
    float* kvA = smem + 64 * SSS;             // 64 x 72
    float* kvB = kvA + 64 * VST;              // 64 x 72

    int bh = blockIdx.y; int b = bh / NHh, h = bh - b * NHh;
    int qt = blockIdx.x * 64;
    int tid = threadIdx.x, lane = tid & 31, warp = tid >> 5;
    int g = lane >> 2, tig = lane & 3;
    int wq = warp >> 1, wh = warp & 1;

    const float* Qg = &qkv[(size_t)(b * Ss + qt) * H3 + h * DHh];
    const float* Kg = &qkv[(size_t)(b * Ss) * H3 + Hh + h * DHh];
    const float* Vg = &qkv[(size_t)(b * Ss) * H3 + 2 * Hh + h * DHh];

    auto issue_tile = [&](float* buf, const float* src, int su32) {
#pragma unroll
        for (int i = 0; i < 4; i++) {
            int idx = tid + i * 256;
            int r = idx >> 4, c4 = (idx & 15) << 2;
            cp_async16(&buf[r * su32 + c4], &src[(size_t)r * H3 + c4]);
        }
        asm volatile("cp.async.commit_group;" ::: "memory");
    };

    // prologue: Q -> kvA, K0 -> kvB
    issue_tile(kvA, Qg, KST);
    issue_tile(kvB, Kg, KST);
    asm volatile("cp.async.wait_group 0;" ::: "memory");
    __syncthreads();

    // extract Q fragments; fold 1/8 scale (exact power of 2) + RNA round
    uint32_t qa[8][4];
    {
        int rm = wq * 16 + g;
#pragma unroll
        for (int ks = 0; ks < 8; ks++) {
            qa[ks][0] = __float_as_uint(kvA[rm * KST + ks * 8 + tig] * 0.125f) + 0x1000u;
            qa[ks][1] = __float_as_uint(kvA[(rm + 8) * KST + ks * 8 + tig] * 0.125f) + 0x1000u;
            qa[ks][2] = __float_as_uint(kvA[rm * KST + ks * 8 + tig + 4] * 0.125f) + 0x1000u;
            qa[ks][3] = __float_as_uint(kvA[(rm + 8) * KST + ks * 8 + tig + 4] * 0.125f) + 0x1000u;
        }
    }
    __syncthreads();   // all Q reads done before K1 overwrites kvA

    // ---- S = (Q/8) @ K^T, double-buffered K ----
    for (int kt = 0; kt < 8; kt++) {
        float* cur = (kt & 1) ? kvA : kvB;
        float* nxt = (kt & 1) ? kvB : kvA;
        if (kt < 7) {
            issue_tile(nxt, Kg + (size_t)(kt + 1) * 64 * H3, KST);
            asm volatile("cp.async.wait_group 1;" ::: "memory");
        } else {
            asm volatile("cp.async.wait_group 0;" ::: "memory");
        }
        __syncthreads();

        const uint32_t* Ku = (const uint32_t*)cur;
        float acc[4][4];
#pragma unroll
        for (int nt = 0; nt < 4; nt++)
#pragma unroll
            for (int r = 0; r < 4; r++) acc[nt][r] = 0.f;
#pragma unroll
        for (int ks = 0; ks < 8; ks++) {
            uint32_t bf[4][2];
#pragma unroll
            for (int nt = 0; nt < 4; nt++) {
                int n = wh * 32 + nt * 8 + g;
                bf[nt][0] = RND_TF32(Ku[n * KST + ks * 8 + tig]);
                bf[nt][1] = RND_TF32(Ku[n * KST + ks * 8 + tig + 4]);
            }
#pragma unroll
            for (int nt = 0; nt < 4; nt++)
                mma_tf32(acc[nt], qa[ks], bf[nt]);
        }
#pragma unroll
        for (int nt = 0; nt < 4; nt++) {
            int col = kt * 64 + wh * 32 + nt * 8 + 2 * tig;
            int row = wq * 16 + g;
            Ssm[row * SSS + col]           = acc[nt][0];
            Ssm[row * SSS + col + 1]       = acc[nt][1];
            Ssm[(row + 8) * SSS + col]     = acc[nt][2];
            Ssm[(row + 8) * SSS + col + 1] = acc[nt][3];
        }
        __syncthreads();
    }

    // prefetch V0 -> kvB, V1 -> kvA; they land while softmax runs
    issue_tile(kvB, Vg, VST);
    issue_tile(kvA, Vg + (size_t)64 * H3, VST);

    // ---- softmax over each row of 512 (one warp per 8 rows) ----
    for (int r = warp * 8; r < warp * 8 + 8; r++) {
        float* row = &Ssm[r * SSS];
        float v[16];
        float m = -1e30f;
#pragma unroll
        for (int i = 0; i < 16; i++) { v[i] = row[lane + 32 * i]; m = fmaxf(m, v[i]); }
#pragma unroll
        for (int o = 16; o > 0; o >>= 1) m = fmaxf(m, __shfl_xor_sync(0xffffffffu, m, o));
        float s = 0.f;
#pragma unroll
        for (int i = 0; i < 16; i++) { v[i] = __expf(v[i] - m); s += v[i]; }
#pragma unroll
        for (int o = 16; o > 0; o >>= 1) s += __shfl_xor_sync(0xffffffffu, s, o);
        float inv = 1.0f / s;
#pragma unroll
        for (int i = 0; i < 16; i++) row[lane + 32 * i] = v[i] * inv;
    }
    __syncthreads();

    // ---- O = P @ V, double-buffered V (V kt in buf[kt&1]: V0->kvB, V1->kvA) ----
    float oacc[4][4];
#pragma unroll
    for (int nt = 0; nt < 4; nt++)
#pragma unroll
        for (int r = 0; r < 4; r++) oacc[nt][r] = 0.f;

    const uint32_t* Pu = (const uint32_t*)Ssm;
    for (int kt = 0; kt < 8; kt++) {
        float* cur = (kt & 1) ? kvA : kvB;
        if (kt < 7) asm volatile("cp.async.wait_group 1;" ::: "memory");
        else        asm volatile("cp.async.wait_group 0;" ::: "memory");
        __syncthreads();

        const uint32_t* Vu = (const uint32_t*)cur;
#pragma unroll
        for (int ks = 0; ks < 8; ks++) {
            uint32_t pa[4];
            int rm = wq * 16 + g;
            int kc = kt * 64 + ks * 8;
            pa[0] = RND_TF32(Pu[rm * SSS + kc + tig]);
            pa[1] = RND_TF32(Pu[(rm + 8) * SSS + kc + tig]);
            pa[2] = RND_TF32(Pu[rm * SSS + kc + tig + 4]);
            pa[3] = RND_TF32(Pu[(rm + 8) * SSS + kc + tig + 4]);
#pragma unroll
            for (int nt = 0; nt < 4; nt++) {
                uint32_t bf[2];
                int n = wh * 32 + nt * 8 + g;
                bf[0] = RND_TF32(Vu[(ks * 8 + tig) * VST + n]);
                bf[1] = RND_TF32(Vu[(ks * 8 + tig + 4) * VST + n]);
                mma_tf32(oacc[nt], pa, bf);
            }
        }
        __syncthreads();
        if (kt + 2 < 8)
            issue_tile(cur, Vg + (size_t)(kt + 2) * 64 * H3, VST);
    }

#pragma unroll
    for (int nt = 0; nt < 4; nt++) {
        int col = h * DHh + wh * 32 + nt * 8 + 2 * tig;
        size_t row = (size_t)(b * Ss + qt + wq * 16 + g);
        *reinterpret_cast<float2*>(&g_ctx[row * Hh + col]) =
            make_float2(oacc[nt][0], oacc[nt][1]);
        *reinterpret_cast<float2*>(&g_ctx[(row + 8) * Hh + col]) =
            make_float2(oacc[nt][2], oacc[nt][3]);
    }
}

// ---------------- segment bookkeeping (deterministic) ----------------
__global__ void seg_prep_kernel(const int* __restrict__ tok) {
    int b = blockIdx.x, s = threadIdx.x;
    __shared__ int sc[Ss];
    __shared__ int cnt[Ss];
    int wid = tok[(b * Ss + s) * 2];
    int isnew = (s == 0) ? 1 : (wid != tok[(b * Ss + s - 1) * 2] ? 1 : 0);
    sc[s] = isnew; cnt[s] = 0; __syncthreads();
    for (int off = 1; off < Ss; off <<= 1) {
        int v = (s >= off) ? sc[s - off] : 0;
        __syncthreads();
        sc[s] += v;
        __syncthreads();
    }
    int gid = sc[s] - 1;
    if (tok[(b * Ss + s) * 2 + 1] != 0) atomicAdd(&cnt[gid], 1);
    if (isnew) g_seg_first[b * Ss + gid] = s;
    __syncthreads();
    g_seg_cnt[b * Ss + s] = cnt[s];
    if (s == Ss - 1) g_nseg[b] = gid + 1;
}

__global__ void seg_mean_kernel(const int* __restrict__ tok, float* __restrict__ out) {
    int g = blockIdx.x, b = blockIdx.y;
    int n = g_nseg[b];
    if (g >= n) return;
    int c = g_seg_cnt[b * Ss + g];
    if (c == 0) return;
    int start = g_seg_first[b * Ss + g];
    int end = (g + 1 < n) ? g_seg_first[b * Ss + g + 1] : Ss;
    __shared__ unsigned char mf[Ss];
    for (int s = threadIdx.x; s < Ss; s += 128)
        mf[s] = (tok[(b * Ss + s) * 2 + 1] != 0);
    __syncthreads();
    float inv = 1.0f / (float)c;
    for (int j = threadIdx.x; j < Hh; j += 128) {
        float sum = 0.f;
        for (int s = start; s < end; s++)
            if (mf[s]) sum += g_x[(size_t)(b * Ss + s) * Hh + j];
        out[(size_t)(b * Ss + g) * Hh + j] = sum * inv;
    }
}

// ---------------- launch ----------------
extern "C" void kernel_launch(void* const* d_in, const int* in_sizes, int n_in,
                              void* d_out, int out_size) {
    const int*   tok  = (const int*)  d_in[0];
    const float* emb  = (const float*)d_in[1];
    const float* pos  = (const float*)d_in[2];
    const float* lng  = (const float*)d_in[3];
    const float* lnb  = (const float*)d_in[4];
    const float* Wqkv = (const float*)d_in[5];
    const float* bqkv = (const float*)d_in[6];
    const float* Wo   = (const float*)d_in[7];
    const float* bo   = (const float*)d_in[8];
    const float* ln1g = (const float*)d_in[9];
    const float* ln1b = (const float*)d_in[10];
    const float* Wff1 = (const float*)d_in[11];
    const float* bff1 = (const float*)d_in[12];
    const float* Wff2 = (const float*)d_in[13];
    const float* bff2 = (const float*)d_in[14];
    const float* ln2g = (const float*)d_in[15];
    const float* ln2b = (const float*)d_in[16];
    float* out = (float*)d_out;

    void* p;
    cudaGetSymbolAddress(&p, g_x);   float* x   = (float*)p;
    cudaGetSymbolAddress(&p, g_tmp); float* tmp = (float*)p;
    cudaGetSymbolAddress(&p, g_ctx); float* ctx = (float*)p;

    cudaFuncSetAttribute(fused_attn_kernel,
                         cudaFuncAttributeMaxDynamicSharedMemorySize, ATTN_SMEM_BYTES);
    cudaFuncSetAttribute(gemm_tf32_kernel,
                         cudaFuncAttributeMaxDynamicSharedMemorySize, GEMM_SMEM_BYTES);

    cudaMemsetAsync(d_out, 0, (size_t)out_size * sizeof(float), 0);

    embed_ln_kernel<<<Tt, 256>>>(tok, emb, pos, lng, lnb);

    for (int l = 0; l < Ll; l++) {
        // QKV: [8192,768] @ [768,2304]
        launch_gemm(x, Wqkv + (size_t)l * Hh * H3, bqkv + l * H3, tmp, Tt, H3, Hh, 0);
        // fused attention (pipelined)
        fused_attn_kernel<<<dim3(8, Bb * NHh), 256, ATTN_SMEM_BYTES>>>(tmp);
        // Wo: [8192,768] @ [768,768]
        launch_gemm(ctx, Wo + (size_t)l * Hh * Hh, bo + l * Hh, tmp, Tt, Hh, Hh, 0);
        add_ln_kernel<<<Tt, 256>>>(x, tmp, ln1g + l * Hh, ln1b + l * Hh, x);
        // FF1: [8192,768] @ [768,3072] + GELU
        launch_gemm(x, Wff1 + (size_t)l * Hh * FFf, bff1 + l * FFf, tmp, Tt, FFf, Hh, 1);
        // FF2: [8192,3072] @ [3072,768]
        launch_gemm(tmp, Wff2 + (size_t)l * FFf * Hh, bff2 + l * Hh, ctx, Tt, Hh, FFf, 0);
        add_ln_kernel<<<Tt, 256>>>(x, ctx, ln2g + l * Hh, ln2b + l * Hh, x);
    }

    seg_prep_kernel<<<Bb, Ss>>>(tok);
    seg_mean_kernel<<<dim3(Ss, Bb), 128>>>(tok, out);
}

// round 11
// speedup vs baseline: 1.5648x; 1.3462x over previous
#include <cuda_runtime.h>
#include <cuda_fp16.h>
#include <math.h>
#include <stdint.h>

#define Bb   16
#define Ss   512
#define Hh   768
#define NHh  12
#define DHh  64
#define Ll   2
#define FFf  3072
#define Tt   (Bb*Ss)          // 8192 tokens
#define H3   (3*Hh)           // 2304

#define NSM       148
#define PERSIST   (2*NSM)

// ---------------- scratch (no allocations allowed) ----------------
__device__ float  g_x[Tt*Hh];                   // hidden state fp32
__device__ float  g_tmp[Tt*H3];                 // qkv / wo out (fp32)
__device__ float  g_ctx[Tt*Hh];                 // ff2 out (fp32)
__device__ __half g_xh[Tt*Hh];                  // fp16 copy of x
__device__ __half g_ctxh[Tt*Hh];                // fp16 attention output
__device__ __half g_ff1h[Tt*FFf];               // fp16 FF1 output (post-GELU)
// fp16 transposed weights, per layer: qkvT | woT | ff1T | ff2T  ([N][K])
#define WT_LAYER 7077888
#define WT_QKV   0
#define WT_WO    1769472
#define WT_FF1   2359296
#define WT_FF2   4718592
__device__ __half g_wh[2*WT_LAYER];             // 28.3 MB
__device__ int    g_seg_first[Bb*Ss];
__device__ int    g_seg_cnt[Bb*Ss];
__device__ int    g_nseg[Bb];

// ---------------- helpers ----------------
__device__ __forceinline__ float block_reduce_sum_256(float v, float* red) {
    int t = threadIdx.x;
    red[t] = v; __syncthreads();
#pragma unroll
    for (int o = 128; o > 0; o >>= 1) {
        if (t < o) red[t] += red[t + o];
        __syncthreads();
    }
    float r = red[0];
    __syncthreads();
    return r;
}

__device__ __forceinline__ void mma_tf32(float* c, const uint32_t* a, const uint32_t* b) {
    asm volatile(
        "mma.sync.aligned.m16n8k8.row.col.f32.tf32.tf32.f32 "
        "{%0,%1,%2,%3}, {%4,%5,%6,%7}, {%8,%9}, {%0,%1,%2,%3};"
        : "+f"(c[0]), "+f"(c[1]), "+f"(c[2]), "+f"(c[3])
        : "r"(a[0]), "r"(a[1]), "r"(a[2]), "r"(a[3]), "r"(b[0]), "r"(b[1]));
}

__device__ __forceinline__ void mma_f16(float* c, const uint32_t* a, const uint32_t* b) {
    asm volatile(
        "mma.sync.aligned.m16n8k16.row.col.f32.f16.f16.f32 "
        "{%0,%1,%2,%3}, {%4,%5,%6,%7}, {%8,%9}, {%0,%1,%2,%3};"
        : "+f"(c[0]), "+f"(c[1]), "+f"(c[2]), "+f"(c[3])
        : "r"(a[0]), "r"(a[1]), "r"(a[2]), "r"(a[3]), "r"(b[0]), "r"(b[1]));
}

__device__ __forceinline__ void cp_async16(void* smem_ptr, const void* gptr) {
    uint32_t s = (uint32_t)__cvta_generic_to_shared(smem_ptr);
    asm volatile("cp.async.cg.shared.global [%0], [%1], 16;" :: "r"(s), "l"(gptr));
}

#define RND_TF32(x) ((x) + 0x1000u)

// ---------------- weight transpose + fp16 cvt: dst[N][K] = h(src[K][N]^T) ------
__global__ void transpose_h_kernel(const float* __restrict__ src,
                                   __half* __restrict__ dst, int K, int N) {
    __shared__ float tile[32][33];
    int bx = blockIdx.x * 32;   // n
    int by = blockIdx.y * 32;   // k
    int tx = threadIdx.x, ty = threadIdx.y;   // 32 x 8
#pragma unroll
    for (int j = 0; j < 32; j += 8)
        tile[ty + j][tx] = src[(size_t)(by + ty + j) * N + bx + tx];
    __syncthreads();
#pragma unroll
    for (int j = 0; j < 32; j += 8)
        dst[(size_t)(bx + ty + j) * K + by + tx] = __float2half_rn(tile[tx][ty + j]);
}

// ---------------- embedding + LN (writes fp32 + fp16) ----------------
__global__ void embed_ln_kernel(const int* __restrict__ tok,
                                const float* __restrict__ emb,
                                const float* __restrict__ pos,
                                const float* __restrict__ g,
                                const float* __restrict__ bt) {
    int row = blockIdx.x;
    int s   = row & (Ss - 1);
    int id  = tok[row * 2 + 1];
    __shared__ float y[Hh];
    __shared__ float red[256];
    int t = threadIdx.x;
    float part = 0.f;
    for (int j = t; j < Hh; j += 256) {
        float v = emb[(size_t)id * Hh + j] + pos[s * Hh + j];
        y[j] = v; part += v;
    }
    float mean = block_reduce_sum_256(part, red) * (1.f / Hh);
    part = 0.f;
    for (int j = t; j < Hh; j += 256) { float d = y[j] - mean; part += d * d; }
    float var = block_reduce_sum_256(part, red) * (1.f / Hh);
    float inv = rsqrtf(var + 1e-12f);
    for (int j = t; j < Hh; j += 256) {
        float o = (y[j] - mean) * inv * g[j] + bt[j];
        g_x[(size_t)row * Hh + j]  = o;
        g_xh[(size_t)row * Hh + j] = __float2half_rn(o);
    }
}

// ---------------- residual add + LN (writes fp32 + fp16) ----------------
__global__ void add_ln_kernel(const float* __restrict__ x,
                              const float* __restrict__ tadd,
                              const float* __restrict__ g,
                              const float* __restrict__ bt,
                              float* __restrict__ out,
                              __half* __restrict__ outh) {
    int row = blockIdx.x;
    size_t base = (size_t)row * Hh;
    __shared__ float y[Hh];
    __shared__ float red[256];
    int t = threadIdx.x;
    float part = 0.f;
    for (int j = t; j < Hh; j += 256) {
        float v = x[base + j] + tadd[base + j];
        y[j] = v; part += v;
    }
    float mean = block_reduce_sum_256(part, red) * (1.f / Hh);
    part = 0.f;
    for (int j = t; j < Hh; j += 256) { float d = y[j] - mean; part += d * d; }
    float var = block_reduce_sum_256(part, red) * (1.f / Hh);
    float inv = rsqrtf(var + 1e-12f);
    for (int j = t; j < Hh; j += 256) {
        float o = (y[j] - mean) * inv * g[j] + bt[j];
        out[base + j]  = o;
        outh[base + j] = __float2half_rn(o);
    }
}

// ------- persistent FP16 tensor-core GEMM, 3-stage cp.async pipeline ---------
// C = A[M,K](fp16) @ WT[N,K](fp16)^T + bias. act=0: fp32 C; act=1: GELU + fp16 C.
// BM=BN=128, BK=32, 8 warps (2x4), warp tile 64x32 via m16n8k16.
// smem rows padded to 40 halves (20 words): (20g+tig) mod 32 hits all banks.
#define HAS     40
#define HA_SZ   (128 * HAS)                  // halves
#define HSTAGE  (2 * HA_SZ)                  // A + B halves = 10240
#define GEMM_SMEM_BYTES (3 * HSTAGE * 2)     // 61440 B

__global__ __launch_bounds__(256) void gemm_f16_kernel(const __half* __restrict__ A,
                                                       const __half* __restrict__ WT,
                                                       const float* __restrict__ bias,
                                                       void* __restrict__ Cout,
                                                       int M, int N, int K, int act,
                                                       int numTiles, int nTN) {
    extern __shared__ __half hsm[];
    int tid  = threadIdx.x;
    int lane = tid & 31;
    int warp = tid >> 5;
    int g    = lane >> 2, tig = lane & 3;
    int wm   = warp >> 2, wn = warp & 3;
    int nK   = K >> 5;

    for (int t = blockIdx.x; t < numTiles; t += gridDim.x) {
        int mBase = (t / nTN) * 128;
        int nBase = (t % nTN) * 128;

        float acc[4][4][4];
#pragma unroll
        for (int i = 0; i < 4; i++)
#pragma unroll
            for (int j = 0; j < 4; j++)
#pragma unroll
                for (int r = 0; r < 4; r++) acc[i][j][r] = 0.f;

        auto load_stage = [&](int stage, int k0) {
            __half* st = hsm + stage * HSTAGE;
            // A: 128 rows x 32 halves = 512 x 16B, 2 per thread
#pragma unroll
            for (int i = 0; i < 2; i++) {
                int idx = tid + i * 256;
                int r = idx >> 2, c = (idx & 3) << 3;
                cp_async16(&st[r * HAS + c], &A[(size_t)(mBase + r) * K + k0 + c]);
            }
            __half* bs = st + HA_SZ;
#pragma unroll
            for (int i = 0; i < 2; i++) {
                int idx = tid + i * 256;
                int r = idx >> 2, c = (idx & 3) << 3;
                cp_async16(&bs[r * HAS + c], &WT[(size_t)(nBase + r) * K + k0 + c]);
            }
            asm volatile("cp.async.commit_group;" ::: "memory");
        };

        load_stage(0, 0);
        load_stage(1, 32);

        int s_cur = 0, s_next = 2;
        for (int i = 0; i < nK; i++) {
            if (i + 2 < nK) {
                load_stage(s_next, (i + 2) << 5);
                asm volatile("cp.async.wait_group 2;" ::: "memory");
            } else if (i + 1 < nK) {
                asm volatile("cp.async.wait_group 1;" ::: "memory");
            } else {
                asm volatile("cp.async.wait_group 0;" ::: "memory");
            }
            __syncthreads();

            const uint32_t* As32 = (const uint32_t*)(hsm + s_cur * HSTAGE);
            const uint32_t* Bs32 = As32 + HA_SZ / 2;
#pragma unroll
            for (int ks = 0; ks < 2; ks++) {          // two K=16 steps per BK=32
                uint32_t a[4][4], b[4][2];
#pragma unroll
                for (int mi = 0; mi < 4; mi++) {
                    int rm = wm * 64 + mi * 16 + g;
                    a[mi][0] = As32[rm * 20 + ks * 8 + tig];
                    a[mi][1] = As32[(rm + 8) * 20 + ks * 8 + tig];
                    a[mi][2] = As32[rm * 20 + ks * 8 + tig + 4];
                    a[mi][3] = As32[(rm + 8) * 20 + ks * 8 + tig + 4];
                }
#pragma unroll
                for (int ni = 0; ni < 4; ni++) {
                    int cn = wn * 32 + ni * 8 + g;
                    b[ni][0] = Bs32[cn * 20 + ks * 8 + tig];
                    b[ni][1] = Bs32[cn * 20 + ks * 8 + tig + 4];
                }
#pragma unroll
                for (int mi = 0; mi < 4; mi++)
#pragma unroll
                    for (int ni = 0; ni < 4; ni++)
                        mma_f16(acc[mi][ni], a[mi], b[ni]);
            }
            __syncthreads();
            s_cur = (s_cur == 2) ? 0 : s_cur + 1;
            s_next = (s_next == 2) ? 0 : s_next + 1;
        }

        // epilogue
#pragma unroll
        for (int mi = 0; mi < 4; mi++) {
            int rm0 = mBase + wm * 64 + mi * 16 + g;
#pragma unroll
            for (int ni = 0; ni < 4; ni++) {
                int cn = nBase + wn * 32 + ni * 8 + 2 * tig;
                float b0 = bias[cn], b1 = bias[cn + 1];
                float v0 = acc[mi][ni][0] + b0;
                float v1 = acc[mi][ni][1] + b1;
                float v2 = acc[mi][ni][2] + b0;
                float v3 = acc[mi][ni][3] + b1;
                if (act) {   // GELU + fp16 store
                    v0 = 0.5f * v0 * (1.0f + erff(v0 * 0.70710678118654752f));
                    v1 = 0.5f * v1 * (1.0f + erff(v1 * 0.70710678118654752f));
                    v2 = 0.5f * v2 * (1.0f + erff(v2 * 0.70710678118654752f));
                    v3 = 0.5f * v3 * (1.0f + erff(v3 * 0.70710678118654752f));
                    __half2* Ch = (__half2*)Cout;
                    Ch[((size_t)rm0 * N + cn) >> 1]       = __floats2half2_rn(v0, v1);
                    Ch[((size_t)(rm0 + 8) * N + cn) >> 1] = __floats2half2_rn(v2, v3);
                } else {     // fp32 store
                    float* Cf = (float*)Cout;
                    *reinterpret_cast<float2*>(&Cf[(size_t)rm0 * N + cn])       = make_float2(v0, v1);
                    *reinterpret_cast<float2*>(&Cf[(size_t)(rm0 + 8) * N + cn]) = make_float2(v2, v3);
                }
            }
        }
    }
}

static inline void launch_gemm(const __half* A, const __half* WT, const float* bias,
                               void* C, int M, int N, int K, int act) {
    int nTM = M / 128, nTN = N / 128;
    int tiles = nTM * nTN;
    int grid = tiles < PERSIST ? tiles : PERSIST;
    gemm_f16_kernel<<<grid, 256, GEMM_SMEM_BYTES>>>(A, WT, bias, C, M, N, K, act,
                                                    tiles, nTN);
}

// -------- fused attention (tf32 internals, fp16 output) ------------------------
#define SSS   516
#define KST   68
#define VST   72
#define ATTN_SMEM_BYTES ((64*SSS + 2*64*VST) * 4)

__global__ __launch_bounds__(256) void fused_attn_kernel(const float* __restrict__ qkv) {
    extern __shared__ float smem[];
    float* Ssm = smem;
    float* kvA = smem + 64 * SSS;
    float* kvB = kvA + 64 * VST;

    int bh = blockIdx.y; int b = bh / NHh, h = bh - b * NHh;
    int qt = blockIdx.x * 64;
    int tid = threadIdx.x, lane = tid & 31, warp = tid >> 5;
    int g = lane >> 2, tig = lane & 3;
    int wq = warp >> 1, wh = warp & 1;

    const float* Qg = &qkv[(size_t)(b * Ss + qt) * H3 + h * DHh];
    const float* Kg = &qkv[(size_t)(b * Ss) * H3 + Hh + h * DHh];
    const float* Vg = &qkv[(size_t)(b * Ss) * H3 + 2 * Hh + h * DHh];

    auto issue_tile = [&](float* buf, const float* src, int su32) {
#pragma unroll
        for (int i = 0; i < 4; i++) {
            int idx = tid + i * 256;
            int r = idx >> 4, c4 = (idx & 15) << 2;
            cp_async16(&buf[r * su32 + c4], &src[(size_t)r * H3 + c4]);
        }
        asm volatile("cp.async.commit_group;" ::: "memory");
    };

    issue_tile(kvA, Qg, KST);
    issue_tile(kvB, Kg, KST);
    asm volatile("cp.async.wait_group 0;" ::: "memory");
    __syncthreads();

    uint32_t qa[8][4];
    {
        int rm = wq * 16 + g;
#pragma unroll
        for (int ks = 0; ks < 8; ks++) {
            qa[ks][0] = __float_as_uint(kvA[rm * KST + ks * 8 + tig] * 0.125f) + 0x1000u;
            qa[ks][1] = __float_as_uint(kvA[(rm + 8) * KST + ks * 8 + tig] * 0.125f) + 0x1000u;
            qa[ks][2] = __float_as_uint(kvA[rm * KST + ks * 8 + tig + 4] * 0.125f) + 0x1000u;
            qa[ks][3] = __float_as_uint(kvA[(rm + 8) * KST + ks * 8 + tig + 4] * 0.125f) + 0x1000u;
        }
    }
    __syncthreads();

    for (int kt = 0; kt < 8; kt++) {
        float* cur = (kt & 1) ? kvA : kvB;
        float* nxt = (kt & 1) ? kvB : kvA;
        if (kt < 7) {
            issue_tile(nxt, Kg + (size_t)(kt + 1) * 64 * H3, KST);
            asm volatile("cp.async.wait_group 1;" ::: "memory");
        } else {
            asm volatile("cp.async.wait_group 0;" ::: "memory");
        }
        __syncthreads();

        const uint32_t* Ku = (const uint32_t*)cur;
        float acc[4][4];
#pragma unroll
        for (int nt = 0; nt < 4; nt++)
#pragma unroll
            for (int r = 0; r < 4; r++) acc[nt][r] = 0.f;
#pragma unroll
        for (int ks = 0; ks < 8; ks++) {
            uint32_t bf[4][2];
#pragma unroll
            for (int nt = 0; nt < 4; nt++) {
                int n = wh * 32 + nt * 8 + g;
                bf[nt][0] = RND_TF32(Ku[n * KST + ks * 8 + tig]);
                bf[nt][1] = RND_TF32(Ku[n * KST + ks * 8 + tig + 4]);
            }
#pragma unroll
            for (int nt = 0; nt < 4; nt++)
                mma_tf32(acc[nt], qa[ks], bf[nt]);
        }
#pragma unroll
        for (int nt = 0; nt < 4; nt++) {
            int col = kt * 64 + wh * 32 + nt * 8 + 2 * tig;
            int row = wq * 16 + g;
            Ssm[row * SSS + col]           = acc[nt][0];
            Ssm[row * SSS + col + 1]       = acc[nt][1];
            Ssm[(row + 8) * SSS + col]     = acc[nt][2];
            Ssm[(row + 8) * SSS + col + 1] = acc[nt][3];
        }
        __syncthreads();
    }

    issue_tile(kvB, Vg, VST);
    issue_tile(kvA, Vg + (size_t)64 * H3, VST);

    for (int r = warp * 8; r < warp * 8 + 8; r++) {
        float* row = &Ssm[r * SSS];
        float v[16];
        float m = -1e30f;
#pragma unroll
        for (int i = 0; i < 16; i++) { v[i] = row[lane + 32 * i]; m = fmaxf(m, v[i]); }
#pragma unroll
        for (int o = 16; o > 0; o >>= 1) m = fmaxf(m, __shfl_xor_sync(0xffffffffu, m, o));
        float s = 0.f;
#pragma unroll
        for (int i = 0; i < 16; i++) { v[i] = __expf(v[i] - m); s += v[i]; }
#pragma unroll
        for (int o = 16; o > 0; o >>= 1) s += __shfl_xor_sync(0xffffffffu, s, o);
        float inv = 1.0f / s;
#pragma unroll
        for (int i = 0; i < 16; i++) row[lane + 32 * i] = v[i] * inv;
    }
    __syncthreads();

    float oacc[4][4];
#pragma unroll
    for (int nt = 0; nt < 4; nt++)
#pragma unroll
        for (int r = 0; r < 4; r++) oacc[nt][r] = 0.f;

    const uint32_t* Pu = (const uint32_t*)Ssm;
    for (int kt = 0; kt < 8; kt++) {
        float* cur = (kt & 1) ? kvA : kvB;
        if (kt < 7) asm volatile("cp.async.wait_group 1;" ::: "memory");
        else        asm volatile("cp.async.wait_group 0;" ::: "memory");
        __syncthreads();

        const uint32_t* Vu = (const uint32_t*)cur;
#pragma unroll
        for (int ks = 0; ks < 8; ks++) {
            uint32_t pa[4];
            int rm = wq * 16 + g;
            int kc = kt * 64 + ks * 8;
            pa[0] = RND_TF32(Pu[rm * SSS + kc + tig]);
            pa[1] = RND_TF32(Pu[(rm + 8) * SSS + kc + tig]);
            pa[2] = RND_TF32(Pu[rm * SSS + kc + tig + 4]);
            pa[3] = RND_TF32(Pu[(rm + 8) * SSS + kc + tig + 4]);
#pragma unroll
            for (int nt = 0; nt < 4; nt++) {
                uint32_t bf[2];
                int n = wh * 32 + nt * 8 + g;
                bf[0] = RND_TF32(Vu[(ks * 8 + tig) * VST + n]);
                bf[1] = RND_TF32(Vu[(ks * 8 + tig + 4) * VST + n]);
                mma_tf32(oacc[nt], pa, bf);
            }
        }
        __syncthreads();
        if (kt + 2 < 8)
            issue_tile(cur, Vg + (size_t)(kt + 2) * 64 * H3, VST);
    }

    // fp16 output (Wo GEMM consumes it)
#pragma unroll
    for (int nt = 0; nt < 4; nt++) {
        int col = h * DHh + wh * 32 + nt * 8 + 2 * tig;
        size_t row = (size_t)(b * Ss + qt + wq * 16 + g);
        g_ctxh[row * Hh + col]     = __float2half_rn(oacc[nt][0]);
        g_ctxh[row * Hh + col + 1] = __float2half_rn(oacc[nt][1]);
        g_ctxh[(row + 8) * Hh + col]     = __float2half_rn(oacc[nt][2]);
        g_ctxh[(row + 8) * Hh + col + 1] = __float2half_rn(oacc[nt][3]);
    }
}

// ---------------- segment bookkeeping (deterministic) ----------------
__global__ void seg_prep_kernel(const int* __restrict__ tok) {
    int b = blockIdx.x, s = threadIdx.x;
    __shared__ int sc[Ss];
    __shared__ int cnt[Ss];
    int wid = tok[(b * Ss + s) * 2];
    int isnew = (s == 0) ? 1 : (wid != tok[(b * Ss + s - 1) * 2] ? 1 : 0);
    sc[s] = isnew; cnt[s] = 0; __syncthreads();
    for (int off = 1; off < Ss; off <<= 1) {
        int v = (s >= off) ? sc[s - off] : 0;
        __syncthreads();
        sc[s] += v;
        __syncthreads();
    }
    int gid = sc[s] - 1;
    if (tok[(b * Ss + s) * 2 + 1] != 0) atomicAdd(&cnt[gid], 1);
    if (isnew) g_seg_first[b * Ss + gid] = s;
    __syncthreads();
    g_seg_cnt[b * Ss + s] = cnt[s];
    if (s == Ss - 1) g_nseg[b] = gid + 1;
}

__global__ void seg_mean_kernel(const int* __restrict__ tok, float* __restrict__ out) {
    int g = blockIdx.x, b = blockIdx.y;
    int n = g_nseg[b];
    if (g >= n) return;
    int c = g_seg_cnt[b * Ss + g];
    if (c == 0) return;
    int start = g_seg_first[b * Ss + g];
    int end = (g + 1 < n) ? g_seg_first[b * Ss + g + 1] : Ss;
    __shared__ unsigned char mf[Ss];
    for (int s = threadIdx.x; s < Ss; s += 128)
        mf[s] = (tok[(b * Ss + s) * 2 + 1] != 0);
    __syncthreads();
    float inv = 1.0f / (float)c;
    for (int j = threadIdx.x; j < Hh; j += 128) {
        float sum = 0.f;
        for (int s = start; s < end; s++)
            if (mf[s]) sum += g_x[(size_t)(b * Ss + s) * Hh + j];
        out[(size_t)(b * Ss + g) * Hh + j] = sum * inv;
    }
}

// ---------------- launch ----------------
extern "C" void kernel_launch(void* const* d_in, const int* in_sizes, int n_in,
                              void* d_out, int out_size) {
    const int*   tok  = (const int*)  d_in[0];
    const float* emb  = (const float*)d_in[1];
    const float* pos  = (const float*)d_in[2];
    const float* lng  = (const float*)d_in[3];
    const float* lnb  = (const float*)d_in[4];
    const float* Wqkv = (const float*)d_in[5];
    const float* bqkv = (const float*)d_in[6];
    const float* Wo   = (const float*)d_in[7];
    const float* bo   = (const float*)d_in[8];
    const float* ln1g = (const float*)d_in[9];
    const float* ln1b = (const float*)d_in[10];
    const float* Wff1 = (const float*)d_in[11];
    const float* bff1 = (const float*)d_in[12];
    const float* Wff2 = (const float*)d_in[13];
    const float* bff2 = (const float*)d_in[14];
    const float* ln2g = (const float*)d_in[15];
    const float* ln2b = (const float*)d_in[16];
    float* out = (float*)d_out;

    void* p;
    cudaGetSymbolAddress(&p, g_x);     float*  x    = (float*)p;
    cudaGetSymbolAddress(&p, g_tmp);   float*  tmp  = (float*)p;
    cudaGetSymbolAddress(&p, g_ctx);   float*  ctx  = (float*)p;
    cudaGetSymbolAddress(&p, g_xh);    __half* xh   = (__half*)p;
    cudaGetSymbolAddress(&p, g_ctxh);  __half* ctxh = (__half*)p;
    cudaGetSymbolAddress(&p, g_ff1h);  __half* ff1h = (__half*)p;
    cudaGetSymbolAddress(&p, g_wh);    __half* wh   = (__half*)p;

    cudaFuncSetAttribute(fused_attn_kernel,
                         cudaFuncAttributeMaxDynamicSharedMemorySize, ATTN_SMEM_BYTES);
    cudaFuncSetAttribute(gemm_f16_kernel,
                         cudaFuncAttributeMaxDynamicSharedMemorySize, GEMM_SMEM_BYTES);

    cudaMemsetAsync(d_out, 0, (size_t)out_size * sizeof(float), 0);

    // per-launch weight transpose + fp16 convert ([K][N] -> [N][K])
    for (int l = 0; l < Ll; l++) {
        __half* wl = wh + (size_t)l * WT_LAYER;
        transpose_h_kernel<<<dim3(H3 / 32, Hh / 32), dim3(32, 8)>>>(
            Wqkv + (size_t)l * Hh * H3, wl + WT_QKV, Hh, H3);
        transpose_h_kernel<<<dim3(Hh / 32, Hh / 32), dim3(32, 8)>>>(
            Wo + (size_t)l * Hh * Hh, wl + WT_WO, Hh, Hh);
        transpose_h_kernel<<<dim3(FFf / 32, Hh / 32), dim3(32, 8)>>>(
            Wff1 + (size_t)l * Hh * FFf, wl + WT_FF1, Hh, FFf);
        transpose_h_kernel<<<dim3(Hh / 32, FFf / 32), dim3(32, 8)>>>(
            Wff2 + (size_t)l * FFf * Hh, wl + WT_FF2, FFf, Hh);
    }

    embed_ln_kernel<<<Tt, 256>>>(tok, emb, pos, lng, lnb);

    for (int l = 0; l < Ll; l++) {
        const __half* wl = wh + (size_t)l * WT_LAYER;
        // QKV: [8192,768] @ [768,2304] -> fp32 tmp
        launch_gemm(xh, wl + WT_QKV, bqkv + l * H3, tmp, Tt, H3, Hh, 0);
        // fused attention -> fp16 ctxh
        fused_attn_kernel<<<dim3(8, Bb * NHh), 256, ATTN_SMEM_BYTES>>>(tmp);
        // Wo: [8192,768] @ [768,768] -> fp32 tmp
        launch_gemm(ctxh, wl + WT_WO, bo + l * Hh, tmp, Tt, Hh, Hh, 0);
        add_ln_kernel<<<Tt, 256>>>(x, tmp, ln1g + l * Hh, ln1b + l * Hh, x, xh);
        // FF1: [8192,768] @ [768,3072] + GELU -> fp16 ff1h
        launch_gemm(xh, wl + WT_FF1, bff1 + l * FFf, ff1h, Tt, FFf, Hh, 1);
        // FF2: [8192,3072] @ [3072,768] -> fp32 ctx
        launch_gemm(ff1h, wl + WT_FF2, bff2 + l * Hh, ctx, Tt, Hh, FFf, 0);
        add_ln_kernel<<<Tt, 256>>>(x, ctx, ln2g + l * Hh, ln2b + l * Hh, x, xh);
    }

    seg_prep_kernel<<<Bb, Ss>>>(tok);
    seg_mean_kernel<<<dim3(Ss, Bb), 128>>>(tok, out);
}

// round 12
// speedup vs baseline: 1.6871x; 1.0782x over previous
#include <cuda_runtime.h>
#include <cuda_fp16.h>
#include <math.h>
#include <stdint.h>

#define Bb   16
#define Ss   512
#define Hh   768
#define NHh  12
#define DHh  64
#define Ll   2
#define FFf  3072
#define Tt   (Bb*Ss)          // 8192 tokens
#define H3   (3*Hh)           // 2304

#define NSM       148
#define PERSIST   (2*NSM)

// ---------------- scratch (no allocations allowed) ----------------
__device__ float  g_x[Tt*Hh];                   // hidden state fp32
__device__ float  g_tmp[Tt*Hh];                 // wo out (fp32)
__device__ float  g_ctx[Tt*Hh];                 // ff2 out (fp32)
__device__ __half g_qkvh[Tt*H3];                // fp16 qkv (37.7 MB)
__device__ __half g_xh[Tt*Hh];                  // fp16 copy of x
__device__ __half g_ctxh[Tt*Hh];                // fp16 attention output
__device__ __half g_ff1h[Tt*FFf];               // fp16 FF1 output (post-GELU)
// fp16 transposed weights, per layer: qkv | wo | ff1 | ff2  ([N][K])
#define WT_LAYER 7077888
#define WT_QKV   0
#define WT_WO    1769472
#define WT_FF1   2359296
#define WT_FF2   4718592
__device__ __half g_wh[2*WT_LAYER];             // 28.3 MB
__device__ int    g_seg_first[Bb*Ss];
__device__ int    g_seg_cnt[Bb*Ss];
__device__ int    g_nseg[Bb];

// ---------------- helpers ----------------
__device__ __forceinline__ float block_reduce_sum_256(float v, float* red) {
    int t = threadIdx.x;
    red[t] = v; __syncthreads();
#pragma unroll
    for (int o = 128; o > 0; o >>= 1) {
        if (t < o) red[t] += red[t + o];
        __syncthreads();
    }
    float r = red[0];
    __syncthreads();
    return r;
}

__device__ __forceinline__ void mma_f16(float* c, const uint32_t* a, const uint32_t* b) {
    asm volatile(
        "mma.sync.aligned.m16n8k16.row.col.f32.f16.f16.f32 "
        "{%0,%1,%2,%3}, {%4,%5,%6,%7}, {%8,%9}, {%0,%1,%2,%3};"
        : "+f"(c[0]), "+f"(c[1]), "+f"(c[2]), "+f"(c[3])
        : "r"(a[0]), "r"(a[1]), "r"(a[2]), "r"(a[3]), "r"(b[0]), "r"(b[1]));
}

__device__ __forceinline__ void ldmatrix_x2_trans(uint32_t& d0, uint32_t& d1, uint32_t addr) {
    asm volatile("ldmatrix.sync.aligned.m8n8.x2.trans.shared.b16 {%0,%1}, [%2];"
                 : "=r"(d0), "=r"(d1) : "r"(addr));
}

__device__ __forceinline__ void cp_async16(void* smem_ptr, const void* gptr) {
    uint32_t s = (uint32_t)__cvta_generic_to_shared(smem_ptr);
    asm volatile("cp.async.cg.shared.global [%0], [%1], 16;" :: "r"(s), "l"(gptr));
}

// ---------------- weight transpose + fp16 cvt: dst[N][K] = h(src[K][N]^T) ------
__global__ void transpose_h_kernel(const float* __restrict__ src,
                                   __half* __restrict__ dst, int K, int N) {
    __shared__ float tile[32][33];
    int bx = blockIdx.x * 32;   // n
    int by = blockIdx.y * 32;   // k
    int tx = threadIdx.x, ty = threadIdx.y;   // 32 x 8
#pragma unroll
    for (int j = 0; j < 32; j += 8)
        tile[ty + j][tx] = src[(size_t)(by + ty + j) * N + bx + tx];
    __syncthreads();
#pragma unroll
    for (int j = 0; j < 32; j += 8)
        dst[(size_t)(bx + ty + j) * K + by + tx] = __float2half_rn(tile[tx][ty + j]);
}

// ---------------- embedding + LN (writes fp32 + fp16) ----------------
__global__ void embed_ln_kernel(const int* __restrict__ tok,
                                const float* __restrict__ emb,
                                const float* __restrict__ pos,
                                const float* __restrict__ g,
                                const float* __restrict__ bt) {
    int row = blockIdx.x;
    int s   = row & (Ss - 1);
    int id  = tok[row * 2 + 1];
    __shared__ float y[Hh];
    __shared__ float red[256];
    int t = threadIdx.x;
    float part = 0.f;
    for (int j = t; j < Hh; j += 256) {
        float v = emb[(size_t)id * Hh + j] + pos[s * Hh + j];
        y[j] = v; part += v;
    }
    float mean = block_reduce_sum_256(part, red) * (1.f / Hh);
    part = 0.f;
    for (int j = t; j < Hh; j += 256) { float d = y[j] - mean; part += d * d; }
    float var = block_reduce_sum_256(part, red) * (1.f / Hh);
    float inv = rsqrtf(var + 1e-12f);
    for (int j = t; j < Hh; j += 256) {
        float o = (y[j] - mean) * inv * g[j] + bt[j];
        g_x[(size_t)row * Hh + j]  = o;
        g_xh[(size_t)row * Hh + j] = __float2half_rn(o);
    }
}

// ---------------- residual add + LN (writes fp32 + fp16) ----------------
__global__ void add_ln_kernel(const float* __restrict__ x,
                              const float* __restrict__ tadd,
                              const float* __restrict__ g,
                              const float* __restrict__ bt,
                              float* __restrict__ out,
                              __half* __restrict__ outh) {
    int row = blockIdx.x;
    size_t base = (size_t)row * Hh;
    __shared__ float y[Hh];
    __shared__ float red[256];
    int t = threadIdx.x;
    float part = 0.f;
    for (int j = t; j < Hh; j += 256) {
        float v = x[base + j] + tadd[base + j];
        y[j] = v; part += v;
    }
    float mean = block_reduce_sum_256(part, red) * (1.f / Hh);
    part = 0.f;
    for (int j = t; j < Hh; j += 256) { float d = y[j] - mean; part += d * d; }
    float var = block_reduce_sum_256(part, red) * (1.f / Hh);
    float inv = rsqrtf(var + 1e-12f);
    for (int j = t; j < Hh; j += 256) {
        float o = (y[j] - mean) * inv * g[j] + bt[j];
        out[base + j]  = o;
        outh[base + j] = __float2half_rn(o);
    }
}

// ------- persistent FP16 tensor-core GEMM, 3-stage cp.async pipeline ---------
// C = A[M,K](fp16) @ WT[N,K](fp16)^T + bias.
// act=0: fp32 C;  act=1: GELU + fp16 C;  act=2: fp16 C (no activation).
#define HAS     40
#define HA_SZ   (128 * HAS)
#define HSTAGE  (2 * HA_SZ)
#define GEMM_SMEM_BYTES (3 * HSTAGE * 2)     // 61440 B

__global__ __launch_bounds__(256) void gemm_f16_kernel(const __half* __restrict__ A,
                                                       const __half* __restrict__ WT,
                                                       const float* __restrict__ bias,
                                                       void* __restrict__ Cout,
                                                       int M, int N, int K, int act,
                                                       int numTiles, int nTN) {
    extern __shared__ __half hsm[];
    int tid  = threadIdx.x;
    int lane = tid & 31;
    int warp = tid >> 5;
    int g    = lane >> 2, tig = lane & 3;
    int wm   = warp >> 2, wn = warp & 3;
    int nK   = K >> 5;

    for (int t = blockIdx.x; t < numTiles; t += gridDim.x) {
        int mBase = (t / nTN) * 128;
        int nBase = (t % nTN) * 128;

        float acc[4][4][4];
#pragma unroll
        for (int i = 0; i < 4; i++)
#pragma unroll
            for (int j = 0; j < 4; j++)
#pragma unroll
                for (int r = 0; r < 4; r++) acc[i][j][r] = 0.f;

        auto load_stage = [&](int stage, int k0) {
            __half* st = hsm + stage * HSTAGE;
#pragma unroll
            for (int i = 0; i < 2; i++) {
                int idx = tid + i * 256;
                int r = idx >> 2, c = (idx & 3) << 3;
                cp_async16(&st[r * HAS + c], &A[(size_t)(mBase + r) * K + k0 + c]);
            }
            __half* bs = st + HA_SZ;
#pragma unroll
            for (int i = 0; i < 2; i++) {
                int idx = tid + i * 256;
                int r = idx >> 2, c = (idx & 3) << 3;
                cp_async16(&bs[r * HAS + c], &WT[(size_t)(nBase + r) * K + k0 + c]);
            }
            asm volatile("cp.async.commit_group;" ::: "memory");
        };

        load_stage(0, 0);
        load_stage(1, 32);

        int s_cur = 0, s_next = 2;
        for (int i = 0; i < nK; i++) {
            if (i + 2 < nK) {
                load_stage(s_next, (i + 2) << 5);
                asm volatile("cp.async.wait_group 2;" ::: "memory");
            } else if (i + 1 < nK) {
                asm volatile("cp.async.wait_group 1;" ::: "memory");
            } else {
                asm volatile("cp.async.wait_group 0;" ::: "memory");
            }
            __syncthreads();

            const uint32_t* As32 = (const uint32_t*)(hsm + s_cur * HSTAGE);
            const uint32_t* Bs32 = As32 + HA_SZ / 2;
#pragma unroll
            for (int ks = 0; ks < 2; ks++) {
                uint32_t a[4][4], b[4][2];
#pragma unroll
                for (int mi = 0; mi < 4; mi++) {
                    int rm = wm * 64 + mi * 16 + g;
                    a[mi][0] = As32[rm * 20 + ks * 8 + tig];
                    a[mi][1] = As32[(rm + 8) * 20 + ks * 8 + tig];
                    a[mi][2] = As32[rm * 20 + ks * 8 + tig + 4];
                    a[mi][3] = As32[(rm + 8) * 20 + ks * 8 + tig + 4];
                }
#pragma unroll
                for (int ni = 0; ni < 4; ni++) {
                    int cn = wn * 32 + ni * 8 + g;
                    b[ni][0] = Bs32[cn * 20 + ks * 8 + tig];
                    b[ni][1] = Bs32[cn * 20 + ks * 8 + tig + 4];
                }
#pragma unroll
                for (int mi = 0; mi < 4; mi++)
#pragma unroll
                    for (int ni = 0; ni < 4; ni++)
                        mma_f16(acc[mi][ni], a[mi], b[ni]);
            }
            __syncthreads();
            s_cur = (s_cur == 2) ? 0 : s_cur + 1;
            s_next = (s_next == 2) ? 0 : s_next + 1;
        }

        // epilogue
#pragma unroll
        for (int mi = 0; mi < 4; mi++) {
            int rm0 = mBase + wm * 64 + mi * 16 + g;
#pragma unroll
            for (int ni = 0; ni < 4; ni++) {
                int cn = nBase + wn * 32 + ni * 8 + 2 * tig;
                float b0 = bias[cn], b1 = bias[cn + 1];
                float v0 = acc[mi][ni][0] + b0;
                float v1 = acc[mi][ni][1] + b1;
                float v2 = acc[mi][ni][2] + b0;
                float v3 = acc[mi][ni][3] + b1;
                if (act == 1) {
                    v0 = 0.5f * v0 * (1.0f + erff(v0 * 0.70710678118654752f));
                    v1 = 0.5f * v1 * (1.0f + erff(v1 * 0.70710678118654752f));
                    v2 = 0.5f * v2 * (1.0f + erff(v2 * 0.70710678118654752f));
                    v3 = 0.5f * v3 * (1.0f + erff(v3 * 0.70710678118654752f));
                }
                if (act) {   // fp16 store
                    __half2* Ch = (__half2*)Cout;
                    Ch[((size_t)rm0 * N + cn) >> 1]       = __floats2half2_rn(v0, v1);
                    Ch[((size_t)(rm0 + 8) * N + cn) >> 1] = __floats2half2_rn(v2, v3);
                } else {     // fp32 store
                    float* Cf = (float*)Cout;
                    *reinterpret_cast<float2*>(&Cf[(size_t)rm0 * N + cn])       = make_float2(v0, v1);
                    *reinterpret_cast<float2*>(&Cf[(size_t)(rm0 + 8) * N + cn]) = make_float2(v2, v3);
                }
            }
        }
    }
}

static inline void launch_gemm(const __half* A, const __half* WT, const float* bias,
                               void* C, int M, int N, int K, int act) {
    int nTM = M / 128, nTN = N / 128;
    int tiles = nTM * nTN;
    int grid = tiles < PERSIST ? tiles : PERSIST;
    gemm_f16_kernel<<<grid, 256, GEMM_SMEM_BYTES>>>(A, WT, bias, C, M, N, K, act,
                                                    tiles, nTN);
}

// -------- fused attention, full fp16 mma ---------------------------------------
// S fp32 in smem (softmax), P re-stored fp16, Q/K/V fp16 tiles via cp.async,
// V B-fragments via ldmatrix.x2.trans.
#define SSS   516                              // fp32 words per S row
#define QSTH  72                               // halves per Q/K/V tile row (36 words)
#define PSTH  520                              // halves per P row (260 words)
#define SMEM_S_BYTES   (64 * SSS * 4)          // 132096
#define SMEM_P_BYTES   (64 * PSTH * 2)         // 66560
#define SMEM_TILE_B    (64 * QSTH * 2)         // 9216
#define ATTN_SMEM_BYTES (SMEM_S_BYTES + SMEM_P_BYTES + 2 * SMEM_TILE_B)  // 217088

__global__ __launch_bounds__(256) void fused_attn_kernel(const __half* __restrict__ qkv) {
    extern __shared__ char asm_raw[];
    float*  Ssm  = (float*)asm_raw;                              // 64 x 516 fp32
    __half* Psm  = (__half*)(asm_raw + SMEM_S_BYTES);            // 64 x 520 fp16
    __half* kvA  = (__half*)(asm_raw + SMEM_S_BYTES + SMEM_P_BYTES);
    __half* kvB  = kvA + 64 * QSTH;

    int bh = blockIdx.y; int b = bh / NHh, h = bh - b * NHh;
    int qt = blockIdx.x * 64;
    int tid = threadIdx.x, lane = tid & 31, warp = tid >> 5;
    int g = lane >> 2, tig = lane & 3;
    int wq = warp >> 1, wh = warp & 1;

    const __half* Qg = &qkv[(size_t)(b * Ss + qt) * H3 + h * DHh];
    const __half* Kg = &qkv[(size_t)(b * Ss) * H3 + Hh + h * DHh];
    const __half* Vg = &qkv[(size_t)(b * Ss) * H3 + 2 * Hh + h * DHh];

    // 64 rows x 64 halves = 512 x 16B chunks, 2 per thread
    auto issue_tile = [&](__half* buf, const __half* src) {
#pragma unroll
        for (int i = 0; i < 2; i++) {
            int idx = tid + i * 256;
            int r = idx >> 3, c = (idx & 7) << 3;
            cp_async16(&buf[r * QSTH + c], &src[(size_t)r * H3 + c]);
        }
        asm volatile("cp.async.commit_group;" ::: "memory");
    };

    // prologue: Q -> kvA, K0 -> kvB
    issue_tile(kvA, Qg);
    issue_tile(kvB, Kg);
    asm volatile("cp.async.wait_group 0;" ::: "memory");
    __syncthreads();

    // extract Q A-fragments (m16n8k16): qa[ks][0..3], ks = 4 k16 steps
    uint32_t qa[4][4];
    {
        const uint32_t* Qw = (const uint32_t*)kvA;
        int rm = wq * 16 + g;
#pragma unroll
        for (int ks = 0; ks < 4; ks++) {
            qa[ks][0] = Qw[rm * 36 + ks * 8 + tig];
            qa[ks][1] = Qw[(rm + 8) * 36 + ks * 8 + tig];
            qa[ks][2] = Qw[rm * 36 + ks * 8 + tig + 4];
            qa[ks][3] = Qw[(rm + 8) * 36 + ks * 8 + tig + 4];
        }
    }
    __syncthreads();   // Q reads done before K1 overwrites kvA

    // ---- S = Q @ K^T * 0.125, double-buffered K ----
    for (int kt = 0; kt < 8; kt++) {
        __half* cur = (kt & 1) ? kvA : kvB;
        __half* nxt = (kt & 1) ? kvB : kvA;
        if (kt < 7) {
            issue_tile(nxt, Kg + (size_t)(kt + 1) * 64 * H3);
            asm volatile("cp.async.wait_group 1;" ::: "memory");
        } else {
            asm volatile("cp.async.wait_group 0;" ::: "memory");
        }
        __syncthreads();

        const uint32_t* Kw = (const uint32_t*)cur;
        float acc[4][4];
#pragma unroll
        for (int nt = 0; nt < 4; nt++)
#pragma unroll
            for (int r = 0; r < 4; r++) acc[nt][r] = 0.f;
#pragma unroll
        for (int ks = 0; ks < 4; ks++) {
            uint32_t bf[4][2];
#pragma unroll
            for (int nt = 0; nt < 4; nt++) {
                int n = wh * 32 + nt * 8 + g;
                bf[nt][0] = Kw[n * 36 + ks * 8 + tig];
                bf[nt][1] = Kw[n * 36 + ks * 8 + tig + 4];
            }
#pragma unroll
            for (int nt = 0; nt < 4; nt++)
                mma_f16(acc[nt], qa[ks], bf[nt]);
        }
#pragma unroll
        for (int nt = 0; nt < 4; nt++) {
            int col = kt * 64 + wh * 32 + nt * 8 + 2 * tig;
            int row = wq * 16 + g;
            Ssm[row * SSS + col]           = acc[nt][0] * 0.125f;
            Ssm[row * SSS + col + 1]       = acc[nt][1] * 0.125f;
            Ssm[(row + 8) * SSS + col]     = acc[nt][2] * 0.125f;
            Ssm[(row + 8) * SSS + col + 1] = acc[nt][3] * 0.125f;
        }
        __syncthreads();
    }

    // prefetch V0 -> kvB, V1 -> kvA (land during softmax)
    issue_tile(kvB, Vg);
    issue_tile(kvA, Vg + (size_t)64 * H3);

    // ---- softmax over each row of 512; write P as fp16 into Psm ----
    for (int r = warp * 8; r < warp * 8 + 8; r++) {
        float* row = &Ssm[r * SSS];
        float v[16];
        float m = -1e30f;
#pragma unroll
        for (int i = 0; i < 16; i++) { v[i] = row[lane + 32 * i]; m = fmaxf(m, v[i]); }
#pragma unroll
        for (int o = 16; o > 0; o >>= 1) m = fmaxf(m, __shfl_xor_sync(0xffffffffu, m, o));
        float s = 0.f;
#pragma unroll
        for (int i = 0; i < 16; i++) { v[i] = __expf(v[i] - m); s += v[i]; }
#pragma unroll
        for (int o = 16; o > 0; o >>= 1) s += __shfl_xor_sync(0xffffffffu, s, o);
        float inv = 1.0f / s;
        __half* prow = &Psm[r * PSTH];
#pragma unroll
        for (int i = 0; i < 16; i++) prow[lane + 32 * i] = __float2half_rn(v[i] * inv);
    }
    __syncthreads();

    // ---- O = P @ V (fp16 mma, V via ldmatrix.trans) ----
    float oacc[4][4];
#pragma unroll
    for (int nt = 0; nt < 4; nt++)
#pragma unroll
        for (int r = 0; r < 4; r++) oacc[nt][r] = 0.f;

    const uint32_t* Pw = (const uint32_t*)Psm;
    uint32_t kv_base[2] = { (uint32_t)__cvta_generic_to_shared(kvB),
                            (uint32_t)__cvta_generic_to_shared(kvA) };
    int rm = wq * 16 + g;
    for (int kt = 0; kt < 8; kt++) {
        if (kt < 7) asm volatile("cp.async.wait_group 1;" ::: "memory");
        else        asm volatile("cp.async.wait_group 0;" ::: "memory");
        __syncthreads();

        uint32_t vb = kv_base[kt & 1];
#pragma unroll
        for (int ks = 0; ks < 4; ks++) {
            uint32_t pa[4];
            int kw = kt * 32 + ks * 8;          // word offset within P row
            pa[0] = Pw[rm * 260 + kw + tig];
            pa[1] = Pw[(rm + 8) * 260 + kw + tig];
            pa[2] = Pw[rm * 260 + kw + tig + 4];
            pa[3] = Pw[(rm + 8) * 260 + kw + tig + 4];
#pragma unroll
            for (int nt = 0; nt < 4; nt++) {
                int n0 = wh * 32 + nt * 8;
                uint32_t addr = vb + (uint32_t)(((ks * 16 + (lane & 15)) * QSTH + n0) * 2);
                uint32_t bf0, bf1;
                ldmatrix_x2_trans(bf0, bf1, addr);
                uint32_t bf[2] = { bf0, bf1 };
                mma_f16(oacc[nt], pa, bf);
            }
        }
        __syncthreads();
        if (kt + 2 < 8) {
            __half* dst = (kt & 1) ? kvA : kvB;
            issue_tile(dst, Vg + (size_t)(kt + 2) * 64 * H3);
        }
    }

    // fp16 output (Wo GEMM consumes it)
#pragma unroll
    for (int nt = 0; nt < 4; nt++) {
        int col = h * DHh + wh * 32 + nt * 8 + 2 * tig;
        size_t row = (size_t)(b * Ss + qt + wq * 16 + g);
        g_ctxh[row * Hh + col]     = __float2half_rn(oacc[nt][0]);
        g_ctxh[row * Hh + col + 1] = __float2half_rn(oacc[nt][1]);
        g_ctxh[(row + 8) * Hh + col]     = __float2half_rn(oacc[nt][2]);
        g_ctxh[(row + 8) * Hh + col + 1] = __float2half_rn(oacc[nt][3]);
    }
}

// ---------------- segment bookkeeping (deterministic) ----------------
__global__ void seg_prep_kernel(const int* __restrict__ tok) {
    int b = blockIdx.x, s = threadIdx.x;
    __shared__ int sc[Ss];
    __shared__ int cnt[Ss];
    int wid = tok[(b * Ss + s) * 2];
    int isnew = (s == 0) ? 1 : (wid != tok[(b * Ss + s - 1) * 2] ? 1 : 0);
    sc[s] = isnew; cnt[s] = 0; __syncthreads();
    for (int off = 1; off < Ss; off <<= 1) {
        int v = (s >= off) ? sc[s - off] : 0;
        __syncthreads();
        sc[s] += v;
        __syncthreads();
    }
    int gid = sc[s] - 1;
    if (tok[(b * Ss + s) * 2 + 1] != 0) atomicAdd(&cnt[gid], 1);
    if (isnew) g_seg_first[b * Ss + gid] = s;
    __syncthreads();
    g_seg_cnt[b * Ss + s] = cnt[s];
    if (s == Ss - 1) g_nseg[b] = gid + 1;
}

__global__ void seg_mean_kernel(const int* __restrict__ tok, float* __restrict__ out) {
    int g = blockIdx.x, b = blockIdx.y;
    int n = g_nseg[b];
    if (g >= n) return;
    int c = g_seg_cnt[b * Ss + g];
    if (c == 0) return;
    int start = g_seg_first[b * Ss + g];
    int end = (g + 1 < n) ? g_seg_first[b * Ss + g + 1] : Ss;
    __shared__ unsigned char mf[Ss];
    for (int s = threadIdx.x; s < Ss; s += 128)
        mf[s] = (tok[(b * Ss + s) * 2 + 1] != 0);
    __syncthreads();
    float inv = 1.0f / (float)c;
    for (int j = threadIdx.x; j < Hh; j += 128) {
        float sum = 0.f;
        for (int s = start; s < end; s++)
            if (mf[s]) sum += g_x[(size_t)(b * Ss + s) * Hh + j];
        out[(size_t)(b * Ss + g) * Hh + j] = sum * inv;
    }
}

// ---------------- launch ----------------
extern "C" void kernel_launch(void* const* d_in, const int* in_sizes, int n_in,
                              void* d_out, int out_size) {
    const int*   tok  = (const int*)  d_in[0];
    const float* emb  = (const float*)d_in[1];
    const float* pos  = (const float*)d_in[2];
    const float* lng  = (const float*)d_in[3];
    const float* lnb  = (const float*)d_in[4];
    const float* Wqkv = (const float*)d_in[5];
    const float* bqkv = (const float*)d_in[6];
    const float* Wo   = (const float*)d_in[7];
    const float* bo   = (const float*)d_in[8];
    const float* ln1g = (const float*)d_in[9];
    const float* ln1b = (const float*)d_in[10];
    const float* Wff1 = (const float*)d_in[11];
    const float* bff1 = (const float*)d_in[12];
    const float* Wff2 = (const float*)d_in[13];
    const float* bff2 = (const float*)d_in[14];
    const float* ln2g = (const float*)d_in[15];
    const float* ln2b = (const float*)d_in[16];
    float* out = (float*)d_out;

    void* p;
    cudaGetSymbolAddress(&p, g_x);     float*  x    = (float*)p;
    cudaGetSymbolAddress(&p, g_tmp);   float*  tmp  = (float*)p;
    cudaGetSymbolAddress(&p, g_ctx);   float*  ctx  = (float*)p;
    cudaGetSymbolAddress(&p, g_qkvh);  __half* qkvh = (__half*)p;
    cudaGetSymbolAddress(&p, g_xh);    __half* xh   = (__half*)p;
    cudaGetSymbolAddress(&p, g_ctxh);  __half* ctxh = (__half*)p;
    cudaGetSymbolAddress(&p, g_ff1h);  __half* ff1h = (__half*)p;
    cudaGetSymbolAddress(&p, g_wh);    __half* wh   = (__half*)p;

    cudaFuncSetAttribute(fused_attn_kernel,
                         cudaFuncAttributeMaxDynamicSharedMemorySize, ATTN_SMEM_BYTES);
    cudaFuncSetAttribute(gemm_f16_kernel,
                         cudaFuncAttributeMaxDynamicSharedMemorySize, GEMM_SMEM_BYTES);

    cudaMemsetAsync(d_out, 0, (size_t)out_size * sizeof(float), 0);

    // per-launch weight transpose + fp16 convert ([K][N] -> [N][K])
    for (int l = 0; l < Ll; l++) {
        __half* wl = wh + (size_t)l * WT_LAYER;
        transpose_h_kernel<<<dim3(H3 / 32, Hh / 32), dim3(32, 8)>>>(
            Wqkv + (size_t)l * Hh * H3, wl + WT_QKV, Hh, H3);
        transpose_h_kernel<<<dim3(Hh / 32, Hh / 32), dim3(32, 8)>>>(
            Wo + (size_t)l * Hh * Hh, wl + WT_WO, Hh, Hh);
        transpose_h_kernel<<<dim3(FFf / 32, Hh / 32), dim3(32, 8)>>>(
            Wff1 + (size_t)l * Hh * FFf, wl + WT_FF1, Hh, FFf);
        transpose_h_kernel<<<dim3(Hh / 32, FFf / 32), dim3(32, 8)>>>(
            Wff2 + (size_t)l * FFf * Hh, wl + WT_FF2, FFf, Hh);
    }

    embed_ln_kernel<<<Tt, 256>>>(tok, emb, pos, lng, lnb);

    for (int l = 0; l < Ll; l++) {
        const __half* wl = wh + (size_t)l * WT_LAYER;
        // QKV: [8192,768] @ [768,2304] -> fp16 qkvh
        launch_gemm(xh, wl + WT_QKV, bqkv + l * H3, qkvh, Tt, H3, Hh, 2);
        // fused attention (full fp16) -> fp16 ctxh
        fused_attn_kernel<<<dim3(8, Bb * NHh), 256, ATTN_SMEM_BYTES>>>(qkvh);
        // Wo: [8192,768] @ [768,768] -> fp32 tmp
        launch_gemm(ctxh, wl + WT_WO, bo + l * Hh, tmp, Tt, Hh, Hh, 0);
        add_ln_kernel<<<Tt, 256>>>(x, tmp, ln1g + l * Hh, ln1b + l * Hh, x, xh);
        // FF1: [8192,768] @ [768,3072] + GELU -> fp16 ff1h
        launch_gemm(xh, wl + WT_FF1, bff1 + l * FFf, ff1h, Tt, FFf, Hh, 1);
        // FF2: [8192,3072] @ [3072,768] -> fp32 ctx
        launch_gemm(ff1h, wl + WT_FF2, bff2 + l * Hh, ctx, Tt, Hh, FFf, 0);
        add_ln_kernel<<<Tt, 256>>>(x, ctx, ln2g + l * Hh, ln2b + l * Hh, x, xh);
    }

    seg_prep_kernel<<<Bb, Ss>>>(tok);
    seg_mean_kernel<<<dim3(Ss, Bb), 128>>>(tok, out);
}

// round 13
// speedup vs baseline: 1.7944x; 1.0636x over previous
#include <cuda_runtime.h>
#include <cuda_fp16.h>
#include <math.h>
#include <stdint.h>

#define Bb   16
#define Ss   512
#define Hh   768
#define NHh  12
#define DHh  64
#define Ll   2
#define FFf  3072
#define Tt   (Bb*Ss)          // 8192 tokens
#define H3   (3*Hh)           // 2304

#define NSM       148
#define PERSIST   (2*NSM)

// ---------------- scratch (no allocations allowed) ----------------
__device__ float  g_x[Tt*Hh];                   // hidden state fp32
__device__ float  g_tmp[Tt*Hh];                 // wo out (fp32)
__device__ float  g_ctx[Tt*Hh];                 // ff2 out (fp32)
__device__ __half g_qkvh[Tt*H3];                // fp16 qkv
__device__ __half g_xh[Tt*Hh];                  // fp16 copy of x
__device__ __half g_ctxh[Tt*Hh];                // fp16 attention output
__device__ __half g_ff1h[Tt*FFf];               // fp16 FF1 output (post-GELU)
#define WT_LAYER 7077888
#define WT_QKV   0
#define WT_WO    1769472
#define WT_FF1   2359296
#define WT_FF2   4718592
__device__ __half g_wh[2*WT_LAYER];             // 28.3 MB
__device__ int    g_seg_first[Bb*Ss];
__device__ int    g_seg_cnt[Bb*Ss];
__device__ int    g_nseg[Bb];

// ---------------- helpers ----------------
__device__ __forceinline__ void mma_f16(float* c, const uint32_t* a, const uint32_t* b) {
    asm volatile(
        "mma.sync.aligned.m16n8k16.row.col.f32.f16.f16.f32 "
        "{%0,%1,%2,%3}, {%4,%5,%6,%7}, {%8,%9}, {%0,%1,%2,%3};"
        : "+f"(c[0]), "+f"(c[1]), "+f"(c[2]), "+f"(c[3])
        : "r"(a[0]), "r"(a[1]), "r"(a[2]), "r"(a[3]), "r"(b[0]), "r"(b[1]));
}

__device__ __forceinline__ void ldmatrix_x4(uint32_t& d0, uint32_t& d1,
                                            uint32_t& d2, uint32_t& d3, uint32_t addr) {
    asm volatile("ldmatrix.sync.aligned.m8n8.x4.shared.b16 {%0,%1,%2,%3}, [%4];"
                 : "=r"(d0), "=r"(d1), "=r"(d2), "=r"(d3) : "r"(addr));
}

__device__ __forceinline__ void ldmatrix_x2(uint32_t& d0, uint32_t& d1, uint32_t addr) {
    asm volatile("ldmatrix.sync.aligned.m8n8.x2.shared.b16 {%0,%1}, [%2];"
                 : "=r"(d0), "=r"(d1) : "r"(addr));
}

__device__ __forceinline__ void ldmatrix_x2_trans(uint32_t& d0, uint32_t& d1, uint32_t addr) {
    asm volatile("ldmatrix.sync.aligned.m8n8.x2.trans.shared.b16 {%0,%1}, [%2];"
                 : "=r"(d0), "=r"(d1) : "r"(addr));
}

__device__ __forceinline__ void cp_async16(void* smem_ptr, const void* gptr) {
    uint32_t s = (uint32_t)__cvta_generic_to_shared(smem_ptr);
    asm volatile("cp.async.cg.shared.global [%0], [%1], 16;" :: "r"(s), "l"(gptr));
}

// one-pass dual block reduce (sum, sumsq): warp shfl + one smem hop
__device__ __forceinline__ void block_reduce2_256(float& s, float& q, float* red) {
    int lane = threadIdx.x & 31, warp = threadIdx.x >> 5;
#pragma unroll
    for (int o = 16; o > 0; o >>= 1) {
        s += __shfl_xor_sync(0xffffffffu, s, o);
        q += __shfl_xor_sync(0xffffffffu, q, o);
    }
    if (lane == 0) { red[warp] = s; red[8 + warp] = q; }
    __syncthreads();
    if (warp == 0) {
        float ss = (lane < 8) ? red[lane] : 0.f;
        float qq = (lane < 8) ? red[8 + lane] : 0.f;
#pragma unroll
        for (int o = 4; o > 0; o >>= 1) {
            ss += __shfl_xor_sync(0xffffffffu, ss, o);
            qq += __shfl_xor_sync(0xffffffffu, qq, o);
        }
        if (lane == 0) { red[16] = ss; red[17] = qq; }
    }
    __syncthreads();
    s = red[16]; q = red[17];
}

// ---------------- weight transpose + fp16 cvt: dst[N][K] = h(src[K][N]^T) ------
__global__ void transpose_h_kernel(const float* __restrict__ src,
                                   __half* __restrict__ dst, int K, int N) {
    __shared__ float tile[32][33];
    int bx = blockIdx.x * 32;   // n
    int by = blockIdx.y * 32;   // k
    int tx = threadIdx.x, ty = threadIdx.y;   // 32 x 8
#pragma unroll
    for (int j = 0; j < 32; j += 8)
        tile[ty + j][tx] = src[(size_t)(by + ty + j) * N + bx + tx];
    __syncthreads();
#pragma unroll
    for (int j = 0; j < 32; j += 8)
        dst[(size_t)(bx + ty + j) * K + by + tx] = __float2half_rn(tile[tx][ty + j]);
}

// ---------------- embedding + LN (writes fp32 + fp16) ----------------
__global__ void embed_ln_kernel(const int* __restrict__ tok,
                                const float* __restrict__ emb,
                                const float* __restrict__ pos,
                                const float* __restrict__ g,
                                const float* __restrict__ bt) {
    int row = blockIdx.x;
    int s   = row & (Ss - 1);
    int id  = tok[row * 2 + 1];
    __shared__ float y[Hh];
    __shared__ float red[18];
    int t = threadIdx.x;
    float ps = 0.f, pq = 0.f;
    for (int j = t; j < Hh; j += 256) {
        float v = emb[(size_t)id * Hh + j] + pos[s * Hh + j];
        y[j] = v; ps += v; pq += v * v;
    }
    block_reduce2_256(ps, pq, red);
    float mean = ps * (1.f / Hh);
    float var  = pq * (1.f / Hh) - mean * mean;
    float inv = rsqrtf(var + 1e-12f);
    for (int j = t; j < Hh; j += 256) {
        float o = (y[j] - mean) * inv * g[j] + bt[j];
        g_x[(size_t)row * Hh + j]  = o;
        g_xh[(size_t)row * Hh + j] = __float2half_rn(o);
    }
}

// ---------------- residual add + LN (writes fp32 + fp16) ----------------
__global__ void add_ln_kernel(const float* __restrict__ x,
                              const float* __restrict__ tadd,
                              const float* __restrict__ g,
                              const float* __restrict__ bt,
                              float* __restrict__ out,
                              __half* __restrict__ outh) {
    int row = blockIdx.x;
    size_t base = (size_t)row * Hh;
    __shared__ float y[Hh];
    __shared__ float red[18];
    int t = threadIdx.x;
    float ps = 0.f, pq = 0.f;
    for (int j = t; j < Hh; j += 256) {
        float v = x[base + j] + tadd[base + j];
        y[j] = v; ps += v; pq += v * v;
    }
    block_reduce2_256(ps, pq, red);
    float mean = ps * (1.f / Hh);
    float var  = pq * (1.f / Hh) - mean * mean;
    float inv = rsqrtf(var + 1e-12f);
    for (int j = t; j < Hh; j += 256) {
        float o = (y[j] - mean) * inv * g[j] + bt[j];
        out[base + j]  = o;
        outh[base + j] = __float2half_rn(o);
    }
}

// ------- persistent FP16 tensor-core GEMM, 3-stage cp.async + ldmatrix --------
// C = A[M,K](fp16) @ WT[N,K](fp16)^T + bias.
// act=0: fp32 C;  act=1: GELU + fp16 C;  act=2: fp16 C (no activation).
#define HAS     40
#define HA_SZ   (128 * HAS)
#define HSTAGE  (2 * HA_SZ)
#define GEMM_SMEM_BYTES (3 * HSTAGE * 2)     // 61440 B

__global__ __launch_bounds__(256) void gemm_f16_kernel(const __half* __restrict__ A,
                                                       const __half* __restrict__ WT,
                                                       const float* __restrict__ bias,
                                                       void* __restrict__ Cout,
                                                       int M, int N, int K, int act,
                                                       int numTiles, int nTN) {
    extern __shared__ __half hsm[];
    int tid  = threadIdx.x;
    int lane = tid & 31;
    int warp = tid >> 5;
    int g    = lane >> 2, tig = lane & 3;
    int wm   = warp >> 2, wn = warp & 3;
    int nK   = K >> 5;

    uint32_t smem_base = (uint32_t)__cvta_generic_to_shared(hsm);
    // ldmatrix per-lane byte offsets (within a stage)
    int l15 = lane & 15;
    // A x4: row = wm*64 + mi*16 + (lane&15); col8 = (lane>>4)*8
    uint32_t a_off = (uint32_t)(((wm * 64 + (lane & 15)) * HAS + ((lane >> 4) << 3)) * 2);
    // B x2: row(n) = wn*32 + ni*8 + (l15&7); col8 = ((l15>>3)&1)*8 ; B region offset HA_SZ halves
    uint32_t b_off = (uint32_t)((HA_SZ + (wn * 32 + (l15 & 7)) * HAS + (((l15 >> 3) & 1) << 3)) * 2);

    for (int t = blockIdx.x; t < numTiles; t += gridDim.x) {
        int mBase = (t / nTN) * 128;
        int nBase = (t % nTN) * 128;

        float acc[4][4][4];
#pragma unroll
        for (int i = 0; i < 4; i++)
#pragma unroll
            for (int j = 0; j < 4; j++)
#pragma unroll
                for (int r = 0; r < 4; r++) acc[i][j][r] = 0.f;

        auto load_stage = [&](int stage, int k0) {
            __half* st = hsm + stage * HSTAGE;
#pragma unroll
            for (int i = 0; i < 2; i++) {
                int idx = tid + i * 256;
                int r = idx >> 2, c = (idx & 3) << 3;
                cp_async16(&st[r * HAS + c], &A[(size_t)(mBase + r) * K + k0 + c]);
            }
            __half* bs = st + HA_SZ;
#pragma unroll
            for (int i = 0; i < 2; i++) {
                int idx = tid + i * 256;
                int r = idx >> 2, c = (idx & 3) << 3;
                cp_async16(&bs[r * HAS + c], &WT[(size_t)(nBase + r) * K + k0 + c]);
            }
            asm volatile("cp.async.commit_group;" ::: "memory");
        };

        load_stage(0, 0);
        load_stage(1, 32);

        int s_cur = 0, s_next = 2;
        for (int i = 0; i < nK; i++) {
            if (i + 2 < nK) {
                load_stage(s_next, (i + 2) << 5);
                asm volatile("cp.async.wait_group 2;" ::: "memory");
            } else if (i + 1 < nK) {
                asm volatile("cp.async.wait_group 1;" ::: "memory");
            } else {
                asm volatile("cp.async.wait_group 0;" ::: "memory");
            }
            __syncthreads();

            uint32_t stage_b = smem_base + (uint32_t)(s_cur * HSTAGE * 2);
#pragma unroll
            for (int ks = 0; ks < 2; ks++) {
                uint32_t a[4][4], b[4][2];
                uint32_t koff = (uint32_t)(ks * 32);       // 16 halves = 32 bytes
#pragma unroll
                for (int mi = 0; mi < 4; mi++)
                    ldmatrix_x4(a[mi][0], a[mi][1], a[mi][2], a[mi][3],
                                stage_b + a_off + koff + (uint32_t)(mi * 16 * HAS * 2));
#pragma unroll
                for (int ni = 0; ni < 4; ni++)
                    ldmatrix_x2(b[ni][0], b[ni][1],
                                stage_b + b_off + koff + (uint32_t)(ni * 8 * HAS * 2));
#pragma unroll
                for (int mi = 0; mi < 4; mi++)
#pragma unroll
                    for (int ni = 0; ni < 4; ni++)
                        mma_f16(acc[mi][ni], a[mi], b[ni]);
            }
            __syncthreads();
            s_cur = (s_cur == 2) ? 0 : s_cur + 1;
            s_next = (s_next == 2) ? 0 : s_next + 1;
        }

        // epilogue
#pragma unroll
        for (int mi = 0; mi < 4; mi++) {
            int rm0 = mBase + wm * 64 + mi * 16 + g;
#pragma unroll
            for (int ni = 0; ni < 4; ni++) {
                int cn = nBase + wn * 32 + ni * 8 + 2 * tig;
                float b0 = bias[cn], b1 = bias[cn + 1];
                float v0 = acc[mi][ni][0] + b0;
                float v1 = acc[mi][ni][1] + b1;
                float v2 = acc[mi][ni][2] + b0;
                float v3 = acc[mi][ni][3] + b1;
                if (act == 1) {
                    v0 = 0.5f * v0 * (1.0f + erff(v0 * 0.70710678118654752f));
                    v1 = 0.5f * v1 * (1.0f + erff(v1 * 0.70710678118654752f));
                    v2 = 0.5f * v2 * (1.0f + erff(v2 * 0.70710678118654752f));
                    v3 = 0.5f * v3 * (1.0f + erff(v3 * 0.70710678118654752f));
                }
                if (act) {
                    __half2* Ch = (__half2*)Cout;
                    Ch[((size_t)rm0 * N + cn) >> 1]       = __floats2half2_rn(v0, v1);
                    Ch[((size_t)(rm0 + 8) * N + cn) >> 1] = __floats2half2_rn(v2, v3);
                } else {
                    float* Cf = (float*)Cout;
                    *reinterpret_cast<float2*>(&Cf[(size_t)rm0 * N + cn])       = make_float2(v0, v1);
                    *reinterpret_cast<float2*>(&Cf[(size_t)(rm0 + 8) * N + cn]) = make_float2(v2, v3);
                }
            }
        }
    }
}

static inline void launch_gemm(const __half* A, const __half* WT, const float* bias,
                               void* C, int M, int N, int K, int act) {
    int nTM = M / 128, nTN = N / 128;
    int tiles = nTM * nTN;
    int grid = tiles < PERSIST ? tiles : PERSIST;
    gemm_f16_kernel<<<grid, 256, GEMM_SMEM_BYTES>>>(A, WT, bias, C, M, N, K, act,
                                                    tiles, nTN);
}

// -------- fused attention, full fp16 mma ---------------------------------------
#define SSS   516
#define QSTH  72
#define PSTH  520
#define SMEM_S_BYTES   (64 * SSS * 4)
#define SMEM_P_BYTES   (64 * PSTH * 2)
#define SMEM_TILE_B    (64 * QSTH * 2)
#define ATTN_SMEM_BYTES (SMEM_S_BYTES + SMEM_P_BYTES + 2 * SMEM_TILE_B)  // 217088

__global__ __launch_bounds__(256) void fused_attn_kernel(const __half* __restrict__ qkv) {
    extern __shared__ char asm_raw[];
    float*  Ssm  = (float*)asm_raw;
    __half* Psm  = (__half*)(asm_raw + SMEM_S_BYTES);
    __half* kvA  = (__half*)(asm_raw + SMEM_S_BYTES + SMEM_P_BYTES);
    __half* kvB  = kvA + 64 * QSTH;

    int bh = blockIdx.y; int b = bh / NHh, h = bh - b * NHh;
    int qt = blockIdx.x * 64;
    int tid = threadIdx.x, lane = tid & 31, warp = tid >> 5;
    int g = lane >> 2, tig = lane & 3;
    int wq = warp >> 1, wh = warp & 1;

    const __half* Qg = &qkv[(size_t)(b * Ss + qt) * H3 + h * DHh];
    const __half* Kg = &qkv[(size_t)(b * Ss) * H3 + Hh + h * DHh];
    const __half* Vg = &qkv[(size_t)(b * Ss) * H3 + 2 * Hh + h * DHh];

    auto issue_tile = [&](__half* buf, const __half* src) {
#pragma unroll
        for (int i = 0; i < 2; i++) {
            int idx = tid + i * 256;
            int r = idx >> 3, c = (idx & 7) << 3;
            cp_async16(&buf[r * QSTH + c], &src[(size_t)r * H3 + c]);
        }
        asm volatile("cp.async.commit_group;" ::: "memory");
    };

    issue_tile(kvA, Qg);
    issue_tile(kvB, Kg);
    asm volatile("cp.async.wait_group 0;" ::: "memory");
    __syncthreads();

    uint32_t qa[4][4];
    {
        const uint32_t* Qw = (const uint32_t*)kvA;
        int rm = wq * 16 + g;
#pragma unroll
        for (int ks = 0; ks < 4; ks++) {
            qa[ks][0] = Qw[rm * 36 + ks * 8 + tig];
            qa[ks][1] = Qw[(rm + 8) * 36 + ks * 8 + tig];
            qa[ks][2] = Qw[rm * 36 + ks * 8 + tig + 4];
            qa[ks][3] = Qw[(rm + 8) * 36 + ks * 8 + tig + 4];
        }
    }
    __syncthreads();

    for (int kt = 0; kt < 8; kt++) {
        __half* cur = (kt & 1) ? kvA : kvB;
        __half* nxt = (kt & 1) ? kvB : kvA;
        if (kt < 7) {
            issue_tile(nxt, Kg + (size_t)(kt + 1) * 64 * H3);
            asm volatile("cp.async.wait_group 1;" ::: "memory");
        } else {
            asm volatile("cp.async.wait_group 0;" ::: "memory");
        }
        __syncthreads();

        const uint32_t* Kw = (const uint32_t*)cur;
        float acc[4][4];
#pragma unroll
        for (int nt = 0; nt < 4; nt++)
#pragma unroll
            for (int r = 0; r < 4; r++) acc[nt][r] = 0.f;
#pragma unroll
        for (int ks = 0; ks < 4; ks++) {
            uint32_t bf[4][2];
#pragma unroll
            for (int nt = 0; nt < 4; nt++) {
                int n = wh * 32 + nt * 8 + g;
                bf[nt][0] = Kw[n * 36 + ks * 8 + tig];
                bf[nt][1] = Kw[n * 36 + ks * 8 + tig + 4];
            }
#pragma unroll
            for (int nt = 0; nt < 4; nt++)
                mma_f16(acc[nt], qa[ks], bf[nt]);
        }
#pragma unroll
        for (int nt = 0; nt < 4; nt++) {
            int col = kt * 64 + wh * 32 + nt * 8 + 2 * tig;
            int row = wq * 16 + g;
            Ssm[row * SSS + col]           = acc[nt][0] * 0.125f;
            Ssm[row * SSS + col + 1]       = acc[nt][1] * 0.125f;
            Ssm[(row + 8) * SSS + col]     = acc[nt][2] * 0.125f;
            Ssm[(row + 8) * SSS + col + 1] = acc[nt][3] * 0.125f;
        }
        __syncthreads();
    }

    issue_tile(kvB, Vg);
    issue_tile(kvA, Vg + (size_t)64 * H3);

    for (int r = warp * 8; r < warp * 8 + 8; r++) {
        float* row = &Ssm[r * SSS];
        float v[16];
        float m = -1e30f;
#pragma unroll
        for (int i = 0; i < 16; i++) { v[i] = row[lane + 32 * i]; m = fmaxf(m, v[i]); }
#pragma unroll
        for (int o = 16; o > 0; o >>= 1) m = fmaxf(m, __shfl_xor_sync(0xffffffffu, m, o));
        float s = 0.f;
#pragma unroll
        for (int i = 0; i < 16; i++) { v[i] = __expf(v[i] - m); s += v[i]; }
#pragma unroll
        for (int o = 16; o > 0; o >>= 1) s += __shfl_xor_sync(0xffffffffu, s, o);
        float inv = 1.0f / s;
        __half* prow = &Psm[r * PSTH];
#pragma unroll
        for (int i = 0; i < 16; i++) prow[lane + 32 * i] = __float2half_rn(v[i] * inv);
    }
    __syncthreads();

    float oacc[4][4];
#pragma unroll
    for (int nt = 0; nt < 4; nt++)
#pragma unroll
        for (int r = 0; r < 4; r++) oacc[nt][r] = 0.f;

    const uint32_t* Pw = (const uint32_t*)Psm;
    uint32_t kv_base[2] = { (uint32_t)__cvta_generic_to_shared(kvB),
                            (uint32_t)__cvta_generic_to_shared(kvA) };
    int rm = wq * 16 + g;
    for (int kt = 0; kt < 8; kt++) {
        if (kt < 7) asm volatile("cp.async.wait_group 1;" ::: "memory");
        else        asm volatile("cp.async.wait_group 0;" ::: "memory");
        __syncthreads();

        uint32_t vb = kv_base[kt & 1];
#pragma unroll
        for (int ks = 0; ks < 4; ks++) {
            uint32_t pa[4];
            int kw = kt * 32 + ks * 8;
            pa[0] = Pw[rm * 260 + kw + tig];
            pa[1] = Pw[(rm + 8) * 260 + kw + tig];
            pa[2] = Pw[rm * 260 + kw + tig + 4];
            pa[3] = Pw[(rm + 8) * 260 + kw + tig + 4];
#pragma unroll
            for (int nt = 0; nt < 4; nt++) {
                int n0 = wh * 32 + nt * 8;
                uint32_t addr = vb + (uint32_t)(((ks * 16 + (lane & 15)) * QSTH + n0) * 2);
                uint32_t bf0, bf1;
                ldmatrix_x2_trans(bf0, bf1, addr);
                uint32_t bf[2] = { bf0, bf1 };
                mma_f16(oacc[nt], pa, bf);
            }
        }
        __syncthreads();
        if (kt + 2 < 8) {
            __half* dst = (kt & 1) ? kvA : kvB;
            issue_tile(dst, Vg + (size_t)(kt + 2) * 64 * H3);
        }
    }

#pragma unroll
    for (int nt = 0; nt < 4; nt++) {
        int col = h * DHh + wh * 32 + nt * 8 + 2 * tig;
        size_t row = (size_t)(b * Ss + qt + wq * 16 + g);
        g_ctxh[row * Hh + col]     = __float2half_rn(oacc[nt][0]);
        g_ctxh[row * Hh + col + 1] = __float2half_rn(oacc[nt][1]);
        g_ctxh[(row + 8) * Hh + col]     = __float2half_rn(oacc[nt][2]);
        g_ctxh[(row + 8) * Hh + col + 1] = __float2half_rn(oacc[nt][3]);
    }
}

// ---------------- segment bookkeeping (deterministic) ----------------
__global__ void seg_prep_kernel(const int* __restrict__ tok) {
    int b = blockIdx.x, s = threadIdx.x;
    __shared__ int sc[Ss];
    __shared__ int cnt[Ss];
    int wid = tok[(b * Ss + s) * 2];
    int isnew = (s == 0) ? 1 : (wid != tok[(b * Ss + s - 1) * 2] ? 1 : 0);
    sc[s] = isnew; cnt[s] = 0; __syncthreads();
    for (int off = 1; off < Ss; off <<= 1) {
        int v = (s >= off) ? sc[s - off] : 0;
        __syncthreads();
        sc[s] += v;
        __syncthreads();
    }
    int gid = sc[s] - 1;
    if (tok[(b * Ss + s) * 2 + 1] != 0) atomicAdd(&cnt[gid], 1);
    if (isnew) g_seg_first[b * Ss + gid] = s;
    __syncthreads();
    g_seg_cnt[b * Ss + s] = cnt[s];
    if (s == Ss - 1) g_nseg[b] = gid + 1;
}

__global__ void seg_mean_kernel(const int* __restrict__ tok, float* __restrict__ out) {
    int g = blockIdx.x, b = blockIdx.y;
    int n = g_nseg[b];
    if (g >= n) return;
    int c = g_seg_cnt[b * Ss + g];
    if (c == 0) return;
    int start = g_seg_first[b * Ss + g];
    int end = (g + 1 < n) ? g_seg_first[b * Ss + g + 1] : Ss;
    __shared__ unsigned char mf[Ss];
    for (int s = threadIdx.x; s < Ss; s += 128)
        mf[s] = (tok[(b * Ss + s) * 2 + 1] != 0);
    __syncthreads();
    float inv = 1.0f / (float)c;
    for (int j = threadIdx.x; j < Hh; j += 128) {
        float sum = 0.f;
        for (int s = start; s < end; s++)
            if (mf[s]) sum += g_x[(size_t)(b * Ss + s) * Hh + j];
        out[(size_t)(b * Ss + g) * Hh + j] = sum * inv;
    }
}

// ---------------- launch ----------------
extern "C" void kernel_launch(void* const* d_in, const int* in_sizes, int n_in,
                              void* d_out, int out_size) {
    const int*   tok  = (const int*)  d_in[0];
    const float* emb  = (const float*)d_in[1];
    const float* pos  = (const float*)d_in[2];
    const float* lng  = (const float*)d_in[3];
    const float* lnb  = (const float*)d_in[4];
    const float* Wqkv = (const float*)d_in[5];
    const float* bqkv = (const float*)d_in[6];
    const float* Wo   = (const float*)d_in[7];
    const float* bo   = (const float*)d_in[8];
    const float* ln1g = (const float*)d_in[9];
    const float* ln1b = (const float*)d_in[10];
    const float* Wff1 = (const float*)d_in[11];
    const float* bff1 = (const float*)d_in[12];
    const float* Wff2 = (const float*)d_in[13];
    const float* bff2 = (const float*)d_in[14];
    const float* ln2g = (const float*)d_in[15];
    const float* ln2b = (const float*)d_in[16];
    float* out = (float*)d_out;

    void* p;
    cudaGetSymbolAddress(&p, g_x);     float*  x    = (float*)p;
    cudaGetSymbolAddress(&p, g_tmp);   float*  tmp  = (float*)p;
    cudaGetSymbolAddress(&p, g_ctx);   float*  ctx  = (float*)p;
    cudaGetSymbolAddress(&p, g_qkvh);  __half* qkvh = (__half*)p;
    cudaGetSymbolAddress(&p, g_xh);    __half* xh   = (__half*)p;
    cudaGetSymbolAddress(&p, g_ctxh);  __half* ctxh = (__half*)p;
    cudaGetSymbolAddress(&p, g_ff1h);  __half* ff1h = (__half*)p;
    cudaGetSymbolAddress(&p, g_wh);    __half* wh   = (__half*)p;

    cudaFuncSetAttribute(fused_attn_kernel,
                         cudaFuncAttributeMaxDynamicSharedMemorySize, ATTN_SMEM_BYTES);
    cudaFuncSetAttribute(gemm_f16_kernel,
                         cudaFuncAttributeMaxDynamicSharedMemorySize, GEMM_SMEM_BYTES);

    cudaMemsetAsync(d_out, 0, (size_t)out_size * sizeof(float), 0);

    for (int l = 0; l < Ll; l++) {
        __half* wl = wh + (size_t)l * WT_LAYER;
        transpose_h_kernel<<<dim3(H3 / 32, Hh / 32), dim3(32, 8)>>>(
            Wqkv + (size_t)l * Hh * H3, wl + WT_QKV, Hh, H3);
        transpose_h_kernel<<<dim3(Hh / 32, Hh / 32), dim3(32, 8)>>>(
            Wo + (size_t)l * Hh * Hh, wl + WT_WO, Hh, Hh);
        transpose_h_kernel<<<dim3(FFf / 32, Hh / 32), dim3(32, 8)>>>(
            Wff1 + (size_t)l * Hh * FFf, wl + WT_FF1, Hh, FFf);
        transpose_h_kernel<<<dim3(Hh / 32, FFf / 32), dim3(32, 8)>>>(
            Wff2 + (size_t)l * FFf * Hh, wl + WT_FF2, FFf, Hh);
    }

    embed_ln_kernel<<<Tt, 256>>>(tok, emb, pos, lng, lnb);

    for (int l = 0; l < Ll; l++) {
        const __half* wl = wh + (size_t)l * WT_LAYER;
        launch_gemm(xh, wl + WT_QKV, bqkv + l * H3, qkvh, Tt, H3, Hh, 2);
        fused_attn_kernel<<<dim3(8, Bb * NHh), 256, ATTN_SMEM_BYTES>>>(qkvh);
        launch_gemm(ctxh, wl + WT_WO, bo + l * Hh, tmp, Tt, Hh, Hh, 0);
        add_ln_kernel<<<Tt, 256>>>(x, tmp, ln1g + l * Hh, ln1b + l * Hh, x, xh);
        launch_gemm(xh, wl + WT_FF1, bff1 + l * FFf, ff1h, Tt, FFf, Hh, 1);
        launch_gemm(ff1h, wl + WT_FF2, bff2 + l * Hh, ctx, Tt, Hh, FFf, 0);
        add_ln_kernel<<<Tt, 256>>>(x, ctx, ln2g + l * Hh, ln2b + l * Hh, x, xh);
    }

    seg_prep_kernel<<<Bb, Ss>>>(tok);
    seg_mean_kernel<<<dim3(Ss, Bb), 128>>>(tok, out);
}

// round 14
// speedup vs baseline: 1.9832x; 1.1052x over previous
#include <cuda_runtime.h>
#include <cuda_fp16.h>
#include <math.h>
#include <stdint.h>

#define Bb   16
#define Ss   512
#define Hh   768
#define NHh  12
#define DHh  64
#define Ll   2
#define FFf  3072
#define Tt   (Bb*Ss)          // 8192 tokens
#define H3   (3*Hh)           // 2304

#define NSM       148
#define PERSIST   (2*NSM)

// ---------------- scratch (no allocations allowed) ----------------
__device__ float  g_x[Tt*Hh];                   // hidden state fp32
__device__ float  g_tmp[Tt*Hh];                 // wo out (fp32)
__device__ float  g_ctx[Tt*Hh];                 // ff2 out (fp32)
__device__ __half g_qkvh[Tt*H3];                // fp16 qkv
__device__ __half g_xh[Tt*Hh];                  // fp16 copy of x
__device__ __half g_ctxh[Tt*Hh];                // fp16 attention output
__device__ __half g_ff1h[Tt*FFf];               // fp16 FF1 output (post-GELU)
#define WT_LAYER 7077888
#define WT_QKV   0
#define WT_WO    1769472
#define WT_FF1   2359296
#define WT_FF2   4718592
__device__ __half g_wh[2*WT_LAYER];             // 28.3 MB
__device__ int    g_seg_first[Bb*Ss];
__device__ int    g_seg_cnt[Bb*Ss];
__device__ int    g_nseg[Bb];

// ---------------- helpers ----------------
__device__ __forceinline__ void mma_f16(float* c, const uint32_t* a, const uint32_t* b) {
    asm volatile(
        "mma.sync.aligned.m16n8k16.row.col.f32.f16.f16.f32 "
        "{%0,%1,%2,%3}, {%4,%5,%6,%7}, {%8,%9}, {%0,%1,%2,%3};"
        : "+f"(c[0]), "+f"(c[1]), "+f"(c[2]), "+f"(c[3])
        : "r"(a[0]), "r"(a[1]), "r"(a[2]), "r"(a[3]), "r"(b[0]), "r"(b[1]));
}

__device__ __forceinline__ void ldmatrix_x4(uint32_t& d0, uint32_t& d1,
                                            uint32_t& d2, uint32_t& d3, uint32_t addr) {
    asm volatile("ldmatrix.sync.aligned.m8n8.x4.shared.b16 {%0,%1,%2,%3}, [%4];"
                 : "=r"(d0), "=r"(d1), "=r"(d2), "=r"(d3) : "r"(addr));
}

__device__ __forceinline__ void ldmatrix_x2(uint32_t& d0, uint32_t& d1, uint32_t addr) {
    asm volatile("ldmatrix.sync.aligned.m8n8.x2.shared.b16 {%0,%1}, [%2];"
                 : "=r"(d0), "=r"(d1) : "r"(addr));
}

__device__ __forceinline__ void ldmatrix_x2_trans(uint32_t& d0, uint32_t& d1, uint32_t addr) {
    asm volatile("ldmatrix.sync.aligned.m8n8.x2.trans.shared.b16 {%0,%1}, [%2];"
                 : "=r"(d0), "=r"(d1) : "r"(addr));
}

__device__ __forceinline__ void cp_async16(void* smem_ptr, const void* gptr) {
    uint32_t s = (uint32_t)__cvta_generic_to_shared(smem_ptr);
    asm volatile("cp.async.cg.shared.global [%0], [%1], 16;" :: "r"(s), "l"(gptr));
}

// one-pass dual block reduce (sum, sumsq): warp shfl + one smem hop
__device__ __forceinline__ void block_reduce2_256(float& s, float& q, float* red) {
    int lane = threadIdx.x & 31, warp = threadIdx.x >> 5;
#pragma unroll
    for (int o = 16; o > 0; o >>= 1) {
        s += __shfl_xor_sync(0xffffffffu, s, o);
        q += __shfl_xor_sync(0xffffffffu, q, o);
    }
    if (lane == 0) { red[warp] = s; red[8 + warp] = q; }
    __syncthreads();
    if (warp == 0) {
        float ss = (lane < 8) ? red[lane] : 0.f;
        float qq = (lane < 8) ? red[8 + lane] : 0.f;
#pragma unroll
        for (int o = 4; o > 0; o >>= 1) {
            ss += __shfl_xor_sync(0xffffffffu, ss, o);
            qq += __shfl_xor_sync(0xffffffffu, qq, o);
        }
        if (lane == 0) { red[16] = ss; red[17] = qq; }
    }
    __syncthreads();
    s = red[16]; q = red[17];
}

// ---------------- weight transpose + fp16 cvt: dst[N][K] = h(src[K][N]^T) ------
__global__ void transpose_h_kernel(const float* __restrict__ src,
                                   __half* __restrict__ dst, int K, int N) {
    __shared__ float tile[32][33];
    int bx = blockIdx.x * 32;   // n
    int by = blockIdx.y * 32;   // k
    int tx = threadIdx.x, ty = threadIdx.y;   // 32 x 8
#pragma unroll
    for (int j = 0; j < 32; j += 8)
        tile[ty + j][tx] = src[(size_t)(by + ty + j) * N + bx + tx];
    __syncthreads();
#pragma unroll
    for (int j = 0; j < 32; j += 8)
        dst[(size_t)(bx + ty + j) * K + by + tx] = __float2half_rn(tile[tx][ty + j]);
}

// ---------------- embedding + LN (writes fp32 + fp16) ----------------
__global__ void embed_ln_kernel(const int* __restrict__ tok,
                                const float* __restrict__ emb,
                                const float* __restrict__ pos,
                                const float* __restrict__ g,
                                const float* __restrict__ bt) {
    int row = blockIdx.x;
    int s   = row & (Ss - 1);
    int id  = tok[row * 2 + 1];
    __shared__ float y[Hh];
    __shared__ float red[18];
    int t = threadIdx.x;
    float ps = 0.f, pq = 0.f;
    for (int j = t; j < Hh; j += 256) {
        float v = emb[(size_t)id * Hh + j] + pos[s * Hh + j];
        y[j] = v; ps += v; pq += v * v;
    }
    block_reduce2_256(ps, pq, red);
    float mean = ps * (1.f / Hh);
    float var  = pq * (1.f / Hh) - mean * mean;
    float inv = rsqrtf(var + 1e-12f);
    for (int j = t; j < Hh; j += 256) {
        float o = (y[j] - mean) * inv * g[j] + bt[j];
        g_x[(size_t)row * Hh + j]  = o;
        g_xh[(size_t)row * Hh + j] = __float2half_rn(o);
    }
}

// ---------------- residual add + LN (writes fp32 + fp16) ----------------
__global__ void add_ln_kernel(const float* __restrict__ x,
                              const float* __restrict__ tadd,
                              const float* __restrict__ g,
                              const float* __restrict__ bt,
                              float* __restrict__ out,
                              __half* __restrict__ outh) {
    int row = blockIdx.x;
    size_t base = (size_t)row * Hh;
    __shared__ float y[Hh];
    __shared__ float red[18];
    int t = threadIdx.x;
    float ps = 0.f, pq = 0.f;
    for (int j = t; j < Hh; j += 256) {
        float v = x[base + j] + tadd[base + j];
        y[j] = v; ps += v; pq += v * v;
    }
    block_reduce2_256(ps, pq, red);
    float mean = ps * (1.f / Hh);
    float var  = pq * (1.f / Hh) - mean * mean;
    float inv = rsqrtf(var + 1e-12f);
    for (int j = t; j < Hh; j += 256) {
        float o = (y[j] - mean) * inv * g[j] + bt[j];
        out[base + j]  = o;
        outh[base + j] = __float2half_rn(o);
    }
}

// ------- persistent FP16 GEMM, 4-stage cp.async + ldmatrix, 1 barrier/iter ----
// C = A[M,K](fp16) @ WT[N,K](fp16)^T + bias.
// act=0: fp32 C;  act=1: GELU + fp16 C;  act=2: fp16 C.
#define HAS     40
#define HA_SZ   (128 * HAS)
#define HSTAGE  (2 * HA_SZ)
#define NSTAGE  4
#define GEMM_SMEM_BYTES (NSTAGE * HSTAGE * 2)   // 81920 B

__global__ __launch_bounds__(256) void gemm_f16_kernel(const __half* __restrict__ A,
                                                       const __half* __restrict__ WT,
                                                       const float* __restrict__ bias,
                                                       void* __restrict__ Cout,
                                                       int M, int N, int K, int act,
                                                       int numTiles, int nTN) {
    extern __shared__ __half hsm[];
    int tid  = threadIdx.x;
    int lane = tid & 31;
    int warp = tid >> 5;
    int g    = lane >> 2, tig = lane & 3;
    int wm   = warp >> 2, wn = warp & 3;
    int nK   = K >> 5;

    uint32_t smem_base = (uint32_t)__cvta_generic_to_shared(hsm);
    int l15 = lane & 15;
    uint32_t a_off = (uint32_t)(((wm * 64 + (lane & 15)) * HAS + ((lane >> 4) << 3)) * 2);
    uint32_t b_off = (uint32_t)((HA_SZ + (wn * 32 + (l15 & 7)) * HAS + (((l15 >> 3) & 1) << 3)) * 2);

    for (int t = blockIdx.x; t < numTiles; t += gridDim.x) {
        int mBase = (t / nTN) * 128;
        int nBase = (t % nTN) * 128;

        float acc[4][4][4];
#pragma unroll
        for (int i = 0; i < 4; i++)
#pragma unroll
            for (int j = 0; j < 4; j++)
#pragma unroll
                for (int r = 0; r < 4; r++) acc[i][j][r] = 0.f;

        auto load_stage = [&](int stage, int k0) {
            __half* st = hsm + stage * HSTAGE;
#pragma unroll
            for (int i = 0; i < 2; i++) {
                int idx = tid + i * 256;
                int r = idx >> 2, c = (idx & 3) << 3;
                cp_async16(&st[r * HAS + c], &A[(size_t)(mBase + r) * K + k0 + c]);
            }
            __half* bs = st + HA_SZ;
#pragma unroll
            for (int i = 0; i < 2; i++) {
                int idx = tid + i * 256;
                int r = idx >> 2, c = (idx & 3) << 3;
                cp_async16(&bs[r * HAS + c], &WT[(size_t)(nBase + r) * K + k0 + c]);
            }
            asm volatile("cp.async.commit_group;" ::: "memory");
        };

        // prologue: 3 stages in flight (nK >= 3 always here)
        load_stage(0, 0);
        load_stage(1, 32);
        load_stage(2, 64);

        for (int i = 0; i < nK; i++) {
            // ensure stage i's group is complete (pending <= min(2, nK-1-i))
            if (i + 2 < nK)      asm volatile("cp.async.wait_group 2;" ::: "memory");
            else if (i + 1 < nK) asm volatile("cp.async.wait_group 1;" ::: "memory");
            else                 asm volatile("cp.async.wait_group 0;" ::: "memory");
            __syncthreads();   // single barrier: makes stage i visible AND protects
                               // stage (i+3)&3 (last read at iter i-1) for overwrite

            uint32_t stage_b = smem_base + (uint32_t)((i & 3) * HSTAGE * 2);
#pragma unroll
            for (int ks = 0; ks < 2; ks++) {
                uint32_t a[4][4], b[4][2];
                uint32_t koff = (uint32_t)(ks * 32);
#pragma unroll
                for (int mi = 0; mi < 4; mi++)
                    ldmatrix_x4(a[mi][0], a[mi][1], a[mi][2], a[mi][3],
                                stage_b + a_off + koff + (uint32_t)(mi * 16 * HAS * 2));
#pragma unroll
                for (int ni = 0; ni < 4; ni++)
                    ldmatrix_x2(b[ni][0], b[ni][1],
                                stage_b + b_off + koff + (uint32_t)(ni * 8 * HAS * 2));
#pragma unroll
                for (int mi = 0; mi < 4; mi++)
#pragma unroll
                    for (int ni = 0; ni < 4; ni++)
                        mma_f16(acc[mi][ni], a[mi], b[ni]);
            }
            if (i + 3 < nK)
                load_stage((i + 3) & 3, (i + 3) << 5);
        }
        __syncthreads();   // protect stages before next tile's prologue overwrites

        // epilogue
#pragma unroll
        for (int mi = 0; mi < 4; mi++) {
            int rm0 = mBase + wm * 64 + mi * 16 + g;
#pragma unroll
            for (int ni = 0; ni < 4; ni++) {
                int cn = nBase + wn * 32 + ni * 8 + 2 * tig;
                float b0 = bias[cn], b1 = bias[cn + 1];
                float v0 = acc[mi][ni][0] + b0;
                float v1 = acc[mi][ni][1] + b1;
                float v2 = acc[mi][ni][2] + b0;
                float v3 = acc[mi][ni][3] + b1;
                if (act == 1) {
                    v0 = 0.5f * v0 * (1.0f + erff(v0 * 0.70710678118654752f));
                    v1 = 0.5f * v1 * (1.0f + erff(v1 * 0.70710678118654752f));
                    v2 = 0.5f * v2 * (1.0f + erff(v2 * 0.70710678118654752f));
                    v3 = 0.5f * v3 * (1.0f + erff(v3 * 0.70710678118654752f));
                }
                if (act) {
                    __half2* Ch = (__half2*)Cout;
                    Ch[((size_t)rm0 * N + cn) >> 1]       = __floats2half2_rn(v0, v1);
                    Ch[((size_t)(rm0 + 8) * N + cn) >> 1] = __floats2half2_rn(v2, v3);
                } else {
                    float* Cf = (float*)Cout;
                    *reinterpret_cast<float2*>(&Cf[(size_t)rm0 * N + cn])       = make_float2(v0, v1);
                    *reinterpret_cast<float2*>(&Cf[(size_t)(rm0 + 8) * N + cn]) = make_float2(v2, v3);
                }
            }
        }
    }
}

static inline void launch_gemm(const __half* A, const __half* WT, const float* bias,
                               void* C, int M, int N, int K, int act) {
    int nTM = M / 128, nTN = N / 128;
    int tiles = nTM * nTN;
    int grid = tiles < PERSIST ? tiles : PERSIST;
    gemm_f16_kernel<<<grid, 256, GEMM_SMEM_BYTES>>>(A, WT, bias, C, M, N, K, act,
                                                    tiles, nTN);
}

// -------- fused attention, full fp16 mma ---------------------------------------
#define SSS   516
#define QSTH  72
#define PSTH  520
#define SMEM_S_BYTES   (64 * SSS * 4)
#define SMEM_P_BYTES   (64 * PSTH * 2)
#define SMEM_TILE_B    (64 * QSTH * 2)
#define ATTN_SMEM_BYTES (SMEM_S_BYTES + SMEM_P_BYTES + 2 * SMEM_TILE_B)  // 217088

__global__ __launch_bounds__(256) void fused_attn_kernel(const __half* __restrict__ qkv) {
    extern __shared__ char asm_raw[];
    float*  Ssm  = (float*)asm_raw;
    __half* Psm  = (__half*)(asm_raw + SMEM_S_BYTES);
    __half* kvA  = (__half*)(asm_raw + SMEM_S_BYTES + SMEM_P_BYTES);
    __half* kvB  = kvA + 64 * QSTH;

    int bh = blockIdx.y; int b = bh / NHh, h = bh - b * NHh;
    int qt = blockIdx.x * 64;
    int tid = threadIdx.x, lane = tid & 31, warp = tid >> 5;
    int g = lane >> 2, tig = lane & 3;
    int wq = warp >> 1, wh = warp & 1;

    const __half* Qg = &qkv[(size_t)(b * Ss + qt) * H3 + h * DHh];
    const __half* Kg = &qkv[(size_t)(b * Ss) * H3 + Hh + h * DHh];
    const __half* Vg = &qkv[(size_t)(b * Ss) * H3 + 2 * Hh + h * DHh];

    auto issue_tile = [&](__half* buf, const __half* src) {
#pragma unroll
        for (int i = 0; i < 2; i++) {
            int idx = tid + i * 256;
            int r = idx >> 3, c = (idx & 7) << 3;
            cp_async16(&buf[r * QSTH + c], &src[(size_t)r * H3 + c]);
        }
        asm volatile("cp.async.commit_group;" ::: "memory");
    };

    issue_tile(kvA, Qg);
    issue_tile(kvB, Kg);
    asm volatile("cp.async.wait_group 0;" ::: "memory");
    __syncthreads();

    uint32_t qa[4][4];
    {
        const uint32_t* Qw = (const uint32_t*)kvA;
        int rm = wq * 16 + g;
#pragma unroll
        for (int ks = 0; ks < 4; ks++) {
            qa[ks][0] = Qw[rm * 36 + ks * 8 + tig];
            qa[ks][1] = Qw[(rm + 8) * 36 + ks * 8 + tig];
            qa[ks][2] = Qw[rm * 36 + ks * 8 + tig + 4];
            qa[ks][3] = Qw[(rm + 8) * 36 + ks * 8 + tig + 4];
        }
    }
    __syncthreads();

    for (int kt = 0; kt < 8; kt++) {
        __half* cur = (kt & 1) ? kvA : kvB;
        __half* nxt = (kt & 1) ? kvB : kvA;
        if (kt < 7) {
            issue_tile(nxt, Kg + (size_t)(kt + 1) * 64 * H3);
            asm volatile("cp.async.wait_group 1;" ::: "memory");
        } else {
            asm volatile("cp.async.wait_group 0;" ::: "memory");
        }
        __syncthreads();

        const uint32_t* Kw = (const uint32_t*)cur;
        float acc[4][4];
#pragma unroll
        for (int nt = 0; nt < 4; nt++)
#pragma unroll
            for (int r = 0; r < 4; r++) acc[nt][r] = 0.f;
#pragma unroll
        for (int ks = 0; ks < 4; ks++) {
            uint32_t bf[4][2];
#pragma unroll
            for (int nt = 0; nt < 4; nt++) {
                int n = wh * 32 + nt * 8 + g;
                bf[nt][0] = Kw[n * 36 + ks * 8 + tig];
                bf[nt][1] = Kw[n * 36 + ks * 8 + tig + 4];
            }
#pragma unroll
            for (int nt = 0; nt < 4; nt++)
                mma_f16(acc[nt], qa[ks], bf[nt]);
        }
#pragma unroll
        for (int nt = 0; nt < 4; nt++) {
            int col = kt * 64 + wh * 32 + nt * 8 + 2 * tig;
            int row = wq * 16 + g;
            Ssm[row * SSS + col]           = acc[nt][0] * 0.125f;
            Ssm[row * SSS + col + 1]       = acc[nt][1] * 0.125f;
            Ssm[(row + 8) * SSS + col]     = acc[nt][2] * 0.125f;
            Ssm[(row + 8) * SSS + col + 1] = acc[nt][3] * 0.125f;
        }
        __syncthreads();
    }

    issue_tile(kvB, Vg);
    issue_tile(kvA, Vg + (size_t)64 * H3);

    for (int r = warp * 8; r < warp * 8 + 8; r++) {
        float* row = &Ssm[r * SSS];
        float v[16];
        float m = -1e30f;
#pragma unroll
        for (int i = 0; i < 16; i++) { v[i] = row[lane + 32 * i]; m = fmaxf(m, v[i]); }
#pragma unroll
        for (int o = 16; o > 0; o >>= 1) m = fmaxf(m, __shfl_xor_sync(0xffffffffu, m, o));
        float s = 0.f;
#pragma unroll
        for (int i = 0; i < 16; i++) { v[i] = __expf(v[i] - m); s += v[i]; }
#pragma unroll
        for (int o = 16; o > 0; o >>= 1) s += __shfl_xor_sync(0xffffffffu, s, o);
        float inv = 1.0f / s;
        __half* prow = &Psm[r * PSTH];
#pragma unroll
        for (int i = 0; i < 16; i++) prow[lane + 32 * i] = __float2half_rn(v[i] * inv);
    }
    __syncthreads();

    float oacc[4][4];
#pragma unroll
    for (int nt = 0; nt < 4; nt++)
#pragma unroll
        for (int r = 0; r < 4; r++) oacc[nt][r] = 0.f;

    const uint32_t* Pw = (const uint32_t*)Psm;
    uint32_t kv_base[2] = { (uint32_t)__cvta_generic_to_shared(kvB),
                            (uint32_t)__cvta_generic_to_shared(kvA) };
    int rm = wq * 16 + g;
    for (int kt = 0; kt < 8; kt++) {
        if (kt < 7) asm volatile("cp.async.wait_group 1;" ::: "memory");
        else        asm volatile("cp.async.wait_group 0;" ::: "memory");
        __syncthreads();

        uint32_t vb = kv_base[kt & 1];
#pragma unroll
        for (int ks = 0; ks < 4; ks++) {
            uint32_t pa[4];
            int kw = kt * 32 + ks * 8;
            pa[0] = Pw[rm * 260 + kw + tig];
            pa[1] = Pw[(rm + 8) * 260 + kw + tig];
            pa[2] = Pw[rm * 260 + kw + tig + 4];
            pa[3] = Pw[(rm + 8) * 260 + kw + tig + 4];
#pragma unroll
            for (int nt = 0; nt < 4; nt++) {
                int n0 = wh * 32 + nt * 8;
                uint32_t addr = vb + (uint32_t)(((ks * 16 + (lane & 15)) * QSTH + n0) * 2);
                uint32_t bf0, bf1;
                ldmatrix_x2_trans(bf0, bf1, addr);
                uint32_t bf[2] = { bf0, bf1 };
                mma_f16(oacc[nt], pa, bf);
            }
        }
        __syncthreads();
        if (kt + 2 < 8) {
            __half* dst = (kt & 1) ? kvA : kvB;
            issue_tile(dst, Vg + (size_t)(kt + 2) * 64 * H3);
        }
    }

#pragma unroll
    for (int nt = 0; nt < 4; nt++) {
        int col = h * DHh + wh * 32 + nt * 8 + 2 * tig;
        size_t row = (size_t)(b * Ss + qt + wq * 16 + g);
        g_ctxh[row * Hh + col]     = __float2half_rn(oacc[nt][0]);
        g_ctxh[row * Hh + col + 1] = __float2half_rn(oacc[nt][1]);
        g_ctxh[(row + 8) * Hh + col]     = __float2half_rn(oacc[nt][2]);
        g_ctxh[(row + 8) * Hh + col + 1] = __float2half_rn(oacc[nt][3]);
    }
}

// ---------------- segment bookkeeping (deterministic) ----------------
__global__ void seg_prep_kernel(const int* __restrict__ tok) {
    int b = blockIdx.x, s = threadIdx.x;
    __shared__ int sc[Ss];
    __shared__ int cnt[Ss];
    int wid = tok[(b * Ss + s) * 2];
    int isnew = (s == 0) ? 1 : (wid != tok[(b * Ss + s - 1) * 2] ? 1 : 0);
    sc[s] = isnew; cnt[s] = 0; __syncthreads();
    for (int off = 1; off < Ss; off <<= 1) {
        int v = (s >= off) ? sc[s - off] : 0;
        __syncthreads();
        sc[s] += v;
        __syncthreads();
    }
    int gid = sc[s] - 1;
    if (tok[(b * Ss + s) * 2 + 1] != 0) atomicAdd(&cnt[gid], 1);
    if (isnew) g_seg_first[b * Ss + gid] = s;
    __syncthreads();
    g_seg_cnt[b * Ss + s] = cnt[s];
    if (s == Ss - 1) g_nseg[b] = gid + 1;
}

__global__ void seg_mean_kernel(const int* __restrict__ tok, float* __restrict__ out) {
    int g = blockIdx.x, b = blockIdx.y;
    int n = g_nseg[b];
    if (g >= n) return;
    int c = g_seg_cnt[b * Ss + g];
    if (c == 0) return;
    int start = g_seg_first[b * Ss + g];
    int end = (g + 1 < n) ? g_seg_first[b * Ss + g + 1] : Ss;
    __shared__ unsigned char mf[Ss];
    for (int s = threadIdx.x; s < Ss; s += 128)
        mf[s] = (tok[(b * Ss + s) * 2 + 1] != 0);
    __syncthreads();
    float inv = 1.0f / (float)c;
    for (int j = threadIdx.x; j < Hh; j += 128) {
        float sum = 0.f;
        for (int s = start; s < end; s++)
            if (mf[s]) sum += g_x[(size_t)(b * Ss + s) * Hh + j];
        out[(size_t)(b * Ss + g) * Hh + j] = sum * inv;
    }
}

// ---------------- launch ----------------
extern "C" void kernel_launch(void* const* d_in, const int* in_sizes, int n_in,
                              void* d_out, int out_size) {
    const int*   tok  = (const int*)  d_in[0];
    const float* emb  = (const float*)d_in[1];
    const float* pos  = (const float*)d_in[2];
    const float* lng  = (const float*)d_in[3];
    const float* lnb  = (const float*)d_in[4];
    const float* Wqkv = (const float*)d_in[5];
    const float* bqkv = (const float*)d_in[6];
    const float* Wo   = (const float*)d_in[7];
    const float* bo   = (const float*)d_in[8];
    const float* ln1g = (const float*)d_in[9];
    const float* ln1b = (const float*)d_in[10];
    const float* Wff1 = (const float*)d_in[11];
    const float* bff1 = (const float*)d_in[12];
    const float* Wff2 = (const float*)d_in[13];
    const float* bff2 = (const float*)d_in[14];
    const float* ln2g = (const float*)d_in[15];
    const float* ln2b = (const float*)d_in[16];
    float* out = (float*)d_out;

    void* p;
    cudaGetSymbolAddress(&p, g_x);     float*  x    = (float*)p;
    cudaGetSymbolAddress(&p, g_tmp);   float*  tmp  = (float*)p;
    cudaGetSymbolAddress(&p, g_ctx);   float*  ctx  = (float*)p;
    cudaGetSymbolAddress(&p, g_qkvh);  __half* qkvh = (__half*)p;
    cudaGetSymbolAddress(&p, g_xh);    __half* xh   = (__half*)p;
    cudaGetSymbolAddress(&p, g_ctxh);  __half* ctxh = (__half*)p;
    cudaGetSymbolAddress(&p, g_ff1h);  __half* ff1h = (__half*)p;
    cudaGetSymbolAddress(&p, g_wh);    __half* wh   = (__half*)p;

    cudaFuncSetAttribute(fused_attn_kernel,
                         cudaFuncAttributeMaxDynamicSharedMemorySize, ATTN_SMEM_BYTES);
    cudaFuncSetAttribute(gemm_f16_kernel,
                         cudaFuncAttributeMaxDynamicSharedMemorySize, GEMM_SMEM_BYTES);

    cudaMemsetAsync(d_out, 0, (size_t)out_size * sizeof(float), 0);

    for (int l = 0; l < Ll; l++) {
        __half* wl = wh + (size_t)l * WT_LAYER;
        transpose_h_kernel<<<dim3(H3 / 32, Hh / 32), dim3(32, 8)>>>(
            Wqkv + (size_t)l * Hh * H3, wl + WT_QKV, Hh, H3);
        transpose_h_kernel<<<dim3(Hh / 32, Hh / 32), dim3(32, 8)>>>(
            Wo + (size_t)l * Hh * Hh, wl + WT_WO, Hh, Hh);
        transpose_h_kernel<<<dim3(FFf / 32, Hh / 32), dim3(32, 8)>>>(
            Wff1 + (size_t)l * Hh * FFf, wl + WT_FF1, Hh, FFf);
        transpose_h_kernel<<<dim3(Hh / 32, FFf / 32), dim3(32, 8)>>>(
            Wff2 + (size_t)l * FFf * Hh, wl + WT_FF2, FFf, Hh);
    }

    embed_ln_kernel<<<Tt, 256>>>(tok, emb, pos, lng, lnb);

    for (int l = 0; l < Ll; l++) {
        const __half* wl = wh + (size_t)l * WT_LAYER;
        launch_gemm(xh, wl + WT_QKV, bqkv + l * H3, qkvh, Tt, H3, Hh, 2);
        fused_attn_kernel<<<dim3(8, Bb * NHh), 256, ATTN_SMEM_BYTES>>>(qkvh);
        launch_gemm(ctxh, wl + WT_WO, bo + l * Hh, tmp, Tt, Hh, Hh, 0);
        add_ln_kernel<<<Tt, 256>>>(x, tmp, ln1g + l * Hh, ln1b + l * Hh, x, xh);
        launch_gemm(xh, wl + WT_FF1, bff1 + l * FFf, ff1h, Tt, FFf, Hh, 1);
        launch_gemm(ff1h, wl + WT_FF2, bff2 + l * Hh, ctx, Tt, Hh, FFf, 0);
        add_ln_kernel<<<Tt, 256>>>(x, ctx, ln2g + l * Hh, ln2b + l * Hh, x, xh);
    }

    seg_prep_kernel<<<Bb, Ss>>>(tok);
    seg_mean_kernel<<<dim3(Ss, Bb), 128>>>(tok, out);
}

// round 15
// speedup vs baseline: 2.3226x; 1.1712x over previous
#include <cuda_runtime.h>
#include <cuda_fp16.h>
#include <math.h>
#include <stdint.h>

#define Bb   16
#define Ss   512
#define Hh   768
#define NHh  12
#define DHh  64
#define Ll   2
#define FFf  3072
#define Tt   (Bb*Ss)          // 8192 tokens
#define H3   (3*Hh)           // 2304

#define NSM       148
#define PERSIST   (2*NSM)

// ---------------- scratch (no allocations allowed) ----------------
__device__ float  g_x[Tt*Hh];                   // hidden state fp32
__device__ float  g_tmp[Tt*Hh];                 // wo out (fp32)
__device__ float  g_ctx[Tt*Hh];                 // ff2 out (fp32)
__device__ __half g_qkvh[Tt*H3];                // fp16 qkv
__device__ __half g_xh[Tt*Hh];                  // fp16 copy of x
__device__ __half g_ctxh[Tt*Hh];                // fp16 attention output
__device__ __half g_ff1h[Tt*FFf];               // fp16 FF1 output (post-GELU)
#define WT_LAYER 7077888
#define WT_QKV   0
#define WT_WO    1769472
#define WT_FF1   2359296
#define WT_FF2   4718592
__device__ __half g_wh[2*WT_LAYER];             // 28.3 MB
__device__ int    g_seg_first[Bb*Ss];
__device__ int    g_seg_cnt[Bb*Ss];
__device__ int    g_nseg[Bb];

// ---------------- helpers ----------------
__device__ __forceinline__ void mma_f16(float* c, const uint32_t* a, const uint32_t* b) {
    asm volatile(
        "mma.sync.aligned.m16n8k16.row.col.f32.f16.f16.f32 "
        "{%0,%1,%2,%3}, {%4,%5,%6,%7}, {%8,%9}, {%0,%1,%2,%3};"
        : "+f"(c[0]), "+f"(c[1]), "+f"(c[2]), "+f"(c[3])
        : "r"(a[0]), "r"(a[1]), "r"(a[2]), "r"(a[3]), "r"(b[0]), "r"(b[1]));
}

__device__ __forceinline__ void ldmatrix_x4(uint32_t& d0, uint32_t& d1,
                                            uint32_t& d2, uint32_t& d3, uint32_t addr) {
    asm volatile("ldmatrix.sync.aligned.m8n8.x4.shared.b16 {%0,%1,%2,%3}, [%4];"
                 : "=r"(d0), "=r"(d1), "=r"(d2), "=r"(d3) : "r"(addr));
}

__device__ __forceinline__ void ldmatrix_x2(uint32_t& d0, uint32_t& d1, uint32_t addr) {
    asm volatile("ldmatrix.sync.aligned.m8n8.x2.shared.b16 {%0,%1}, [%2];"
                 : "=r"(d0), "=r"(d1) : "r"(addr));
}

__device__ __forceinline__ void ldmatrix_x2_trans(uint32_t& d0, uint32_t& d1, uint32_t addr) {
    asm volatile("ldmatrix.sync.aligned.m8n8.x2.trans.shared.b16 {%0,%1}, [%2];"
                 : "=r"(d0), "=r"(d1) : "r"(addr));
}

__device__ __forceinline__ void cp_async16(void* smem_ptr, const void* gptr) {
    uint32_t s = (uint32_t)__cvta_generic_to_shared(smem_ptr);
    asm volatile("cp.async.cg.shared.global [%0], [%1], 16;" :: "r"(s), "l"(gptr));
}

// ---------------- weight transpose + fp16 cvt: dst[N][K] = h(src[K][N]^T) ------
__global__ void transpose_h_kernel(const float* __restrict__ src,
                                   __half* __restrict__ dst, int K, int N) {
    __shared__ float tile[32][33];
    int bx = blockIdx.x * 32;   // n
    int by = blockIdx.y * 32;   // k
    int tx = threadIdx.x, ty = threadIdx.y;   // 32 x 8
#pragma unroll
    for (int j = 0; j < 32; j += 8)
        tile[ty + j][tx] = src[(size_t)(by + ty + j) * N + bx + tx];
    __syncthreads();
#pragma unroll
    for (int j = 0; j < 32; j += 8)
        dst[(size_t)(bx + ty + j) * K + by + tx] = __float2half_rn(tile[tx][ty + j]);
}

// ---------------- embedding + LN: one warp per row, register-resident ---------
__global__ void embed_ln_kernel(const int* __restrict__ tok,
                                const float* __restrict__ emb,
                                const float* __restrict__ pos,
                                const float* __restrict__ g,
                                const float* __restrict__ bt) {
    int row  = blockIdx.x * 8 + (threadIdx.x >> 5);
    int lane = threadIdx.x & 31;
    int s    = row & (Ss - 1);
    int id   = tok[row * 2 + 1];
    float v[24];
    float ps = 0.f, pq = 0.f;
#pragma unroll
    for (int i = 0; i < 24; i++) {
        int j = lane + 32 * i;
        float t = emb[(size_t)id * Hh + j] + pos[s * Hh + j];
        v[i] = t; ps += t; pq += t * t;
    }
#pragma unroll
    for (int o = 16; o > 0; o >>= 1) {
        ps += __shfl_xor_sync(0xffffffffu, ps, o);
        pq += __shfl_xor_sync(0xffffffffu, pq, o);
    }
    float mean = ps * (1.f / Hh);
    float var  = pq * (1.f / Hh) - mean * mean;
    float inv  = rsqrtf(var + 1e-12f);
    size_t base = (size_t)row * Hh;
#pragma unroll
    for (int i = 0; i < 24; i++) {
        int j = lane + 32 * i;
        float o = (v[i] - mean) * inv * g[j] + bt[j];
        g_x[base + j]  = o;
        g_xh[base + j] = __float2half_rn(o);
    }
}

// ---------------- residual add + LN: one warp per row -------------------------
__global__ void add_ln_kernel(const float* __restrict__ x,
                              const float* __restrict__ tadd,
                              const float* __restrict__ g,
                              const float* __restrict__ bt,
                              float* __restrict__ out,
                              __half* __restrict__ outh) {
    int row  = blockIdx.x * 8 + (threadIdx.x >> 5);
    int lane = threadIdx.x & 31;
    size_t base = (size_t)row * Hh;
    float v[24];
    float ps = 0.f, pq = 0.f;
#pragma unroll
    for (int i = 0; i < 24; i++) {
        int j = lane + 32 * i;
        float t = x[base + j] + tadd[base + j];
        v[i] = t; ps += t; pq += t * t;
    }
#pragma unroll
    for (int o = 16; o > 0; o >>= 1) {
        ps += __shfl_xor_sync(0xffffffffu, ps, o);
        pq += __shfl_xor_sync(0xffffffffu, pq, o);
    }
    float mean = ps * (1.f / Hh);
    float var  = pq * (1.f / Hh) - mean * mean;
    float inv  = rsqrtf(var + 1e-12f);
#pragma unroll
    for (int i = 0; i < 24; i++) {
        int j = lane + 32 * i;
        float o = (v[i] - mean) * inv * g[j] + bt[j];
        out[base + j]  = o;
        outh[base + j] = __float2half_rn(o);
    }
}

// ------- persistent FP16 GEMM, 4-stage cp.async + ldmatrix, 1 barrier/iter ----
#define HAS     40
#define HA_SZ   (128 * HAS)
#define HSTAGE  (2 * HA_SZ)
#define NSTAGE  4
#define GEMM_SMEM_BYTES (NSTAGE * HSTAGE * 2)   // 81920 B

__global__ __launch_bounds__(256) void gemm_f16_kernel(const __half* __restrict__ A,
                                                       const __half* __restrict__ WT,
                                                       const float* __restrict__ bias,
                                                       void* __restrict__ Cout,
                                                       int M, int N, int K, int act,
                                                       int numTiles, int nTN) {
    extern __shared__ __half hsm[];
    int tid  = threadIdx.x;
    int lane = tid & 31;
    int warp = tid >> 5;
    int g    = lane >> 2, tig = lane & 3;
    int wm   = warp >> 2, wn = warp & 3;
    int nK   = K >> 5;

    uint32_t smem_base = (uint32_t)__cvta_generic_to_shared(hsm);
    int l15 = lane & 15;
    uint32_t a_off = (uint32_t)(((wm * 64 + (lane & 15)) * HAS + ((lane >> 4) << 3)) * 2);
    uint32_t b_off = (uint32_t)((HA_SZ + (wn * 32 + (l15 & 7)) * HAS + (((l15 >> 3) & 1) << 3)) * 2);

    for (int t = blockIdx.x; t < numTiles; t += gridDim.x) {
        int mBase = (t / nTN) * 128;
        int nBase = (t % nTN) * 128;

        float acc[4][4][4];
#pragma unroll
        for (int i = 0; i < 4; i++)
#pragma unroll
            for (int j = 0; j < 4; j++)
#pragma unroll
                for (int r = 0; r < 4; r++) acc[i][j][r] = 0.f;

        auto load_stage = [&](int stage, int k0) {
            __half* st = hsm + stage * HSTAGE;
#pragma unroll
            for (int i = 0; i < 2; i++) {
                int idx = tid + i * 256;
                int r = idx >> 2, c = (idx & 3) << 3;
                cp_async16(&st[r * HAS + c], &A[(size_t)(mBase + r) * K + k0 + c]);
            }
            __half* bs = st + HA_SZ;
#pragma unroll
            for (int i = 0; i < 2; i++) {
                int idx = tid + i * 256;
                int r = idx >> 2, c = (idx & 3) << 3;
                cp_async16(&bs[r * HAS + c], &WT[(size_t)(nBase + r) * K + k0 + c]);
            }
            asm volatile("cp.async.commit_group;" ::: "memory");
        };

        load_stage(0, 0);
        load_stage(1, 32);
        load_stage(2, 64);

        for (int i = 0; i < nK; i++) {
            if (i + 2 < nK)      asm volatile("cp.async.wait_group 2;" ::: "memory");
            else if (i + 1 < nK) asm volatile("cp.async.wait_group 1;" ::: "memory");
            else                 asm volatile("cp.async.wait_group 0;" ::: "memory");
            __syncthreads();

            uint32_t stage_b = smem_base + (uint32_t)((i & 3) * HSTAGE * 2);
#pragma unroll
            for (int ks = 0; ks < 2; ks++) {
                uint32_t a[4][4], b[4][2];
                uint32_t koff = (uint32_t)(ks * 32);
#pragma unroll
                for (int mi = 0; mi < 4; mi++)
                    ldmatrix_x4(a[mi][0], a[mi][1], a[mi][2], a[mi][3],
                                stage_b + a_off + koff + (uint32_t)(mi * 16 * HAS * 2));
#pragma unroll
                for (int ni = 0; ni < 4; ni++)
                    ldmatrix_x2(b[ni][0], b[ni][1],
                                stage_b + b_off + koff + (uint32_t)(ni * 8 * HAS * 2));
#pragma unroll
                for (int mi = 0; mi < 4; mi++)
#pragma unroll
                    for (int ni = 0; ni < 4; ni++)
                        mma_f16(acc[mi][ni], a[mi], b[ni]);
            }
            if (i + 3 < nK)
                load_stage((i + 3) & 3, (i + 3) << 5);
        }
        __syncthreads();

        // epilogue
#pragma unroll
        for (int mi = 0; mi < 4; mi++) {
            int rm0 = mBase + wm * 64 + mi * 16 + g;
#pragma unroll
            for (int ni = 0; ni < 4; ni++) {
                int cn = nBase + wn * 32 + ni * 8 + 2 * tig;
                float b0 = bias[cn], b1 = bias[cn + 1];
                float v0 = acc[mi][ni][0] + b0;
                float v1 = acc[mi][ni][1] + b1;
                float v2 = acc[mi][ni][2] + b0;
                float v3 = acc[mi][ni][3] + b1;
                if (act == 1) {
                    v0 = 0.5f * v0 * (1.0f + erff(v0 * 0.70710678118654752f));
                    v1 = 0.5f * v1 * (1.0f + erff(v1 * 0.70710678118654752f));
                    v2 = 0.5f * v2 * (1.0f + erff(v2 * 0.70710678118654752f));
                    v3 = 0.5f * v3 * (1.0f + erff(v3 * 0.70710678118654752f));
                }
                if (act) {
                    __half2* Ch = (__half2*)Cout;
                    Ch[((size_t)rm0 * N + cn) >> 1]       = __floats2half2_rn(v0, v1);
                    Ch[((size_t)(rm0 + 8) * N + cn) >> 1] = __floats2half2_rn(v2, v3);
                } else {
                    float* Cf = (float*)Cout;
                    *reinterpret_cast<float2*>(&Cf[(size_t)rm0 * N + cn])       = make_float2(v0, v1);
                    *reinterpret_cast<float2*>(&Cf[(size_t)(rm0 + 8) * N + cn]) = make_float2(v2, v3);
                }
            }
        }
    }
}

static inline void launch_gemm(const __half* A, const __half* WT, const float* bias,
                               void* C, int M, int N, int K, int act) {
    int nTM = M / 128, nTN = N / 128;
    int tiles = nTM * nTN;
    int grid = tiles < PERSIST ? tiles : PERSIST;
    gemm_f16_kernel<<<grid, 256, GEMM_SMEM_BYTES>>>(A, WT, bias, C, M, N, K, act,
                                                    tiles, nTN);
}

// -------- flash attention: online softmax, S/P in registers -------------------
// 128 q-rows per block, 8 warps x 16 rows; K/V streamed through 9 KB buffers.
#define KVST 72
#define FLASH_SMEM (128*KVST*2 + 2*64*KVST*2)   // 18432 + 18432 = 36864 B

__global__ __launch_bounds__(256) void flash_attn_kernel(const __half* __restrict__ qkv) {
    extern __shared__ __half fsm[];
    __half* Qs = fsm;                 // 128 x 72
    __half* Ks = fsm + 128 * KVST;    // 64 x 72
    __half* Vs = Ks + 64 * KVST;      // 64 x 72

    int bh = blockIdx.y; int b = bh / NHh, h = bh - b * NHh;
    int qt = blockIdx.x * 128;
    int tid = threadIdx.x, lane = tid & 31, warp = tid >> 5;
    int g = lane >> 2, tig = lane & 3;

    const __half* Qg = &qkv[(size_t)(b * Ss + qt) * H3 + h * DHh];
    const __half* Kg = &qkv[(size_t)(b * Ss) * H3 + Hh + h * DHh];
    const __half* Vg = &qkv[(size_t)(b * Ss) * H3 + 2 * Hh + h * DHh];

    // Q: 128 rows x 64 halves = 1024 x 16B, 4 per thread
#pragma unroll
    for (int i = 0; i < 4; i++) {
        int idx = tid + i * 256;
        int r = idx >> 3, c = (idx & 7) << 3;
        cp_async16(&Qs[r * KVST + c], &Qg[(size_t)r * H3 + c]);
    }
    asm volatile("cp.async.commit_group;" ::: "memory");

    auto issue_kv = [&](__half* buf, const __half* src) {
#pragma unroll
        for (int i = 0; i < 2; i++) {
            int idx = tid + i * 256;
            int r = idx >> 3, c = (idx & 7) << 3;
            cp_async16(&buf[r * KVST + c], &src[(size_t)r * H3 + c]);
        }
        asm volatile("cp.async.commit_group;" ::: "memory");
    };
    issue_kv(Ks, Kg);
    issue_kv(Vs, Vg);

    asm volatile("cp.async.wait_group 2;" ::: "memory");   // Q complete
    __syncthreads();

    // Q fragments, pre-scaled by 1/8 (exact power of 2)
    uint32_t qa[4][4];
    {
        const uint32_t* Qw = (const uint32_t*)Qs;
        const __half2 sc = __float2half2_rn(0.125f);
        int rm = warp * 16 + g;
#pragma unroll
        for (int ks = 0; ks < 4; ks++) {
            uint32_t t0 = Qw[rm * 36 + ks * 8 + tig];
            uint32_t t1 = Qw[(rm + 8) * 36 + ks * 8 + tig];
            uint32_t t2 = Qw[rm * 36 + ks * 8 + tig + 4];
            uint32_t t3 = Qw[(rm + 8) * 36 + ks * 8 + tig + 4];
            __half2 h0 = __hmul2(*(__half2*)&t0, sc); qa[ks][0] = *(uint32_t*)&h0;
            __half2 h1 = __hmul2(*(__half2*)&t1, sc); qa[ks][1] = *(uint32_t*)&h1;
            __half2 h2 = __hmul2(*(__half2*)&t2, sc); qa[ks][2] = *(uint32_t*)&h2;
            __half2 h3 = __hmul2(*(__half2*)&t3, sc); qa[ks][3] = *(uint32_t*)&h3;
        }
    }

    float m0 = -1e30f, m1 = -1e30f, l0 = 0.f, l1 = 0.f;
    float oacc[8][4];
#pragma unroll
    for (int nt = 0; nt < 8; nt++)
#pragma unroll
        for (int r = 0; r < 4; r++) oacc[nt][r] = 0.f;

    uint32_t vsm = (uint32_t)__cvta_generic_to_shared(Vs);

    for (int kt = 0; kt < 8; kt++) {
        asm volatile("cp.async.wait_group 1;" ::: "memory");   // K_kt ready
        __syncthreads();

        // S tile (16x64 per warp) in registers
        float sacc[8][4];
#pragma unroll
        for (int nt = 0; nt < 8; nt++)
#pragma unroll
            for (int r = 0; r < 4; r++) sacc[nt][r] = 0.f;
        {
            const uint32_t* Kw = (const uint32_t*)Ks;
#pragma unroll
            for (int ks = 0; ks < 4; ks++)
#pragma unroll
                for (int nt = 0; nt < 8; nt++) {
                    uint32_t bf[2];
                    int n = nt * 8 + g;
                    bf[0] = Kw[n * 36 + ks * 8 + tig];
                    bf[1] = Kw[n * 36 + ks * 8 + tig + 4];
                    mma_f16(sacc[nt], qa[ks], bf);
                }
        }
        __syncthreads();
        if (kt < 7) issue_kv(Ks, Kg + (size_t)(kt + 1) * 64 * H3);

        // online softmax update (rows r0 = warp*16+g, r1 = r0+8)
        float tm0 = -1e30f, tm1 = -1e30f;
#pragma unroll
        for (int nt = 0; nt < 8; nt++) {
            tm0 = fmaxf(tm0, fmaxf(sacc[nt][0], sacc[nt][1]));
            tm1 = fmaxf(tm1, fmaxf(sacc[nt][2], sacc[nt][3]));
        }
        tm0 = fmaxf(tm0, __shfl_xor_sync(0xffffffffu, tm0, 1));
        tm0 = fmaxf(tm0, __shfl_xor_sync(0xffffffffu, tm0, 2));
        tm1 = fmaxf(tm1, __shfl_xor_sync(0xffffffffu, tm1, 1));
        tm1 = fmaxf(tm1, __shfl_xor_sync(0xffffffffu, tm1, 2));
        float mn0 = fmaxf(m0, tm0), mn1 = fmaxf(m1, tm1);
        float a0 = __expf(m0 - mn0), a1 = __expf(m1 - mn1);

        uint32_t ph[8][2];
        float s0 = 0.f, s1 = 0.f;
#pragma unroll
        for (int nt = 0; nt < 8; nt++) {
            float p00 = __expf(sacc[nt][0] - mn0);
            float p01 = __expf(sacc[nt][1] - mn0);
            float p10 = __expf(sacc[nt][2] - mn1);
            float p11 = __expf(sacc[nt][3] - mn1);
            s0 += p00 + p01; s1 += p10 + p11;
            __half2 q0 = __floats2half2_rn(p00, p01); ph[nt][0] = *(uint32_t*)&q0;
            __half2 q1 = __floats2half2_rn(p10, p11); ph[nt][1] = *(uint32_t*)&q1;
        }
        s0 += __shfl_xor_sync(0xffffffffu, s0, 1);
        s0 += __shfl_xor_sync(0xffffffffu, s0, 2);
        s1 += __shfl_xor_sync(0xffffffffu, s1, 1);
        s1 += __shfl_xor_sync(0xffffffffu, s1, 2);
        l0 = l0 * a0 + s0; l1 = l1 * a1 + s1;
        m0 = mn0; m1 = mn1;
#pragma unroll
        for (int nt = 0; nt < 8; nt++) {
            oacc[nt][0] *= a0; oacc[nt][1] *= a0;
            oacc[nt][2] *= a1; oacc[nt][3] *= a1;
        }

        // V_kt ready; compute PV
        if (kt < 7) asm volatile("cp.async.wait_group 1;" ::: "memory");
        else        asm volatile("cp.async.wait_group 0;" ::: "memory");
        __syncthreads();

#pragma unroll
        for (int ks = 0; ks < 4; ks++) {
            uint32_t pa[4] = { ph[2*ks][0], ph[2*ks][1], ph[2*ks+1][0], ph[2*ks+1][1] };
#pragma unroll
            for (int nt = 0; nt < 8; nt++) {
                uint32_t addr = vsm + (uint32_t)(((ks * 16 + (lane & 15)) * KVST + nt * 8) * 2);
                uint32_t bf[2];
                ldmatrix_x2_trans(bf[0], bf[1], addr);
                mma_f16(oacc[nt], pa, bf);
            }
        }
        __syncthreads();
        if (kt < 7) issue_kv(Vs, Vg + (size_t)(kt + 1) * 64 * H3);
    }

    // normalize + write fp16 output
    float il0 = 1.f / l0, il1 = 1.f / l1;
    size_t r0 = (size_t)(b * Ss + qt + warp * 16 + g);
#pragma unroll
    for (int nt = 0; nt < 8; nt++) {
        int col = h * DHh + nt * 8 + 2 * tig;
        *(__half2*)&g_ctxh[r0 * Hh + col] =
            __floats2half2_rn(oacc[nt][0] * il0, oacc[nt][1] * il0);
        *(__half2*)&g_ctxh[(r0 + 8) * Hh + col] =
            __floats2half2_rn(oacc[nt][2] * il1, oacc[nt][3] * il1);
    }
}

// ---------------- segment bookkeeping (deterministic) ----------------
__global__ void seg_prep_kernel(const int* __restrict__ tok) {
    int b = blockIdx.x, s = threadIdx.x;
    __shared__ int sc[Ss];
    __shared__ int cnt[Ss];
    int wid = tok[(b * Ss + s) * 2];
    int isnew = (s == 0) ? 1 : (wid != tok[(b * Ss + s - 1) * 2] ? 1 : 0);
    sc[s] = isnew; cnt[s] = 0; __syncthreads();
    for (int off = 1; off < Ss; off <<= 1) {
        int v = (s >= off) ? sc[s - off] : 0;
        __syncthreads();
        sc[s] += v;
        __syncthreads();
    }
    int gid = sc[s] - 1;
    if (tok[(b * Ss + s) * 2 + 1] != 0) atomicAdd(&cnt[gid], 1);
    if (isnew) g_seg_first[b * Ss + gid] = s;
    __syncthreads();
    g_seg_cnt[b * Ss + s] = cnt[s];
    if (s == Ss - 1) g_nseg[b] = gid + 1;
}

__global__ void seg_mean_kernel(const int* __restrict__ tok, float* __restrict__ out) {
    int g = blockIdx.x, b = blockIdx.y;
    int n = g_nseg[b];
    if (g >= n) return;
    int c = g_seg_cnt[b * Ss + g];
    if (c == 0) return;
    int start = g_seg_first[b * Ss + g];
    int end = (g + 1 < n) ? g_seg_first[b * Ss + g + 1] : Ss;
    __shared__ unsigned char mf[Ss];
    for (int s = threadIdx.x; s < Ss; s += 128)
        mf[s] = (tok[(b * Ss + s) * 2 + 1] != 0);
    __syncthreads();
    float inv = 1.0f / (float)c;
    for (int j = threadIdx.x; j < Hh; j += 128) {
        float sum = 0.f;
        for (int s = start; s < end; s++)
            if (mf[s]) sum += g_x[(size_t)(b * Ss + s) * Hh + j];
        out[(size_t)(b * Ss + g) * Hh + j] = sum * inv;
    }
}

// ---------------- launch ----------------
extern "C" void kernel_launch(void* const* d_in, const int* in_sizes, int n_in,
                              void* d_out, int out_size) {
    const int*   tok  = (const int*)  d_in[0];
    const float* emb  = (const float*)d_in[1];
    const float* pos  = (const float*)d_in[2];
    const float* lng  = (const float*)d_in[3];
    const float* lnb  = (const float*)d_in[4];
    const float* Wqkv = (const float*)d_in[5];
    const float* bqkv = (const float*)d_in[6];
    const float* Wo   = (const float*)d_in[7];
    const float* bo   = (const float*)d_in[8];
    const float* ln1g = (const float*)d_in[9];
    const float* ln1b = (const float*)d_in[10];
    const float* Wff1 = (const float*)d_in[11];
    const float* bff1 = (const float*)d_in[12];
    const float* Wff2 = (const float*)d_in[13];
    const float* bff2 = (const float*)d_in[14];
    const float* ln2g = (const float*)d_in[15];
    const float* ln2b = (const float*)d_in[16];
    float* out = (float*)d_out;

    void* p;
    cudaGetSymbolAddress(&p, g_x);     float*  x    = (float*)p;
    cudaGetSymbolAddress(&p, g_tmp);   float*  tmp  = (float*)p;
    cudaGetSymbolAddress(&p, g_ctx);   float*  ctx  = (float*)p;
    cudaGetSymbolAddress(&p, g_qkvh);  __half* qkvh = (__half*)p;
    cudaGetSymbolAddress(&p, g_xh);    __half* xh   = (__half*)p;
    cudaGetSymbolAddress(&p, g_ctxh);  __half* ctxh = (__half*)p;
    cudaGetSymbolAddress(&p, g_ff1h);  __half* ff1h = (__half*)p;
    cudaGetSymbolAddress(&p, g_wh);    __half* wh   = (__half*)p;

    cudaFuncSetAttribute(flash_attn_kernel,
                         cudaFuncAttributeMaxDynamicSharedMemorySize, FLASH_SMEM);
    cudaFuncSetAttribute(gemm_f16_kernel,
                         cudaFuncAttributeMaxDynamicSharedMemorySize, GEMM_SMEM_BYTES);

    cudaMemsetAsync(d_out, 0, (size_t)out_size * sizeof(float), 0);

    for (int l = 0; l < Ll; l++) {
        __half* wl = wh + (size_t)l * WT_LAYER;
        transpose_h_kernel<<<dim3(H3 / 32, Hh / 32), dim3(32, 8)>>>(
            Wqkv + (size_t)l * Hh * H3, wl + WT_QKV, Hh, H3);
        transpose_h_kernel<<<dim3(Hh / 32, Hh / 32), dim3(32, 8)>>>(
            Wo + (size_t)l * Hh * Hh, wl + WT_WO, Hh, Hh);
        transpose_h_kernel<<<dim3(FFf / 32, Hh / 32), dim3(32, 8)>>>(
            Wff1 + (size_t)l * Hh * FFf, wl + WT_FF1, Hh, FFf);
        transpose_h_kernel<<<dim3(Hh / 32, FFf / 32), dim3(32, 8)>>>(
            Wff2 + (size_t)l * FFf * Hh, wl + WT_FF2, FFf, Hh);
    }

    embed_ln_kernel<<<Tt / 8, 256>>>(tok, emb, pos, lng, lnb);

    for (int l = 0; l < Ll; l++) {
        const __half* wl = wh + (size_t)l * WT_LAYER;
        launch_gemm(xh, wl + WT_QKV, bqkv + l * H3, qkvh, Tt, H3, Hh, 2);
        flash_attn_kernel<<<dim3(Ss / 128, Bb * NHh), 256, FLASH_SMEM>>>(qkvh);
        launch_gemm(ctxh, wl + WT_WO, bo + l * Hh, tmp, Tt, Hh, Hh, 0);
        add_ln_kernel<<<Tt / 8, 256>>>(x, tmp, ln1g + l * Hh, ln1b + l * Hh, x, xh);
        launch_gemm(xh, wl + WT_FF1, bff1 + l * FFf, ff1h, Tt, FFf, Hh, 1);
        launch_gemm(ff1h, wl + WT_FF2, bff2 + l * Hh, ctx, Tt, Hh, FFf, 0);
        add_ln_kernel<<<Tt / 8, 256>>>(x, ctx, ln2g + l * Hh, ln2b + l * Hh, x, xh);
    }

    seg_prep_kernel<<<Bb, Ss>>>(tok);
    seg_mean_kernel<<<dim3(Ss, Bb), 128>>>(tok, out);
}